// round 1
// baseline (speedup 1.0000x reference)
#include <cuda_runtime.h>
#include <cuda_bf16.h>
#include <cstdint>
#include <cstddef>

// Problem constants
#define BB   2
#define LL   2048
#define EE   1024
#define NHH  16
#define DHH  64
#define HIDD 4096
#define MROWS (BB*LL)          // 4096

// ---------------------------------------------------------------------------
// Scratch (no cudaMalloc allowed) — __device__ globals
// ---------------------------------------------------------------------------
__device__ float g_o1  [MROWS * EE];          // LN1(x)
__device__ float g_qkv [MROWS * (NHH*3*DHH)]; // o1 @ Wa     (4096 x 3072)
__device__ float g_attn[MROWS * EE];          // attention out (b,l, nh*dh)
__device__ float g_res1[MROWS * EE];          // x + attn@Wout + bout
__device__ float g_o2  [MROWS * EE];          // LN2(res1)
__device__ float g_h   [MROWS * HIDD];        // o2 @ W1 + b1 (4096 x 4096)

// ---------------------------------------------------------------------------
// LayerNorm: one block per row (E=1024), 256 threads, one float4 per thread
// ---------------------------------------------------------------------------
__global__ __launch_bounds__(256)
void ln_kernel(const float* __restrict__ in, const float* __restrict__ g,
               const float* __restrict__ be, float* __restrict__ out) {
    int row = blockIdx.x;
    int tid = threadIdx.x;
    const float4* ip = (const float4*)(in + (size_t)row * EE);
    float4 v = ip[tid];
    float s  = v.x + v.y + v.z + v.w;
    float ss = v.x*v.x + v.y*v.y + v.z*v.z + v.w*v.w;
    #pragma unroll
    for (int o = 16; o; o >>= 1) {
        s  += __shfl_xor_sync(0xffffffffu, s,  o);
        ss += __shfl_xor_sync(0xffffffffu, ss, o);
    }
    __shared__ float sm[8], sm2[8];
    int w = tid >> 5;
    if ((tid & 31) == 0) { sm[w] = s; sm2[w] = ss; }
    __syncthreads();
    float ts = 0.f, tss = 0.f;
    #pragma unroll
    for (int i = 0; i < 8; i++) { ts += sm[i]; tss += sm2[i]; }
    float mu  = ts  * (1.f / EE);
    float var = tss * (1.f / EE) - mu * mu;
    float rs  = rsqrtf(var + 1e-5f);
    float4 gv = ((const float4*)g)[tid];
    float4 bv = ((const float4*)be)[tid];
    float4 o;
    o.x = (v.x - mu) * rs * gv.x + bv.x;
    o.y = (v.y - mu) * rs * gv.y + bv.y;
    o.z = (v.z - mu) * rs * gv.z + bv.z;
    o.w = (v.w - mu) * rs * gv.w + bv.w;
    ((float4*)(out + (size_t)row * EE))[tid] = o;
}

// ---------------------------------------------------------------------------
// Tiled fp32 GEMM: C = A(MxK) * B(KxN) [+ bias[n]] [+ res(MxN)]
// 128x128 block tile, BK=16, 256 threads, 8x8 per thread, float4 everywhere.
// All dims are multiples of the tile sizes for this problem -> no bounds checks.
// ---------------------------------------------------------------------------
template<bool BIAS, bool RES>
__global__ __launch_bounds__(256)
void gemm128(const float* __restrict__ A, const float* __restrict__ B,
             const float* __restrict__ bias, const float* __restrict__ res,
             float* __restrict__ C, int M, int N, int K) {
    __shared__ float As[16][132];   // transposed A tile, padded
    __shared__ float Bs[16][128];
    int tid = threadIdx.x;
    int rowBase = blockIdx.y * 128;
    int colBase = blockIdx.x * 128;
    int ty = tid >> 4, tx = tid & 15;

    float acc[8][8];
    #pragma unroll
    for (int i = 0; i < 8; i++)
        #pragma unroll
        for (int j = 0; j < 8; j++) acc[i][j] = 0.f;

    const float* Ab = A + (size_t)rowBase * K;
    const float* Bb = B + colBase;

    for (int kt = 0; kt < K; kt += 16) {
        #pragma unroll
        for (int t = 0; t < 2; t++) {
            int id = tid + t * 256;          // 0..511 float4 slots of A tile
            int r  = id >> 2;                // 0..127
            int kq = (id & 3) * 4;           // 0,4,8,12
            float4 a = *(const float4*)&Ab[(size_t)r * K + kt + kq];
            As[kq + 0][r] = a.x;
            As[kq + 1][r] = a.y;
            As[kq + 2][r] = a.z;
            As[kq + 3][r] = a.w;
        }
        #pragma unroll
        for (int t = 0; t < 2; t++) {
            int id = tid + t * 256;          // 0..511 float4 slots of B tile
            int r  = id >> 5;                // 0..15
            int c4 = (id & 31) * 4;          // 0..124
            *(float4*)&Bs[r][c4] = *(const float4*)&Bb[(size_t)(kt + r) * N + c4];
        }
        __syncthreads();
        #pragma unroll
        for (int k = 0; k < 16; k++) {
            float ar[8], br[8];
            *(float4*)&ar[0] = *(float4*)&As[k][ty * 8];
            *(float4*)&ar[4] = *(float4*)&As[k][ty * 8 + 4];
            *(float4*)&br[0] = *(float4*)&Bs[k][tx * 8];
            *(float4*)&br[4] = *(float4*)&Bs[k][tx * 8 + 4];
            #pragma unroll
            for (int i = 0; i < 8; i++)
                #pragma unroll
                for (int j = 0; j < 8; j++)
                    acc[i][j] += ar[i] * br[j];
        }
        __syncthreads();
    }

    #pragma unroll
    for (int i = 0; i < 8; i++) {
        int r = rowBase + ty * 8 + i;
        #pragma unroll
        for (int jq = 0; jq < 2; jq++) {
            int c = colBase + tx * 8 + jq * 4;
            float4 v;
            v.x = acc[i][jq*4+0]; v.y = acc[i][jq*4+1];
            v.z = acc[i][jq*4+2]; v.w = acc[i][jq*4+3];
            if (BIAS) {
                float4 bb = *(const float4*)&bias[c];
                v.x += bb.x; v.y += bb.y; v.z += bb.z; v.w += bb.w;
            }
            if (RES) {
                float4 rr = *(const float4*)&res[(size_t)r * N + c];
                v.x += rr.x; v.y += rr.y; v.z += rr.z; v.w += rr.w;
            }
            *(float4*)&C[(size_t)r * N + c] = v;
        }
    }
}

// ---------------------------------------------------------------------------
// Causal flash attention, fp32. qkv layout: row (b*L+l), col h*192 + [q|k|v]*64+d
// One block = (q-chunk of 128 queries) x (one (b,h) pair). 128 threads,
// one query per thread; K/V tiles of 64 keys staged in shared memory.
// ---------------------------------------------------------------------------
__global__ __launch_bounds__(128)
void attn_kernel(const float* __restrict__ qkv, float* __restrict__ out) {
    __shared__ float4 sK[64 * 16];
    __shared__ float4 sV[64 * 16];
    int tid   = threadIdx.x;
    int chunk = blockIdx.x;       // 0..15
    int bh    = blockIdx.y;       // 0..31
    int b     = bh >> 4, h = bh & 15;
    int q     = chunk * 128 + tid;

    size_t rowq = (size_t)(b * LL + q) * 3072 + h * 192;
    float4 qv[16];
    #pragma unroll
    for (int i = 0; i < 16; i++) qv[i] = *(const float4*)&qkv[rowq + i * 4];
    const float scale = 0.125f;   // 1/sqrt(64)
    #pragma unroll
    for (int i = 0; i < 16; i++) {
        qv[i].x *= scale; qv[i].y *= scale; qv[i].z *= scale; qv[i].w *= scale;
    }

    float4 ov[16];
    #pragma unroll
    for (int i = 0; i < 16; i++) ov[i] = make_float4(0.f, 0.f, 0.f, 0.f);
    float mi = -1e30f, li = 0.f;

    int ntiles = chunk * 2 + 2;   // keys [0, chunk*128+128) in tiles of 64
    for (int kt = 0; kt < ntiles; kt++) {
        int kstart = kt * 64;
        #pragma unroll
        for (int t = 0; t < 8; t++) {
            int id = tid + t * 128;              // 0..1023
            int j  = id >> 4, d4 = id & 15;
            size_t base = (size_t)(b * LL + kstart + j) * 3072 + h * 192;
            sK[id] = *(const float4*)&qkv[base + 64  + d4 * 4];
            sV[id] = *(const float4*)&qkv[base + 128 + d4 * 4];
        }
        __syncthreads();

        #pragma unroll 1
        for (int j0 = 0; j0 < 64; j0 += 16) {
            float s[16];
            #pragma unroll
            for (int jj = 0; jj < 16; jj++) {
                int j = j0 + jj;
                float a = 0.f;
                #pragma unroll
                for (int d = 0; d < 16; d++) {
                    float4 kv = sK[j * 16 + d];
                    a += qv[d].x * kv.x + qv[d].y * kv.y
                       + qv[d].z * kv.z + qv[d].w * kv.w;
                }
                s[jj] = (kstart + j > q) ? -1e30f : a;
            }
            float mt = mi;
            #pragma unroll
            for (int jj = 0; jj < 16; jj++) mt = fmaxf(mt, s[jj]);
            float c = __expf(mi - mt);
            li *= c;
            #pragma unroll
            for (int i = 0; i < 16; i++) {
                ov[i].x *= c; ov[i].y *= c; ov[i].z *= c; ov[i].w *= c;
            }
            #pragma unroll
            for (int jj = 0; jj < 16; jj++) {
                float p = __expf(s[jj] - mt);
                li += p;
                int j = j0 + jj;
                #pragma unroll
                for (int d = 0; d < 16; d++) {
                    float4 vv = sV[j * 16 + d];
                    ov[d].x += p * vv.x; ov[d].y += p * vv.y;
                    ov[d].z += p * vv.z; ov[d].w += p * vv.w;
                }
            }
            mi = mt;
        }
        __syncthreads();
    }

    float inv = 1.f / li;
    size_t orow = (size_t)(b * LL + q) * EE + h * DHH;
    #pragma unroll
    for (int i = 0; i < 16; i++) {
        float4 o4 = ov[i];
        o4.x *= inv; o4.y *= inv; o4.z *= inv; o4.w *= inv;
        *(float4*)&out[orow + i * 4] = o4;
    }
}

// ---------------------------------------------------------------------------
// Launch
// ---------------------------------------------------------------------------
extern "C" void kernel_launch(void* const* d_in, const int* in_sizes, int n_in,
                              void* d_out, int out_size) {
    const float* x    = (const float*)d_in[0];
    const float* Wa   = (const float*)d_in[1];
    const float* Wout = (const float*)d_in[2];
    const float* bout = (const float*)d_in[3];
    const float* W1   = (const float*)d_in[4];
    const float* b1   = (const float*)d_in[5];
    const float* W2   = (const float*)d_in[6];
    const float* b2   = (const float*)d_in[7];
    const float* g1   = (const float*)d_in[8];
    const float* be1  = (const float*)d_in[9];
    const float* g2   = (const float*)d_in[10];
    const float* be2  = (const float*)d_in[11];
    float* out = (float*)d_out;

    float *o1, *qkv, *attn, *res1, *o2, *hbuf;
    cudaGetSymbolAddress((void**)&o1,   g_o1);
    cudaGetSymbolAddress((void**)&qkv,  g_qkv);
    cudaGetSymbolAddress((void**)&attn, g_attn);
    cudaGetSymbolAddress((void**)&res1, g_res1);
    cudaGetSymbolAddress((void**)&o2,   g_o2);
    cudaGetSymbolAddress((void**)&hbuf, g_h);

    // 1) o1 = LN(x; g1, be1)
    ln_kernel<<<MROWS, 256>>>(x, g1, be1, o1);

    // 2) qkv = o1 @ Wa                        (4096 x 3072, K=1024)
    gemm128<false, false><<<dim3(3072/128, MROWS/128), 256>>>(
        o1, Wa, nullptr, nullptr, qkv, MROWS, 3072, EE);

    // 3) attention (causal flash, fp32)
    attn_kernel<<<dim3(LL/128, BB*NHH), 128>>>(qkv, attn);

    // 4) res1 = attn @ Wout + bout + x        (4096 x 1024, K=1024)
    gemm128<true, true><<<dim3(EE/128, MROWS/128), 256>>>(
        attn, Wout, bout, x, res1, MROWS, EE, EE);

    // 5) o2 = LN(res1; g2, be2)
    ln_kernel<<<MROWS, 256>>>(res1, g2, be2, o2);

    // 6) h = o2 @ W1 + b1                     (4096 x 4096, K=1024)
    gemm128<true, false><<<dim3(HIDD/128, MROWS/128), 256>>>(
        o2, W1, b1, nullptr, hbuf, MROWS, HIDD, EE);

    // 7) out = h @ W2 + b2 + x                (4096 x 1024, K=4096)
    gemm128<true, true><<<dim3(EE/128, MROWS/128), 256>>>(
        hbuf, W2, b2, x, out, MROWS, EE, HIDD);
}

// round 2
// speedup vs baseline: 1.5544x; 1.5544x over previous
#include <cuda_runtime.h>
#include <cuda_bf16.h>
#include <cstdint>
#include <cstddef>

// Problem constants
#define BB   2
#define LL   2048
#define EE   1024
#define NHH  16
#define DHH  64
#define HIDD 4096
#define MROWS (BB*LL)          // 4096

// ---------------------------------------------------------------------------
// Scratch arena (no cudaMalloc allowed)
// ---------------------------------------------------------------------------
constexpr size_t SZ_QKV  = (size_t)MROWS * 3072 * 4;   // fp32
constexpr size_t SZ_RES1 = (size_t)MROWS * EE * 4;     // fp32
constexpr size_t SZ_ACT  = (size_t)MROWS * EE * 2;     // bf16 (o1/att/o2 each h & l)
constexpr size_t SZ_H    = (size_t)MROWS * HIDD * 2;   // bf16
constexpr size_t SZ_WA   = (size_t)EE * 3072 * 2;
constexpr size_t SZ_WO   = (size_t)EE * EE * 2;
constexpr size_t SZ_W1   = (size_t)EE * HIDD * 2;
constexpr size_t SZ_W2   = (size_t)HIDD * EE * 2;

constexpr size_t OFF_QKV  = 0;
constexpr size_t OFF_RES1 = OFF_QKV  + SZ_QKV;
constexpr size_t OFF_O1H  = OFF_RES1 + SZ_RES1;
constexpr size_t OFF_O1L  = OFF_O1H  + SZ_ACT;
constexpr size_t OFF_ATH  = OFF_O1L  + SZ_ACT;
constexpr size_t OFF_ATL  = OFF_ATH  + SZ_ACT;
constexpr size_t OFF_O2H  = OFF_ATL  + SZ_ACT;
constexpr size_t OFF_O2L  = OFF_O2H  + SZ_ACT;
constexpr size_t OFF_HH   = OFF_O2L  + SZ_ACT;
constexpr size_t OFF_HL   = OFF_HH   + SZ_H;
constexpr size_t OFF_WAH  = OFF_HL   + SZ_H;
constexpr size_t OFF_WAL  = OFF_WAH  + SZ_WA;
constexpr size_t OFF_WOH  = OFF_WAL  + SZ_WA;
constexpr size_t OFF_WOL  = OFF_WOH  + SZ_WO;
constexpr size_t OFF_W1H  = OFF_WOL  + SZ_WO;
constexpr size_t OFF_W1L  = OFF_W1H  + SZ_W1;
constexpr size_t OFF_W2H  = OFF_W1L  + SZ_W1;
constexpr size_t OFF_W2L  = OFF_W2H  + SZ_W2;
constexpr size_t ARENA_SZ = OFF_W2L  + SZ_W2;

__device__ __align__(256) unsigned char g_arena[ARENA_SZ];

// ---------------------------------------------------------------------------
// Helpers
// ---------------------------------------------------------------------------
__device__ __forceinline__ void split2(float v, __nv_bfloat16& h, __nv_bfloat16& l) {
    h = __float2bfloat16(v);
    l = __float2bfloat16(v - __bfloat162float(h));
}

__device__ __forceinline__ void ldsm4(uint32_t* r, uint32_t a) {
    asm volatile("ldmatrix.sync.aligned.m8n8.x4.shared.b16 {%0,%1,%2,%3}, [%4];\n"
        : "=r"(r[0]), "=r"(r[1]), "=r"(r[2]), "=r"(r[3]) : "r"(a));
}
__device__ __forceinline__ void ldsm4t(uint32_t* r, uint32_t a) {
    asm volatile("ldmatrix.sync.aligned.m8n8.x4.trans.shared.b16 {%0,%1,%2,%3}, [%4];\n"
        : "=r"(r[0]), "=r"(r[1]), "=r"(r[2]), "=r"(r[3]) : "r"(a));
}
__device__ __forceinline__ void mma16816(float* c, const uint32_t* a, const uint32_t* b) {
    asm volatile(
        "mma.sync.aligned.m16n8k16.row.col.f32.bf16.bf16.f32 "
        "{%0,%1,%2,%3}, {%4,%5,%6,%7}, {%8,%9}, {%0,%1,%2,%3};\n"
        : "+f"(c[0]), "+f"(c[1]), "+f"(c[2]), "+f"(c[3])
        : "r"(a[0]), "r"(a[1]), "r"(a[2]), "r"(a[3]), "r"(b[0]), "r"(b[1]));
}

// ---------------------------------------------------------------------------
// Elementwise fp32 -> (bf16 hi, bf16 lo) splitter
// ---------------------------------------------------------------------------
__global__ __launch_bounds__(256)
void split_kernel(const float* __restrict__ in, __nv_bfloat16* __restrict__ oh,
                  __nv_bfloat16* __restrict__ ol, int n4) {
    int i = blockIdx.x * 256 + threadIdx.x;
    if (i >= n4) return;
    float4 v = ((const float4*)in)[i];
    __nv_bfloat16 h0,h1,h2,h3,l0,l1,l2,l3;
    split2(v.x,h0,l0); split2(v.y,h1,l1); split2(v.z,h2,l2); split2(v.w,h3,l3);
    __nv_bfloat162 a; a.x=h0; a.y=h1;
    __nv_bfloat162 b; b.x=h2; b.y=h3;
    __nv_bfloat162 c; c.x=l0; c.y=l1;
    __nv_bfloat162 d; d.x=l2; d.y=l3;
    *(__nv_bfloat162*)&oh[(size_t)i*4]     = a;
    *(__nv_bfloat162*)&oh[(size_t)i*4 + 2] = b;
    *(__nv_bfloat162*)&ol[(size_t)i*4]     = c;
    *(__nv_bfloat162*)&ol[(size_t)i*4 + 2] = d;
}

// ---------------------------------------------------------------------------
// LayerNorm writing split bf16 output
// ---------------------------------------------------------------------------
__global__ __launch_bounds__(256)
void ln_split_kernel(const float* __restrict__ in, const float* __restrict__ g,
                     const float* __restrict__ be, __nv_bfloat16* __restrict__ oh,
                     __nv_bfloat16* __restrict__ ol) {
    int row = blockIdx.x;
    int tid = threadIdx.x;
    const float4* ip = (const float4*)(in + (size_t)row * EE);
    float4 v = ip[tid];
    float s  = v.x + v.y + v.z + v.w;
    float ss = v.x*v.x + v.y*v.y + v.z*v.z + v.w*v.w;
    #pragma unroll
    for (int o = 16; o; o >>= 1) {
        s  += __shfl_xor_sync(0xffffffffu, s,  o);
        ss += __shfl_xor_sync(0xffffffffu, ss, o);
    }
    __shared__ float sm[8], sm2[8];
    int w = tid >> 5;
    if ((tid & 31) == 0) { sm[w] = s; sm2[w] = ss; }
    __syncthreads();
    float ts = 0.f, tss = 0.f;
    #pragma unroll
    for (int i = 0; i < 8; i++) { ts += sm[i]; tss += sm2[i]; }
    float mu  = ts  * (1.f / EE);
    float var = tss * (1.f / EE) - mu * mu;
    float rs  = rsqrtf(var + 1e-5f);
    float4 gv = ((const float4*)g)[tid];
    float4 bv = ((const float4*)be)[tid];
    float4 o;
    o.x = (v.x - mu) * rs * gv.x + bv.x;
    o.y = (v.y - mu) * rs * gv.y + bv.y;
    o.z = (v.z - mu) * rs * gv.z + bv.z;
    o.w = (v.w - mu) * rs * gv.w + bv.w;
    __nv_bfloat16 h0,h1,h2,h3,l0,l1,l2,l3;
    split2(o.x,h0,l0); split2(o.y,h1,l1); split2(o.z,h2,l2); split2(o.w,h3,l3);
    size_t base = (size_t)row * EE + tid * 4;
    __nv_bfloat162 p0; p0.x=h0; p0.y=h1;
    __nv_bfloat162 p1; p1.x=h2; p1.y=h3;
    __nv_bfloat162 p2; p2.x=l0; p2.y=l1;
    __nv_bfloat162 p3; p3.x=l2; p3.y=l3;
    *(__nv_bfloat162*)&oh[base]     = p0;
    *(__nv_bfloat162*)&oh[base + 2] = p1;
    *(__nv_bfloat162*)&ol[base]     = p2;
    *(__nv_bfloat162*)&ol[base + 2] = p3;
}

// ---------------------------------------------------------------------------
// bf16x3 tensor-core GEMM: C = (Ah+Al)(Bh+Bl) ~= AhBh + AhBl + AlBh
// A: MxK row-major (hi/lo), B: KxN row-major (hi/lo). Block 128x128, BK=32.
// 8 warps (2M x 4N), warp tile 64x32, mma.m16n8k16.
// ---------------------------------------------------------------------------
#define SA 40    // A smem row stride in halves (conflict-free for ldmatrix)
#define SB 136   // B smem row stride in halves

template<bool BIAS, bool RES, bool SPLIT>
__global__ __launch_bounds__(256)
void gemm_bf3(const __nv_bfloat16* __restrict__ Ah, const __nv_bfloat16* __restrict__ Al,
              const __nv_bfloat16* __restrict__ Bh, const __nv_bfloat16* __restrict__ Bl,
              const float* __restrict__ bias, const float* __restrict__ res,
              float* __restrict__ C, __nv_bfloat16* __restrict__ Ch,
              __nv_bfloat16* __restrict__ Cl, int M, int N, int K) {
    __shared__ __align__(16) __nv_bfloat16 sAh[128 * SA];
    __shared__ __align__(16) __nv_bfloat16 sAl[128 * SA];
    __shared__ __align__(16) __nv_bfloat16 sBh[32 * SB];
    __shared__ __align__(16) __nv_bfloat16 sBl[32 * SB];

    const int tid = threadIdx.x, lane = tid & 31, warp = tid >> 5;
    const int wm = (warp & 1) * 64, wn = (warp >> 1) * 32;
    const int rowBase = blockIdx.y * 128, colBase = blockIdx.x * 128;

    // global load assignments
    const int am = tid >> 2, ak = (tid & 3) * 8;   // A rows am, am+64 ; k cols ak..ak+7
    const int bk = tid >> 4, bn = (tid & 15) * 8;  // B rows bk, bk+16 ; n cols bn..bn+7

    const __nv_bfloat16* gAh = Ah + (size_t)(rowBase + am) * K + ak;
    const __nv_bfloat16* gAl = Al + (size_t)(rowBase + am) * K + ak;
    const __nv_bfloat16* gBh = Bh + (size_t)bk * N + colBase + bn;
    const __nv_bfloat16* gBl = Bl + (size_t)bk * N + colBase + bn;
    const size_t aStep = 64 * (size_t)K;
    const size_t bStep = 16 * (size_t)N;

    uint4 rah[2], ral[2], rbh[2], rbl[2];

#define LDG_TILE(kt) do {                                                     \
        rah[0] = *(const uint4*)(gAh + (kt));                                 \
        rah[1] = *(const uint4*)(gAh + aStep + (kt));                         \
        ral[0] = *(const uint4*)(gAl + (kt));                                 \
        ral[1] = *(const uint4*)(gAl + aStep + (kt));                         \
        rbh[0] = *(const uint4*)(gBh + (size_t)(kt) * N);                     \
        rbh[1] = *(const uint4*)(gBh + (size_t)(kt) * N + bStep);             \
        rbl[0] = *(const uint4*)(gBl + (size_t)(kt) * N);                     \
        rbl[1] = *(const uint4*)(gBl + (size_t)(kt) * N + bStep);             \
    } while (0)

#define STS_TILE() do {                                                       \
        *(uint4*)&sAh[am * SA + ak]        = rah[0];                          \
        *(uint4*)&sAh[(am + 64) * SA + ak] = rah[1];                          \
        *(uint4*)&sAl[am * SA + ak]        = ral[0];                          \
        *(uint4*)&sAl[(am + 64) * SA + ak] = ral[1];                          \
        *(uint4*)&sBh[bk * SB + bn]        = rbh[0];                          \
        *(uint4*)&sBh[(bk + 16) * SB + bn] = rbh[1];                          \
        *(uint4*)&sBl[bk * SB + bn]        = rbl[0];                          \
        *(uint4*)&sBl[(bk + 16) * SB + bn] = rbl[1];                          \
    } while (0)

    const uint32_t uAh = (uint32_t)__cvta_generic_to_shared(sAh);
    const uint32_t uAl = (uint32_t)__cvta_generic_to_shared(sAl);
    const uint32_t uBh = (uint32_t)__cvta_generic_to_shared(sBh);
    const uint32_t uBl = (uint32_t)__cvta_generic_to_shared(sBl);

    // ldmatrix lane offsets
    const int rA = (lane & 7) + ((lane >> 3) & 1) * 8;  // row within 16
    const int cA = (lane >> 4) * 8;                     // k offset 0/8
    const int rB = (lane & 7) + ((lane >> 3) & 1) * 8;  // k within 16
    const int cB = (lane >> 4) * 8;                     // n offset 0/8

    float acc[4][4][4];
    #pragma unroll
    for (int i = 0; i < 4; i++)
        #pragma unroll
        for (int j = 0; j < 4; j++)
            #pragma unroll
            for (int k = 0; k < 4; k++) acc[i][j][k] = 0.f;

    LDG_TILE(0);
    STS_TILE();
    __syncthreads();

    for (int kt = 0; kt < K; kt += 32) {
        if (kt + 32 < K) LDG_TILE(kt + 32);
        #pragma unroll
        for (int kk = 0; kk < 32; kk += 16) {
            uint32_t bhf[2][4], blf[2][4];
            #pragma unroll
            for (int j = 0; j < 2; j++) {
                uint32_t offB = (uint32_t)(((kk + rB) * SB + wn + j * 16 + cB) * 2);
                ldsm4t(bhf[j], uBh + offB);
                ldsm4t(blf[j], uBl + offB);
            }
            #pragma unroll
            for (int mi = 0; mi < 4; mi++) {
                uint32_t offA = (uint32_t)(((wm + mi * 16 + rA) * SA + kk + cA) * 2);
                uint32_t ahf[4], alf[4];
                ldsm4(ahf, uAh + offA);
                ldsm4(alf, uAl + offA);
                #pragma unroll
                for (int ni = 0; ni < 4; ni++) {
                    const uint32_t* bh = &bhf[ni >> 1][(ni & 1) * 2];
                    const uint32_t* bl = &blf[ni >> 1][(ni & 1) * 2];
                    mma16816(acc[mi][ni], ahf, bh);
                    mma16816(acc[mi][ni], alf, bh);
                    mma16816(acc[mi][ni], ahf, bl);
                }
            }
        }
        __syncthreads();
        if (kt + 32 < K) { STS_TILE(); __syncthreads(); }
    }

    // epilogue
    const int g = lane >> 2, tg = lane & 3;
    #pragma unroll
    for (int mi = 0; mi < 4; mi++) {
        #pragma unroll
        for (int ni = 0; ni < 4; ni++) {
            int r0 = rowBase + wm + mi * 16 + g;
            int c0 = colBase + wn + ni * 8 + tg * 2;
            float* a = acc[mi][ni];
            float2 v0 = make_float2(a[0], a[1]);
            float2 v1 = make_float2(a[2], a[3]);
            if (BIAS) {
                float bx = bias[c0], by = bias[c0 + 1];
                v0.x += bx; v0.y += by; v1.x += bx; v1.y += by;
            }
            if (RES) {
                float2 q0 = *(const float2*)&res[(size_t)r0 * N + c0];
                float2 q1 = *(const float2*)&res[(size_t)(r0 + 8) * N + c0];
                v0.x += q0.x; v0.y += q0.y; v1.x += q1.x; v1.y += q1.y;
            }
            if (SPLIT) {
                __nv_bfloat16 h0,h1,l0,l1;
                split2(v0.x, h0, l0); split2(v0.y, h1, l1);
                __nv_bfloat162 ph; ph.x = h0; ph.y = h1;
                __nv_bfloat162 pl; pl.x = l0; pl.y = l1;
                *(__nv_bfloat162*)&Ch[(size_t)r0 * N + c0] = ph;
                *(__nv_bfloat162*)&Cl[(size_t)r0 * N + c0] = pl;
                split2(v1.x, h0, l0); split2(v1.y, h1, l1);
                ph.x = h0; ph.y = h1; pl.x = l0; pl.y = l1;
                *(__nv_bfloat162*)&Ch[(size_t)(r0 + 8) * N + c0] = ph;
                *(__nv_bfloat162*)&Cl[(size_t)(r0 + 8) * N + c0] = pl;
            } else {
                *(float2*)&C[(size_t)r0 * N + c0] = v0;
                *(float2*)&C[(size_t)(r0 + 8) * N + c0] = v1;
            }
        }
    }
#undef LDG_TILE
#undef STS_TILE
}

// ---------------------------------------------------------------------------
// Causal flash attention (fp32 SIMT), epilogue writes split bf16.
// qkv layout: row (b*L+l), col hd*192 + [q|k|v]*64 + d
// ---------------------------------------------------------------------------
__global__ __launch_bounds__(128)
void attn_kernel(const float* __restrict__ qkv, __nv_bfloat16* __restrict__ outh,
                 __nv_bfloat16* __restrict__ outl) {
    __shared__ float4 sK[64 * 16];
    __shared__ float4 sV[64 * 16];
    int tid   = threadIdx.x;
    int chunk = blockIdx.x;
    int bh    = blockIdx.y;
    int b     = bh >> 4, hd = bh & 15;
    int q     = chunk * 128 + tid;

    size_t rowq = (size_t)(b * LL + q) * 3072 + hd * 192;
    float4 qv[16];
    #pragma unroll
    for (int i = 0; i < 16; i++) qv[i] = *(const float4*)&qkv[rowq + i * 4];
    const float scale = 0.125f;
    #pragma unroll
    for (int i = 0; i < 16; i++) {
        qv[i].x *= scale; qv[i].y *= scale; qv[i].z *= scale; qv[i].w *= scale;
    }

    float4 ov[16];
    #pragma unroll
    for (int i = 0; i < 16; i++) ov[i] = make_float4(0.f, 0.f, 0.f, 0.f);
    float mi = -1e30f, li = 0.f;

    int ntiles = chunk * 2 + 2;
    for (int kt = 0; kt < ntiles; kt++) {
        int kstart = kt * 64;
        #pragma unroll
        for (int t = 0; t < 8; t++) {
            int id = tid + t * 128;
            int j  = id >> 4, d4 = id & 15;
            size_t base = (size_t)(b * LL + kstart + j) * 3072 + hd * 192;
            sK[id] = *(const float4*)&qkv[base + 64  + d4 * 4];
            sV[id] = *(const float4*)&qkv[base + 128 + d4 * 4];
        }
        __syncthreads();

        #pragma unroll 1
        for (int j0 = 0; j0 < 64; j0 += 16) {
            float s[16];
            #pragma unroll
            for (int jj = 0; jj < 16; jj++) {
                int j = j0 + jj;
                float a = 0.f;
                #pragma unroll
                for (int d = 0; d < 16; d++) {
                    float4 kv = sK[j * 16 + d];
                    a += qv[d].x * kv.x + qv[d].y * kv.y
                       + qv[d].z * kv.z + qv[d].w * kv.w;
                }
                s[jj] = (kstart + j > q) ? -1e30f : a;
            }
            float mt = mi;
            #pragma unroll
            for (int jj = 0; jj < 16; jj++) mt = fmaxf(mt, s[jj]);
            float c = __expf(mi - mt);
            li *= c;
            #pragma unroll
            for (int i = 0; i < 16; i++) {
                ov[i].x *= c; ov[i].y *= c; ov[i].z *= c; ov[i].w *= c;
            }
            #pragma unroll
            for (int jj = 0; jj < 16; jj++) {
                float p = __expf(s[jj] - mt);
                li += p;
                int j = j0 + jj;
                #pragma unroll
                for (int d = 0; d < 16; d++) {
                    float4 vv = sV[j * 16 + d];
                    ov[d].x += p * vv.x; ov[d].y += p * vv.y;
                    ov[d].z += p * vv.z; ov[d].w += p * vv.w;
                }
            }
            mi = mt;
        }
        __syncthreads();
    }

    float inv = 1.f / li;
    size_t orow = (size_t)(b * LL + q) * EE + hd * DHH;
    #pragma unroll
    for (int i = 0; i < 16; i++) {
        float4 o4 = ov[i];
        o4.x *= inv; o4.y *= inv; o4.z *= inv; o4.w *= inv;
        __nv_bfloat16 h0,h1,h2,h3,l0,l1,l2,l3;
        split2(o4.x,h0,l0); split2(o4.y,h1,l1); split2(o4.z,h2,l2); split2(o4.w,h3,l3);
        __nv_bfloat162 p0; p0.x=h0; p0.y=h1;
        __nv_bfloat162 p1; p1.x=h2; p1.y=h3;
        __nv_bfloat162 p2; p2.x=l0; p2.y=l1;
        __nv_bfloat162 p3; p3.x=l2; p3.y=l3;
        *(__nv_bfloat162*)&outh[orow + i * 4]     = p0;
        *(__nv_bfloat162*)&outh[orow + i * 4 + 2] = p1;
        *(__nv_bfloat162*)&outl[orow + i * 4]     = p2;
        *(__nv_bfloat162*)&outl[orow + i * 4 + 2] = p3;
    }
}

// ---------------------------------------------------------------------------
// Launch
// ---------------------------------------------------------------------------
extern "C" void kernel_launch(void* const* d_in, const int* in_sizes, int n_in,
                              void* d_out, int out_size) {
    const float* x    = (const float*)d_in[0];
    const float* Wa   = (const float*)d_in[1];
    const float* Wout = (const float*)d_in[2];
    const float* bout = (const float*)d_in[3];
    const float* W1   = (const float*)d_in[4];
    const float* b1   = (const float*)d_in[5];
    const float* W2   = (const float*)d_in[6];
    const float* b2   = (const float*)d_in[7];
    const float* g1   = (const float*)d_in[8];
    const float* be1  = (const float*)d_in[9];
    const float* g2   = (const float*)d_in[10];
    const float* be2  = (const float*)d_in[11];
    float* out = (float*)d_out;

    unsigned char* arena;
    cudaGetSymbolAddress((void**)&arena, g_arena);

    float* qkv  = (float*)(arena + OFF_QKV);
    float* res1 = (float*)(arena + OFF_RES1);
    __nv_bfloat16* o1h = (__nv_bfloat16*)(arena + OFF_O1H);
    __nv_bfloat16* o1l = (__nv_bfloat16*)(arena + OFF_O1L);
    __nv_bfloat16* ath = (__nv_bfloat16*)(arena + OFF_ATH);
    __nv_bfloat16* atl = (__nv_bfloat16*)(arena + OFF_ATL);
    __nv_bfloat16* o2h = (__nv_bfloat16*)(arena + OFF_O2H);
    __nv_bfloat16* o2l = (__nv_bfloat16*)(arena + OFF_O2L);
    __nv_bfloat16* hh  = (__nv_bfloat16*)(arena + OFF_HH);
    __nv_bfloat16* hl  = (__nv_bfloat16*)(arena + OFF_HL);
    __nv_bfloat16* wah = (__nv_bfloat16*)(arena + OFF_WAH);
    __nv_bfloat16* wal = (__nv_bfloat16*)(arena + OFF_WAL);
    __nv_bfloat16* woh = (__nv_bfloat16*)(arena + OFF_WOH);
    __nv_bfloat16* wol = (__nv_bfloat16*)(arena + OFF_WOL);
    __nv_bfloat16* w1h = (__nv_bfloat16*)(arena + OFF_W1H);
    __nv_bfloat16* w1l = (__nv_bfloat16*)(arena + OFF_W1L);
    __nv_bfloat16* w2h = (__nv_bfloat16*)(arena + OFF_W2H);
    __nv_bfloat16* w2l = (__nv_bfloat16*)(arena + OFF_W2L);

    // weight splits
    split_kernel<<<(EE*3072/4 + 255)/256, 256>>>(Wa,   wah, wal, EE*3072/4);
    split_kernel<<<(EE*EE/4   + 255)/256, 256>>>(Wout, woh, wol, EE*EE/4);
    split_kernel<<<(EE*HIDD/4 + 255)/256, 256>>>(W1,   w1h, w1l, EE*HIDD/4);
    split_kernel<<<(HIDD*EE/4 + 255)/256, 256>>>(W2,   w2h, w2l, HIDD*EE/4);

    // 1) o1 = LN(x)
    ln_split_kernel<<<MROWS, 256>>>(x, g1, be1, o1h, o1l);

    // 2) qkv = o1 @ Wa
    gemm_bf3<false,false,false><<<dim3(3072/128, MROWS/128), 256>>>(
        o1h, o1l, wah, wal, nullptr, nullptr, qkv, nullptr, nullptr,
        MROWS, 3072, EE);

    // 3) attention
    attn_kernel<<<dim3(LL/128, BB*NHH), 128>>>(qkv, ath, atl);

    // 4) res1 = attn @ Wout + bout + x
    gemm_bf3<true,true,false><<<dim3(EE/128, MROWS/128), 256>>>(
        ath, atl, woh, wol, bout, x, res1, nullptr, nullptr,
        MROWS, EE, EE);

    // 5) o2 = LN(res1)
    ln_split_kernel<<<MROWS, 256>>>(res1, g2, be2, o2h, o2l);

    // 6) h = o2 @ W1 + b1  (split output)
    gemm_bf3<true,false,true><<<dim3(HIDD/128, MROWS/128), 256>>>(
        o2h, o2l, w1h, w1l, b1, nullptr, nullptr, hh, hl,
        MROWS, HIDD, EE);

    // 7) out = h @ W2 + b2 + x
    gemm_bf3<true,true,false><<<dim3(EE/128, MROWS/128), 256>>>(
        hh, hl, w2h, w2l, b2, x, out, nullptr, nullptr,
        MROWS, EE, HIDD);
}

// round 3
// speedup vs baseline: 2.8859x; 1.8566x over previous
#include <cuda_runtime.h>
#include <cuda_bf16.h>
#include <cstdint>
#include <cstddef>

// Problem constants
#define BB   2
#define LL   2048
#define EE   1024
#define NHH  16
#define DHH  64
#define HIDD 4096
#define MROWS (BB*LL)          // 4096

typedef __nv_bfloat16 bf;

// ---------------------------------------------------------------------------
// Scratch arena
// ---------------------------------------------------------------------------
constexpr size_t SZ_QKV1 = (size_t)MROWS * 3072 * 2;   // bf16 (h or l)
constexpr size_t SZ_RES1 = (size_t)MROWS * EE * 4;     // fp32
constexpr size_t SZ_ACT  = (size_t)MROWS * EE * 2;     // bf16
constexpr size_t SZ_H    = (size_t)MROWS * HIDD * 2;   // bf16
constexpr size_t SZ_WA   = (size_t)EE * 3072 * 2;
constexpr size_t SZ_WO   = (size_t)EE * EE * 2;
constexpr size_t SZ_W1   = (size_t)EE * HIDD * 2;
constexpr size_t SZ_W2   = (size_t)HIDD * EE * 2;

constexpr size_t OFF_QKVH = 0;
constexpr size_t OFF_QKVL = OFF_QKVH + SZ_QKV1;
constexpr size_t OFF_RES1 = OFF_QKVL + SZ_QKV1;
constexpr size_t OFF_ATH  = OFF_RES1 + SZ_RES1;
constexpr size_t OFF_ATL  = OFF_ATH  + SZ_ACT;
constexpr size_t OFF_O1H  = OFF_ATL  + SZ_ACT;
constexpr size_t OFF_O1L  = OFF_O1H  + SZ_ACT;
constexpr size_t OFF_O2H  = OFF_O1L  + SZ_ACT;
constexpr size_t OFF_O2L  = OFF_O2H  + SZ_ACT;
constexpr size_t OFF_HH   = OFF_O2L  + SZ_ACT;
constexpr size_t OFF_HL   = OFF_HH   + SZ_H;
constexpr size_t OFF_WAH  = OFF_HL   + SZ_H;
constexpr size_t OFF_WAL  = OFF_WAH  + SZ_WA;
constexpr size_t OFF_WOH  = OFF_WAL  + SZ_WA;
constexpr size_t OFF_WOL  = OFF_WOH  + SZ_WO;
constexpr size_t OFF_W1H  = OFF_WOL  + SZ_WO;
constexpr size_t OFF_W1L  = OFF_W1H  + SZ_W1;
constexpr size_t OFF_W2H  = OFF_W1L  + SZ_W1;
constexpr size_t OFF_W2L  = OFF_W2H  + SZ_W2;
constexpr size_t ARENA_SZ = OFF_W2L  + SZ_W2;

__device__ __align__(256) unsigned char g_arena[ARENA_SZ];

// ---------------------------------------------------------------------------
// Helpers
// ---------------------------------------------------------------------------
__device__ __forceinline__ void split2(float v, bf& h, bf& l) {
    h = __float2bfloat16(v);
    l = __float2bfloat16(v - __bfloat162float(h));
}
__device__ __forceinline__ uint32_t pack_bf2(bf a, bf b) {
    __nv_bfloat162 t; t.x = a; t.y = b;
    return *(uint32_t*)&t;
}
__device__ __forceinline__ void ldsm4(uint32_t* r, uint32_t a) {
    asm volatile("ldmatrix.sync.aligned.m8n8.x4.shared.b16 {%0,%1,%2,%3}, [%4];\n"
        : "=r"(r[0]), "=r"(r[1]), "=r"(r[2]), "=r"(r[3]) : "r"(a));
}
__device__ __forceinline__ void ldsm4t(uint32_t* r, uint32_t a) {
    asm volatile("ldmatrix.sync.aligned.m8n8.x4.trans.shared.b16 {%0,%1,%2,%3}, [%4];\n"
        : "=r"(r[0]), "=r"(r[1]), "=r"(r[2]), "=r"(r[3]) : "r"(a));
}
__device__ __forceinline__ void mma16816(float* c, const uint32_t* a, uint32_t b0, uint32_t b1) {
    asm volatile(
        "mma.sync.aligned.m16n8k16.row.col.f32.bf16.bf16.f32 "
        "{%0,%1,%2,%3}, {%4,%5,%6,%7}, {%8,%9}, {%0,%1,%2,%3};\n"
        : "+f"(c[0]), "+f"(c[1]), "+f"(c[2]), "+f"(c[3])
        : "r"(a[0]), "r"(a[1]), "r"(a[2]), "r"(a[3]), "r"(b0), "r"(b1));
}
__device__ __forceinline__ void cp16(uint32_t dst, const void* src) {
    asm volatile("cp.async.cg.shared.global [%0], [%1], 16;\n" :: "r"(dst), "l"(src));
}
#define CP_COMMIT() asm volatile("cp.async.commit_group;\n" ::: "memory")
#define CP_WAIT1()  asm volatile("cp.async.wait_group 1;\n" ::: "memory")

// ---------------------------------------------------------------------------
// fp32 -> (bf16 hi, bf16 lo) splitter (weights)
// ---------------------------------------------------------------------------
__global__ __launch_bounds__(256)
void split_kernel(const float* __restrict__ in, bf* __restrict__ oh,
                  bf* __restrict__ ol, int n4) {
    int i = blockIdx.x * 256 + threadIdx.x;
    if (i >= n4) return;
    float4 v = ((const float4*)in)[i];
    bf h0,h1,h2,h3,l0,l1,l2,l3;
    split2(v.x,h0,l0); split2(v.y,h1,l1); split2(v.z,h2,l2); split2(v.w,h3,l3);
    *(uint32_t*)&oh[(size_t)i*4]     = pack_bf2(h0,h1);
    *(uint32_t*)&oh[(size_t)i*4 + 2] = pack_bf2(h2,h3);
    *(uint32_t*)&ol[(size_t)i*4]     = pack_bf2(l0,l1);
    *(uint32_t*)&ol[(size_t)i*4 + 2] = pack_bf2(l2,l3);
}

// ---------------------------------------------------------------------------
// LayerNorm writing split bf16 output
// ---------------------------------------------------------------------------
__global__ __launch_bounds__(256)
void ln_split_kernel(const float* __restrict__ in, const float* __restrict__ g,
                     const float* __restrict__ be, bf* __restrict__ oh,
                     bf* __restrict__ ol) {
    int row = blockIdx.x;
    int tid = threadIdx.x;
    const float4* ip = (const float4*)(in + (size_t)row * EE);
    float4 v = ip[tid];
    float s  = v.x + v.y + v.z + v.w;
    float ss = v.x*v.x + v.y*v.y + v.z*v.z + v.w*v.w;
    #pragma unroll
    for (int o = 16; o; o >>= 1) {
        s  += __shfl_xor_sync(0xffffffffu, s,  o);
        ss += __shfl_xor_sync(0xffffffffu, ss, o);
    }
    __shared__ float sm[8], sm2[8];
    int w = tid >> 5;
    if ((tid & 31) == 0) { sm[w] = s; sm2[w] = ss; }
    __syncthreads();
    float ts = 0.f, tss = 0.f;
    #pragma unroll
    for (int i = 0; i < 8; i++) { ts += sm[i]; tss += sm2[i]; }
    float mu  = ts  * (1.f / EE);
    float var = tss * (1.f / EE) - mu * mu;
    float rs  = rsqrtf(var + 1e-5f);
    float4 gv = ((const float4*)g)[tid];
    float4 bv = ((const float4*)be)[tid];
    float4 o;
    o.x = (v.x - mu) * rs * gv.x + bv.x;
    o.y = (v.y - mu) * rs * gv.y + bv.y;
    o.z = (v.z - mu) * rs * gv.z + bv.z;
    o.w = (v.w - mu) * rs * gv.w + bv.w;
    bf h0,h1,h2,h3,l0,l1,l2,l3;
    split2(o.x,h0,l0); split2(o.y,h1,l1); split2(o.z,h2,l2); split2(o.w,h3,l3);
    size_t base = (size_t)row * EE + tid * 4;
    *(uint32_t*)&oh[base]     = pack_bf2(h0,h1);
    *(uint32_t*)&oh[base + 2] = pack_bf2(h2,h3);
    *(uint32_t*)&ol[base]     = pack_bf2(l0,l1);
    *(uint32_t*)&ol[base + 2] = pack_bf2(l2,l3);
}

// ---------------------------------------------------------------------------
// bf16x3 tensor-core GEMM, 2-stage cp.async pipeline.
// Block 128x128, BK=32, 8 warps (2Mx4N), warp tile 64x32, mma.m16n8k16.
// Dynamic smem: 2 stages x (A 128x40 h/l + B 32x136 h/l) halves.
// ---------------------------------------------------------------------------
#define SA 40
#define SB 136
// per-stage offsets in halves
#define G_AH 0
#define G_AL 5120
#define G_BH 10240
#define G_BL 14592
#define G_STG 18944              // halves per stage
#define GEMM_SMEM (2 * G_STG * 2)  // bytes = 75776

template<bool BIAS, bool RES, bool SPLIT>
__global__ __launch_bounds__(256)
void gemm_bf3(const bf* __restrict__ Ah, const bf* __restrict__ Al,
              const bf* __restrict__ Bh, const bf* __restrict__ Bl,
              const float* __restrict__ bias, const float* __restrict__ res,
              float* __restrict__ C, bf* __restrict__ Ch, bf* __restrict__ Cl,
              int M, int N, int K) {
    extern __shared__ __align__(16) bf smem[];
    const uint32_t base = (uint32_t)__cvta_generic_to_shared(smem);

    const int tid = threadIdx.x, lane = tid & 31, warp = tid >> 5;
    const int wm = (warp & 1) * 64, wn = (warp >> 1) * 32;
    const int rowBase = blockIdx.y * 128, colBase = blockIdx.x * 128;

    const int am = tid >> 2, ak = (tid & 3) * 8;
    const int bk = tid >> 4, bn = (tid & 15) * 8;

    const bf* gAh = Ah + (size_t)(rowBase + am) * K + ak;
    const bf* gAl = Al + (size_t)(rowBase + am) * K + ak;
    const bf* gBh = Bh + (size_t)bk * N + colBase + bn;
    const bf* gBl = Bl + (size_t)bk * N + colBase + bn;
    const size_t aStep = 64 * (size_t)K;
    const size_t bStep = 16 * (size_t)N;

    // smem sts offsets (bytes), stage-relative
    const uint32_t sA0 = (uint32_t)((am * SA + ak) * 2);
    const uint32_t sA1 = (uint32_t)(((am + 64) * SA + ak) * 2);
    const uint32_t sB0 = (uint32_t)((bk * SB + bn) * 2);
    const uint32_t sB1 = (uint32_t)(((bk + 16) * SB + bn) * 2);

#define G_ISSUE(kt, s) do {                                                   \
        uint32_t sb = base + (uint32_t)(s) * (G_STG * 2);                     \
        cp16(sb + G_AH*2 + sA0, gAh + (kt));                                  \
        cp16(sb + G_AH*2 + sA1, gAh + aStep + (kt));                          \
        cp16(sb + G_AL*2 + sA0, gAl + (kt));                                  \
        cp16(sb + G_AL*2 + sA1, gAl + aStep + (kt));                          \
        cp16(sb + G_BH*2 + sB0, gBh + (size_t)(kt) * N);                      \
        cp16(sb + G_BH*2 + sB1, gBh + (size_t)(kt) * N + bStep);              \
        cp16(sb + G_BL*2 + sB0, gBl + (size_t)(kt) * N);                      \
        cp16(sb + G_BL*2 + sB1, gBl + (size_t)(kt) * N + bStep);              \
    } while (0)

    const int rA = lane & 15, cA = (lane >> 4) * 8;
    const int rB = lane & 15, cB = (lane >> 4) * 8;

    float acc[4][4][4];
    #pragma unroll
    for (int i = 0; i < 4; i++)
        #pragma unroll
        for (int j = 0; j < 4; j++)
            #pragma unroll
            for (int k = 0; k < 4; k++) acc[i][j][k] = 0.f;

    G_ISSUE(0, 0); CP_COMMIT();
    G_ISSUE(32, 1); CP_COMMIT();

    const int nk = K >> 5;
    for (int i = 0; i < nk; i++) {
        CP_WAIT1();
        __syncthreads();
        const int s = i & 1;
        const uint32_t uAh = base + s * (G_STG*2) + G_AH*2;
        const uint32_t uAl = base + s * (G_STG*2) + G_AL*2;
        const uint32_t uBh = base + s * (G_STG*2) + G_BH*2;
        const uint32_t uBl = base + s * (G_STG*2) + G_BL*2;

        #pragma unroll
        for (int kk = 0; kk < 32; kk += 16) {
            uint32_t bhf[2][4], blf[2][4];
            #pragma unroll
            for (int j = 0; j < 2; j++) {
                uint32_t offB = (uint32_t)(((kk + rB) * SB + wn + j * 16 + cB) * 2);
                ldsm4t(bhf[j], uBh + offB);
                ldsm4t(blf[j], uBl + offB);
            }
            #pragma unroll
            for (int mi = 0; mi < 4; mi++) {
                uint32_t offA = (uint32_t)(((wm + mi * 16 + rA) * SA + kk + cA) * 2);
                uint32_t ahf[4], alf[4];
                ldsm4(ahf, uAh + offA);
                ldsm4(alf, uAl + offA);
                #pragma unroll
                for (int ni = 0; ni < 4; ni++) {
                    uint32_t b0 = bhf[ni >> 1][(ni & 1) * 2];
                    uint32_t b1 = bhf[ni >> 1][(ni & 1) * 2 + 1];
                    uint32_t c0 = blf[ni >> 1][(ni & 1) * 2];
                    uint32_t c1 = blf[ni >> 1][(ni & 1) * 2 + 1];
                    mma16816(acc[mi][ni], ahf, b0, b1);
                    mma16816(acc[mi][ni], alf, b0, b1);
                    mma16816(acc[mi][ni], ahf, c0, c1);
                }
            }
        }
        __syncthreads();
        if (i + 2 < nk) G_ISSUE((i + 2) * 32, s);
        CP_COMMIT();
    }
#undef G_ISSUE

    // epilogue
    const int g = lane >> 2, tg = lane & 3;
    #pragma unroll
    for (int mi = 0; mi < 4; mi++) {
        #pragma unroll
        for (int ni = 0; ni < 4; ni++) {
            int r0 = rowBase + wm + mi * 16 + g;
            int c0 = colBase + wn + ni * 8 + tg * 2;
            float* a = acc[mi][ni];
            float2 v0 = make_float2(a[0], a[1]);
            float2 v1 = make_float2(a[2], a[3]);
            if (BIAS) {
                float bx = bias[c0], by = bias[c0 + 1];
                v0.x += bx; v0.y += by; v1.x += bx; v1.y += by;
            }
            if (RES) {
                float2 q0 = *(const float2*)&res[(size_t)r0 * N + c0];
                float2 q1 = *(const float2*)&res[(size_t)(r0 + 8) * N + c0];
                v0.x += q0.x; v0.y += q0.y; v1.x += q1.x; v1.y += q1.y;
            }
            if (SPLIT) {
                bf h0,h1,l0,l1;
                split2(v0.x, h0, l0); split2(v0.y, h1, l1);
                *(uint32_t*)&Ch[(size_t)r0 * N + c0] = pack_bf2(h0,h1);
                *(uint32_t*)&Cl[(size_t)r0 * N + c0] = pack_bf2(l0,l1);
                split2(v1.x, h0, l0); split2(v1.y, h1, l1);
                *(uint32_t*)&Ch[(size_t)(r0 + 8) * N + c0] = pack_bf2(h0,h1);
                *(uint32_t*)&Cl[(size_t)(r0 + 8) * N + c0] = pack_bf2(l0,l1);
            } else {
                *(float2*)&C[(size_t)r0 * N + c0] = v0;
                *(float2*)&C[(size_t)(r0 + 8) * N + c0] = v1;
            }
        }
    }
}

// ---------------------------------------------------------------------------
// Tensor-core causal flash attention.
// qkv split bf16 [row][3072]: h*192 + {q:0, k:64, v:128} + d.
// Block: 128 q rows x one (b,h). 256 threads = 8 warps x 16 rows.
// K/V tiles of 64 keys, 2-stage cp.async. QK: bf16x3; PV: Ph/Pl x Vh/Vl (3 terms).
// Dynamic smem halves: Qh 0, Ql 9216, stage s at 18432+s*18432:
//   Kh +0, Kl +4608, Vh +9216, Vl +13824  (row stride 72 halves)
// ---------------------------------------------------------------------------
#define AQ_H 0
#define AQ_L 9216
#define AKV_BASE 18432
#define AKV_STG  18432
#define A_KH 0
#define A_KL 4608
#define A_VH 9216
#define A_VL 13824
#define ATTN_SMEM ((18432 + 2*18432) * 2)   // 110592 bytes

__global__ __launch_bounds__(256)
void attn_tc(const bf* __restrict__ qkvh, const bf* __restrict__ qkvl,
             bf* __restrict__ outh, bf* __restrict__ outl) {
    extern __shared__ __align__(16) bf smem[];
    const uint32_t base = (uint32_t)__cvta_generic_to_shared(smem);

    const int tid = threadIdx.x, lane = tid & 31, warp = tid >> 5;
    const int qtile = blockIdx.x, bh = blockIdx.y;
    const int b = bh >> 4, h = bh & 15;
    const int qbase = qtile * 128;
    const int wrow = warp * 16;
    const int g = lane >> 2, tg = lane & 3;
    const int rA = lane & 15, cA = (lane >> 4) * 8;

    // ---- issue Q loads (group 0 with KV0) ----
    {
        #pragma unroll
        for (int t = 0; t < 4; t++) {
            int id = tid + t * 256;           // 0..1023
            int r = id >> 3, c = (id & 7) * 8;
            size_t src = (size_t)(b * LL + qbase + r) * 3072 + h * 192 + c;
            uint32_t dst = (uint32_t)((r * 72 + c) * 2);
            cp16(base + AQ_H*2 + dst, qkvh + src);
            cp16(base + AQ_L*2 + dst, qkvl + src);
        }
    }
#define KV_ISSUE(kstart, s) do {                                              \
        uint32_t sb = base + (AKV_BASE + (s) * AKV_STG) * 2;                  \
        _Pragma("unroll")                                                     \
        for (int t = 0; t < 2; t++) {                                         \
            int id = tid + t * 256;                                           \
            int r = id >> 3, c = (id & 7) * 8;                                \
            size_t rowb = (size_t)(b * LL + (kstart) + r) * 3072 + h * 192;   \
            uint32_t dst = (uint32_t)((r * 72 + c) * 2);                      \
            cp16(sb + A_KH*2 + dst, qkvh + rowb + 64 + c);                    \
            cp16(sb + A_KL*2 + dst, qkvl + rowb + 64 + c);                    \
            cp16(sb + A_VH*2 + dst, qkvh + rowb + 128 + c);                   \
            cp16(sb + A_VL*2 + dst, qkvl + rowb + 128 + c);                   \
        }                                                                     \
    } while (0)

    const int ntiles = qtile * 2 + 2;
    KV_ISSUE(0, 0); CP_COMMIT();
    if (ntiles > 1) KV_ISSUE(64, 1);
    CP_COMMIT();

    CP_WAIT1();
    __syncthreads();

    // ---- Q fragments (loop invariant) ----
    uint32_t qh[4][4], ql[4][4];
    #pragma unroll
    for (int j = 0; j < 4; j++) {
        uint32_t off = (uint32_t)(((wrow + rA) * 72 + j * 16 + cA) * 2);
        ldsm4(qh[j], base + AQ_H*2 + off);
        ldsm4(ql[j], base + AQ_L*2 + off);
    }

    float o[8][4];
    #pragma unroll
    for (int i = 0; i < 8; i++)
        #pragma unroll
        for (int k = 0; k < 4; k++) o[i][k] = 0.f;
    float m0 = -1e30f, m1 = -1e30f, li0 = 0.f, li1 = 0.f;

    const int row0 = qbase + wrow + g;      // thread's first q row (l index)
    const int row1 = row0 + 8;

    for (int it = 0; it < ntiles; it++) {
        if (it > 0) { CP_WAIT1(); __syncthreads(); }
        const int s = it & 1;
        const int kstart = it * 64;
        const uint32_t uK_h = base + (AKV_BASE + s * AKV_STG + A_KH) * 2;
        const uint32_t uK_l = base + (AKV_BASE + s * AKV_STG + A_KL) * 2;
        const uint32_t uV_h = base + (AKV_BASE + s * AKV_STG + A_VH) * 2;
        const uint32_t uV_l = base + (AKV_BASE + s * AKV_STG + A_VL) * 2;

        // ---- S = Q @ K^T (bf16x3) ----
        float sc[8][4];
        #pragma unroll
        for (int i = 0; i < 8; i++)
            #pragma unroll
            for (int k = 0; k < 4; k++) sc[i][k] = 0.f;

        #pragma unroll
        for (int j = 0; j < 4; j++) {          // d blocks of 16
            #pragma unroll
            for (int kb = 0; kb < 4; kb++) {   // key blocks of 16
                uint32_t off = (uint32_t)(((kb * 16 + rA) * 72 + j * 16 + cA) * 2);
                uint32_t kh[4], kl[4];
                ldsm4(kh, uK_h + off);
                ldsm4(kl, uK_l + off);
                int n0 = kb * 2;
                mma16816(sc[n0],   qh[j], kh[0], kh[2]);
                mma16816(sc[n0],   ql[j], kh[0], kh[2]);
                mma16816(sc[n0],   qh[j], kl[0], kl[2]);
                mma16816(sc[n0+1], qh[j], kh[1], kh[3]);
                mma16816(sc[n0+1], ql[j], kh[1], kh[3]);
                mma16816(sc[n0+1], qh[j], kl[1], kl[3]);
            }
        }

        // ---- scale + causal mask ----
        const bool need_mask = (kstart + 63) > (qbase + wrow);
        #pragma unroll
        for (int ni = 0; ni < 8; ni++) {
            int col = kstart + ni * 8 + tg * 2;
            if (need_mask) {
                sc[ni][0] = (col     > row0) ? -1e30f : sc[ni][0] * 0.125f;
                sc[ni][1] = (col + 1 > row0) ? -1e30f : sc[ni][1] * 0.125f;
                sc[ni][2] = (col     > row1) ? -1e30f : sc[ni][2] * 0.125f;
                sc[ni][3] = (col + 1 > row1) ? -1e30f : sc[ni][3] * 0.125f;
            } else {
                sc[ni][0] *= 0.125f; sc[ni][1] *= 0.125f;
                sc[ni][2] *= 0.125f; sc[ni][3] *= 0.125f;
            }
        }

        // ---- online softmax ----
        float mx0 = m0, mx1 = m1;
        #pragma unroll
        for (int ni = 0; ni < 8; ni++) {
            mx0 = fmaxf(mx0, fmaxf(sc[ni][0], sc[ni][1]));
            mx1 = fmaxf(mx1, fmaxf(sc[ni][2], sc[ni][3]));
        }
        mx0 = fmaxf(mx0, __shfl_xor_sync(0xffffffffu, mx0, 1));
        mx0 = fmaxf(mx0, __shfl_xor_sync(0xffffffffu, mx0, 2));
        mx1 = fmaxf(mx1, __shfl_xor_sync(0xffffffffu, mx1, 1));
        mx1 = fmaxf(mx1, __shfl_xor_sync(0xffffffffu, mx1, 2));
        float cs0 = __expf(m0 - mx0), cs1 = __expf(m1 - mx1);
        m0 = mx0; m1 = mx1;
        li0 *= cs0; li1 *= cs1;
        #pragma unroll
        for (int ni = 0; ni < 8; ni++) {
            o[ni][0] *= cs0; o[ni][1] *= cs0;
            o[ni][2] *= cs1; o[ni][3] *= cs1;
        }
        float ps0 = 0.f, ps1 = 0.f;
        #pragma unroll
        for (int ni = 0; ni < 8; ni++) {
            sc[ni][0] = __expf(sc[ni][0] - m0);
            sc[ni][1] = __expf(sc[ni][1] - m0);
            sc[ni][2] = __expf(sc[ni][2] - m1);
            sc[ni][3] = __expf(sc[ni][3] - m1);
            ps0 += sc[ni][0] + sc[ni][1];
            ps1 += sc[ni][2] + sc[ni][3];
        }
        ps0 += __shfl_xor_sync(0xffffffffu, ps0, 1);
        ps0 += __shfl_xor_sync(0xffffffffu, ps0, 2);
        ps1 += __shfl_xor_sync(0xffffffffu, ps1, 1);
        ps1 += __shfl_xor_sync(0xffffffffu, ps1, 2);
        li0 += ps0; li1 += ps1;

        // ---- O += P @ V (Ph*Vh + Pl*Vh + Ph*Vl) ----
        #pragma unroll
        for (int j = 0; j < 4; j++) {          // key blocks of 16
            uint32_t pah[4], pal[4];
            {
                bf h0,h1,l0,l1;
                split2(sc[2*j][0], h0, l0); split2(sc[2*j][1], h1, l1);
                pah[0] = pack_bf2(h0,h1); pal[0] = pack_bf2(l0,l1);
                split2(sc[2*j][2], h0, l0); split2(sc[2*j][3], h1, l1);
                pah[1] = pack_bf2(h0,h1); pal[1] = pack_bf2(l0,l1);
                split2(sc[2*j+1][0], h0, l0); split2(sc[2*j+1][1], h1, l1);
                pah[2] = pack_bf2(h0,h1); pal[2] = pack_bf2(l0,l1);
                split2(sc[2*j+1][2], h0, l0); split2(sc[2*j+1][3], h1, l1);
                pah[3] = pack_bf2(h0,h1); pal[3] = pack_bf2(l0,l1);
            }
            #pragma unroll
            for (int nb = 0; nb < 4; nb++) {   // d blocks of 16
                uint32_t off = (uint32_t)(((j * 16 + rA) * 72 + nb * 16 + cA) * 2);
                uint32_t vh[4], vl[4];
                ldsm4t(vh, uV_h + off);
                ldsm4t(vl, uV_l + off);
                int n0 = nb * 2;
                mma16816(o[n0],   pah, vh[0], vh[1]);
                mma16816(o[n0],   pal, vh[0], vh[1]);
                mma16816(o[n0],   pah, vl[0], vl[1]);
                mma16816(o[n0+1], pah, vh[2], vh[3]);
                mma16816(o[n0+1], pal, vh[2], vh[3]);
                mma16816(o[n0+1], pah, vl[2], vl[3]);
            }
        }

        __syncthreads();
        if (it + 2 < ntiles) KV_ISSUE((it + 2) * 64, s);
        CP_COMMIT();
    }
#undef KV_ISSUE

    // ---- epilogue: normalize + split write ----
    float inv0 = 1.f / li0, inv1 = 1.f / li1;
    size_t or0 = (size_t)(b * LL + row0) * EE + h * DHH;
    size_t or1 = (size_t)(b * LL + row1) * EE + h * DHH;
    #pragma unroll
    for (int ni = 0; ni < 8; ni++) {
        int c = ni * 8 + tg * 2;
        bf h0,h1,l0,l1;
        split2(o[ni][0] * inv0, h0, l0); split2(o[ni][1] * inv0, h1, l1);
        *(uint32_t*)&outh[or0 + c] = pack_bf2(h0,h1);
        *(uint32_t*)&outl[or0 + c] = pack_bf2(l0,l1);
        split2(o[ni][2] * inv1, h0, l0); split2(o[ni][3] * inv1, h1, l1);
        *(uint32_t*)&outh[or1 + c] = pack_bf2(h0,h1);
        *(uint32_t*)&outl[or1 + c] = pack_bf2(l0,l1);
    }
}

// ---------------------------------------------------------------------------
// Launch
// ---------------------------------------------------------------------------
extern "C" void kernel_launch(void* const* d_in, const int* in_sizes, int n_in,
                              void* d_out, int out_size) {
    const float* x    = (const float*)d_in[0];
    const float* Wa   = (const float*)d_in[1];
    const float* Wout = (const float*)d_in[2];
    const float* bout = (const float*)d_in[3];
    const float* W1   = (const float*)d_in[4];
    const float* b1   = (const float*)d_in[5];
    const float* W2   = (const float*)d_in[6];
    const float* b2   = (const float*)d_in[7];
    const float* g1   = (const float*)d_in[8];
    const float* be1  = (const float*)d_in[9];
    const float* g2   = (const float*)d_in[10];
    const float* be2  = (const float*)d_in[11];
    float* out = (float*)d_out;

    unsigned char* arena;
    cudaGetSymbolAddress((void**)&arena, g_arena);

    bf* qkvh = (bf*)(arena + OFF_QKVH);
    bf* qkvl = (bf*)(arena + OFF_QKVL);
    float* res1 = (float*)(arena + OFF_RES1);
    bf* ath = (bf*)(arena + OFF_ATH);
    bf* atl = (bf*)(arena + OFF_ATL);
    bf* o1h = (bf*)(arena + OFF_O1H);
    bf* o1l = (bf*)(arena + OFF_O1L);
    bf* o2h = (bf*)(arena + OFF_O2H);
    bf* o2l = (bf*)(arena + OFF_O2L);
    bf* hh  = (bf*)(arena + OFF_HH);
    bf* hl  = (bf*)(arena + OFF_HL);
    bf* wah = (bf*)(arena + OFF_WAH);
    bf* wal = (bf*)(arena + OFF_WAL);
    bf* woh = (bf*)(arena + OFF_WOH);
    bf* wol = (bf*)(arena + OFF_WOL);
    bf* w1h = (bf*)(arena + OFF_W1H);
    bf* w1l = (bf*)(arena + OFF_W1L);
    bf* w2h = (bf*)(arena + OFF_W2H);
    bf* w2l = (bf*)(arena + OFF_W2L);

    // raise dynamic smem limits (idempotent host-side attribute sets)
    static bool attr_done = false;
    if (!attr_done) {
        cudaFuncSetAttribute(gemm_bf3<false,false,true>,
            cudaFuncAttributeMaxDynamicSharedMemorySize, GEMM_SMEM);
        cudaFuncSetAttribute(gemm_bf3<true,true,false>,
            cudaFuncAttributeMaxDynamicSharedMemorySize, GEMM_SMEM);
        cudaFuncSetAttribute(gemm_bf3<true,false,true>,
            cudaFuncAttributeMaxDynamicSharedMemorySize, GEMM_SMEM);
        cudaFuncSetAttribute(attn_tc,
            cudaFuncAttributeMaxDynamicSharedMemorySize, ATTN_SMEM);
        attr_done = true;
    }

    // weight splits
    split_kernel<<<(EE*3072/4 + 255)/256, 256>>>(Wa,   wah, wal, EE*3072/4);
    split_kernel<<<(EE*EE/4   + 255)/256, 256>>>(Wout, woh, wol, EE*EE/4);
    split_kernel<<<(EE*HIDD/4 + 255)/256, 256>>>(W1,   w1h, w1l, EE*HIDD/4);
    split_kernel<<<(HIDD*EE/4 + 255)/256, 256>>>(W2,   w2h, w2l, HIDD*EE/4);

    // 1) o1 = LN(x)
    ln_split_kernel<<<MROWS, 256>>>(x, g1, be1, o1h, o1l);

    // 2) qkv = o1 @ Wa  (split bf16 output)
    gemm_bf3<false,false,true><<<dim3(3072/128, MROWS/128), 256, GEMM_SMEM>>>(
        o1h, o1l, wah, wal, nullptr, nullptr, nullptr, qkvh, qkvl,
        MROWS, 3072, EE);

    // 3) attention (tensor cores)
    attn_tc<<<dim3(LL/128, BB*NHH), 256, ATTN_SMEM>>>(qkvh, qkvl, ath, atl);

    // 4) res1 = attn @ Wout + bout + x
    gemm_bf3<true,true,false><<<dim3(EE/128, MROWS/128), 256, GEMM_SMEM>>>(
        ath, atl, woh, wol, bout, x, res1, nullptr, nullptr,
        MROWS, EE, EE);

    // 5) o2 = LN(res1)
    ln_split_kernel<<<MROWS, 256>>>(res1, g2, be2, o2h, o2l);

    // 6) h = o2 @ W1 + b1 (split output)
    gemm_bf3<true,false,true><<<dim3(HIDD/128, MROWS/128), 256, GEMM_SMEM>>>(
        o2h, o2l, w1h, w1l, b1, nullptr, nullptr, hh, hl,
        MROWS, HIDD, EE);

    // 7) out = h @ W2 + b2 + x
    gemm_bf3<true,true,false><<<dim3(EE/128, MROWS/128), 256, GEMM_SMEM>>>(
        hh, hl, w2h, w2l, b2, x, out, nullptr, nullptr,
        MROWS, EE, HIDD);
}

// round 5
// speedup vs baseline: 2.8899x; 1.0014x over previous
#include <cuda_runtime.h>
#include <cuda_bf16.h>
#include <cstdint>
#include <cstddef>

// Problem constants
#define BB   2
#define LL   2048
#define EE   1024
#define NHH  16
#define DHH  64
#define HIDD 4096
#define MROWS (BB*LL)          // 4096

typedef __nv_bfloat16 bf;

// ---------------------------------------------------------------------------
// Scratch arena
// ---------------------------------------------------------------------------
constexpr size_t SZ_QKV1 = (size_t)MROWS * 3072 * 2;   // bf16 (h or l)
constexpr size_t SZ_RES1 = (size_t)MROWS * EE * 4;     // fp32
constexpr size_t SZ_ACT  = (size_t)MROWS * EE * 2;     // bf16
constexpr size_t SZ_H    = (size_t)MROWS * HIDD * 2;   // bf16
constexpr size_t SZ_WA   = (size_t)EE * 3072 * 2;
constexpr size_t SZ_WO   = (size_t)EE * EE * 2;
constexpr size_t SZ_W1   = (size_t)EE * HIDD * 2;
constexpr size_t SZ_W2   = (size_t)HIDD * EE * 2;

constexpr size_t OFF_QKVH = 0;
constexpr size_t OFF_QKVL = OFF_QKVH + SZ_QKV1;
constexpr size_t OFF_RES1 = OFF_QKVL + SZ_QKV1;
constexpr size_t OFF_ATH  = OFF_RES1 + SZ_RES1;
constexpr size_t OFF_ATL  = OFF_ATH  + SZ_ACT;
constexpr size_t OFF_O1H  = OFF_ATL  + SZ_ACT;
constexpr size_t OFF_O1L  = OFF_O1H  + SZ_ACT;
constexpr size_t OFF_O2H  = OFF_O1L  + SZ_ACT;
constexpr size_t OFF_O2L  = OFF_O2H  + SZ_ACT;
constexpr size_t OFF_HH   = OFF_O2L  + SZ_ACT;
constexpr size_t OFF_HL   = OFF_HH   + SZ_H;
constexpr size_t OFF_WAH  = OFF_HL   + SZ_H;
constexpr size_t OFF_WAL  = OFF_WAH  + SZ_WA;
constexpr size_t OFF_WOH  = OFF_WAL  + SZ_WA;
constexpr size_t OFF_WOL  = OFF_WOH  + SZ_WO;
constexpr size_t OFF_W1H  = OFF_WOL  + SZ_WO;
constexpr size_t OFF_W1L  = OFF_W1H  + SZ_W1;
constexpr size_t OFF_W2H  = OFF_W1L  + SZ_W1;
constexpr size_t OFF_W2L  = OFF_W2H  + SZ_W2;
constexpr size_t ARENA_SZ = OFF_W2L  + SZ_W2;

__device__ __align__(256) unsigned char g_arena[ARENA_SZ];

// ---------------------------------------------------------------------------
// Helpers
// ---------------------------------------------------------------------------
__device__ __forceinline__ void split2(float v, bf& h, bf& l) {
    h = __float2bfloat16(v);
    l = __float2bfloat16(v - __bfloat162float(h));
}
__device__ __forceinline__ uint32_t pack_bf2(bf a, bf b) {
    __nv_bfloat162 t; t.x = a; t.y = b;
    return *(uint32_t*)&t;
}
__device__ __forceinline__ void ldsm4(uint32_t* r, uint32_t a) {
    asm volatile("ldmatrix.sync.aligned.m8n8.x4.shared.b16 {%0,%1,%2,%3}, [%4];\n"
        : "=r"(r[0]), "=r"(r[1]), "=r"(r[2]), "=r"(r[3]) : "r"(a));
}
__device__ __forceinline__ void ldsm4t(uint32_t* r, uint32_t a) {
    asm volatile("ldmatrix.sync.aligned.m8n8.x4.trans.shared.b16 {%0,%1,%2,%3}, [%4];\n"
        : "=r"(r[0]), "=r"(r[1]), "=r"(r[2]), "=r"(r[3]) : "r"(a));
}
__device__ __forceinline__ void mma16816(float* c, const uint32_t* a, uint32_t b0, uint32_t b1) {
    asm volatile(
        "mma.sync.aligned.m16n8k16.row.col.f32.bf16.bf16.f32 "
        "{%0,%1,%2,%3}, {%4,%5,%6,%7}, {%8,%9}, {%0,%1,%2,%3};\n"
        : "+f"(c[0]), "+f"(c[1]), "+f"(c[2]), "+f"(c[3])
        : "r"(a[0]), "r"(a[1]), "r"(a[2]), "r"(a[3]), "r"(b0), "r"(b1));
}
__device__ __forceinline__ void cp16(uint32_t dst, const void* src) {
    asm volatile("cp.async.cg.shared.global [%0], [%1], 16;\n" :: "r"(dst), "l"(src));
}
#define CP_COMMIT() asm volatile("cp.async.commit_group;\n" ::: "memory")
#define CP_WAIT1()  asm volatile("cp.async.wait_group 1;\n" ::: "memory")

// ---------------------------------------------------------------------------
// fp32 -> (bf16 hi, bf16 lo) splitter (weights)
// ---------------------------------------------------------------------------
__global__ __launch_bounds__(256)
void split_kernel(const float* __restrict__ in, bf* __restrict__ oh,
                  bf* __restrict__ ol, int n4) {
    int i = blockIdx.x * 256 + threadIdx.x;
    if (i >= n4) return;
    float4 v = ((const float4*)in)[i];
    bf h0,h1,h2,h3,l0,l1,l2,l3;
    split2(v.x,h0,l0); split2(v.y,h1,l1); split2(v.z,h2,l2); split2(v.w,h3,l3);
    *(uint32_t*)&oh[(size_t)i*4]     = pack_bf2(h0,h1);
    *(uint32_t*)&oh[(size_t)i*4 + 2] = pack_bf2(h2,h3);
    *(uint32_t*)&ol[(size_t)i*4]     = pack_bf2(l0,l1);
    *(uint32_t*)&ol[(size_t)i*4 + 2] = pack_bf2(l2,l3);
}

// ---------------------------------------------------------------------------
// LayerNorm writing split bf16 output
// ---------------------------------------------------------------------------
__global__ __launch_bounds__(256)
void ln_split_kernel(const float* __restrict__ in, const float* __restrict__ g,
                     const float* __restrict__ be, bf* __restrict__ oh,
                     bf* __restrict__ ol) {
    int row = blockIdx.x;
    int tid = threadIdx.x;
    const float4* ip = (const float4*)(in + (size_t)row * EE);
    float4 v = ip[tid];
    float s  = v.x + v.y + v.z + v.w;
    float ss = v.x*v.x + v.y*v.y + v.z*v.z + v.w*v.w;
    #pragma unroll
    for (int o = 16; o; o >>= 1) {
        s  += __shfl_xor_sync(0xffffffffu, s,  o);
        ss += __shfl_xor_sync(0xffffffffu, ss, o);
    }
    __shared__ float sm[8], sm2[8];
    int w = tid >> 5;
    if ((tid & 31) == 0) { sm[w] = s; sm2[w] = ss; }
    __syncthreads();
    float ts = 0.f, tss = 0.f;
    #pragma unroll
    for (int i = 0; i < 8; i++) { ts += sm[i]; tss += sm2[i]; }
    float mu  = ts  * (1.f / EE);
    float var = tss * (1.f / EE) - mu * mu;
    float rs  = rsqrtf(var + 1e-5f);
    float4 gv = ((const float4*)g)[tid];
    float4 bv = ((const float4*)be)[tid];
    float4 o;
    o.x = (v.x - mu) * rs * gv.x + bv.x;
    o.y = (v.y - mu) * rs * gv.y + bv.y;
    o.z = (v.z - mu) * rs * gv.z + bv.z;
    o.w = (v.w - mu) * rs * gv.w + bv.w;
    bf h0,h1,h2,h3,l0,l1,l2,l3;
    split2(o.x,h0,l0); split2(o.y,h1,l1); split2(o.z,h2,l2); split2(o.w,h3,l3);
    size_t base = (size_t)row * EE + tid * 4;
    *(uint32_t*)&oh[base]     = pack_bf2(h0,h1);
    *(uint32_t*)&oh[base + 2] = pack_bf2(h2,h3);
    *(uint32_t*)&ol[base]     = pack_bf2(l0,l1);
    *(uint32_t*)&ol[base + 2] = pack_bf2(l2,l3);
}

// ---------------------------------------------------------------------------
// bf16x3 tensor-core GEMM, 2-stage cp.async pipeline, 2 CTAs/SM.
// Block 128x128, BK=32, 8 warps (2Mx4N), warp tile 64x32, mma.m16n8k16.
// ---------------------------------------------------------------------------
#define SA 40
#define SB 136
#define G_AH 0
#define G_AL 5120
#define G_BH 10240
#define G_BL 14592
#define G_STG 18944
#define GEMM_SMEM (2 * G_STG * 2)  // 75776 bytes

template<bool BIAS, bool RES, bool SPLIT>
__global__ __launch_bounds__(256, 2)
void gemm_bf3(const bf* __restrict__ Ah, const bf* __restrict__ Al,
              const bf* __restrict__ Bh, const bf* __restrict__ Bl,
              const float* __restrict__ bias, const float* __restrict__ res,
              float* __restrict__ C, bf* __restrict__ Ch, bf* __restrict__ Cl,
              int M, int N, int K) {
    extern __shared__ __align__(16) bf smem[];
    const uint32_t base = (uint32_t)__cvta_generic_to_shared(smem);

    const int tid = threadIdx.x, lane = tid & 31, warp = tid >> 5;
    const int wm = (warp & 1) * 64, wn = (warp >> 1) * 32;
    const int rowBase = blockIdx.y * 128, colBase = blockIdx.x * 128;

    const int am = tid >> 2, ak = (tid & 3) * 8;
    const int bk = tid >> 4, bn = (tid & 15) * 8;

    const bf* gAh = Ah + (size_t)(rowBase + am) * K + ak;
    const bf* gAl = Al + (size_t)(rowBase + am) * K + ak;
    const bf* gBh = Bh + (size_t)bk * N + colBase + bn;
    const bf* gBl = Bl + (size_t)bk * N + colBase + bn;
    const size_t aStep = 64 * (size_t)K;
    const size_t bStep = 16 * (size_t)N;

    const uint32_t sA0 = (uint32_t)((am * SA + ak) * 2);
    const uint32_t sA1 = (uint32_t)(((am + 64) * SA + ak) * 2);
    const uint32_t sB0 = (uint32_t)((bk * SB + bn) * 2);
    const uint32_t sB1 = (uint32_t)(((bk + 16) * SB + bn) * 2);

#define G_ISSUE(kt, s) do {                                                   \
        uint32_t sb = base + (uint32_t)(s) * (G_STG * 2);                     \
        cp16(sb + G_AH*2 + sA0, gAh + (kt));                                  \
        cp16(sb + G_AH*2 + sA1, gAh + aStep + (kt));                          \
        cp16(sb + G_AL*2 + sA0, gAl + (kt));                                  \
        cp16(sb + G_AL*2 + sA1, gAl + aStep + (kt));                          \
        cp16(sb + G_BH*2 + sB0, gBh + (size_t)(kt) * N);                      \
        cp16(sb + G_BH*2 + sB1, gBh + (size_t)(kt) * N + bStep);              \
        cp16(sb + G_BL*2 + sB0, gBl + (size_t)(kt) * N);                      \
        cp16(sb + G_BL*2 + sB1, gBl + (size_t)(kt) * N + bStep);              \
    } while (0)

    const int rA = lane & 15, cA = (lane >> 4) * 8;
    const int rB = lane & 15, cB = (lane >> 4) * 8;

    float acc[4][4][4];
    #pragma unroll
    for (int i = 0; i < 4; i++)
        #pragma unroll
        for (int j = 0; j < 4; j++)
            #pragma unroll
            for (int k = 0; k < 4; k++) acc[i][j][k] = 0.f;

    G_ISSUE(0, 0); CP_COMMIT();
    G_ISSUE(32, 1); CP_COMMIT();

    const int nk = K >> 5;
    for (int i = 0; i < nk; i++) {
        CP_WAIT1();
        __syncthreads();
        const int s = i & 1;
        const uint32_t uAh = base + s * (G_STG*2) + G_AH*2;
        const uint32_t uAl = base + s * (G_STG*2) + G_AL*2;
        const uint32_t uBh = base + s * (G_STG*2) + G_BH*2;
        const uint32_t uBl = base + s * (G_STG*2) + G_BL*2;

        #pragma unroll
        for (int kk = 0; kk < 32; kk += 16) {
            uint32_t bhf[2][4], blf[2][4];
            #pragma unroll
            for (int j = 0; j < 2; j++) {
                uint32_t offB = (uint32_t)(((kk + rB) * SB + wn + j * 16 + cB) * 2);
                ldsm4t(bhf[j], uBh + offB);
                ldsm4t(blf[j], uBl + offB);
            }
            #pragma unroll
            for (int mi = 0; mi < 4; mi++) {
                uint32_t offA = (uint32_t)(((wm + mi * 16 + rA) * SA + kk + cA) * 2);
                uint32_t ahf[4], alf[4];
                ldsm4(ahf, uAh + offA);
                ldsm4(alf, uAl + offA);
                #pragma unroll
                for (int ni = 0; ni < 4; ni++) {
                    uint32_t b0 = bhf[ni >> 1][(ni & 1) * 2];
                    uint32_t b1 = bhf[ni >> 1][(ni & 1) * 2 + 1];
                    uint32_t c0 = blf[ni >> 1][(ni & 1) * 2];
                    uint32_t c1 = blf[ni >> 1][(ni & 1) * 2 + 1];
                    mma16816(acc[mi][ni], ahf, b0, b1);
                    mma16816(acc[mi][ni], alf, b0, b1);
                    mma16816(acc[mi][ni], ahf, c0, c1);
                }
            }
        }
        __syncthreads();
        if (i + 2 < nk) G_ISSUE((i + 2) * 32, s);
        CP_COMMIT();
    }
#undef G_ISSUE

    // epilogue
    const int g = lane >> 2, tg = lane & 3;
    #pragma unroll
    for (int mi = 0; mi < 4; mi++) {
        #pragma unroll
        for (int ni = 0; ni < 4; ni++) {
            int r0 = rowBase + wm + mi * 16 + g;
            int c0 = colBase + wn + ni * 8 + tg * 2;
            float* a = acc[mi][ni];
            float2 v0 = make_float2(a[0], a[1]);
            float2 v1 = make_float2(a[2], a[3]);
            if (BIAS) {
                float bx = bias[c0], by = bias[c0 + 1];
                v0.x += bx; v0.y += by; v1.x += bx; v1.y += by;
            }
            if (RES) {
                float2 q0 = *(const float2*)&res[(size_t)r0 * N + c0];
                float2 q1 = *(const float2*)&res[(size_t)(r0 + 8) * N + c0];
                v0.x += q0.x; v0.y += q0.y; v1.x += q1.x; v1.y += q1.y;
            }
            if (SPLIT) {
                bf h0,h1,l0,l1;
                split2(v0.x, h0, l0); split2(v0.y, h1, l1);
                *(uint32_t*)&Ch[(size_t)r0 * N + c0] = pack_bf2(h0,h1);
                *(uint32_t*)&Cl[(size_t)r0 * N + c0] = pack_bf2(l0,l1);
                split2(v1.x, h0, l0); split2(v1.y, h1, l1);
                *(uint32_t*)&Ch[(size_t)(r0 + 8) * N + c0] = pack_bf2(h0,h1);
                *(uint32_t*)&Cl[(size_t)(r0 + 8) * N + c0] = pack_bf2(l0,l1);
            } else {
                *(float2*)&C[(size_t)r0 * N + c0] = v0;
                *(float2*)&C[(size_t)(r0 + 8) * N + c0] = v1;
            }
        }
    }
}

// ---------------------------------------------------------------------------
// Tensor-core causal flash attention (mma.sync), unchanged.
// ---------------------------------------------------------------------------
#define AQ_H 0
#define AQ_L 9216
#define AKV_BASE 18432
#define AKV_STG  18432
#define A_KH 0
#define A_KL 4608
#define A_VH 9216
#define A_VL 13824
#define ATTN_SMEM ((18432 + 2*18432) * 2)

__global__ __launch_bounds__(256)
void attn_tc(const bf* __restrict__ qkvh, const bf* __restrict__ qkvl,
             bf* __restrict__ outh, bf* __restrict__ outl) {
    extern __shared__ __align__(16) bf smem[];
    const uint32_t base = (uint32_t)__cvta_generic_to_shared(smem);

    const int tid = threadIdx.x, lane = tid & 31, warp = tid >> 5;
    const int qtile = blockIdx.x, bh = blockIdx.y;
    const int b = bh >> 4, h = bh & 15;
    const int qbase = qtile * 128;
    const int wrow = warp * 16;
    const int g = lane >> 2, tg = lane & 3;
    const int rA = lane & 15, cA = (lane >> 4) * 8;

    {
        #pragma unroll
        for (int t = 0; t < 4; t++) {
            int id = tid + t * 256;
            int r = id >> 3, cc = (id & 7) * 8;
            size_t src = (size_t)(b * LL + qbase + r) * 3072 + h * 192 + cc;
            uint32_t dst = (uint32_t)((r * 72 + cc) * 2);
            cp16(base + AQ_H*2 + dst, qkvh + src);
            cp16(base + AQ_L*2 + dst, qkvl + src);
        }
    }
#define KV_ISSUE(kstart, s) do {                                              \
        uint32_t sb = base + (AKV_BASE + (s) * AKV_STG) * 2;                  \
        _Pragma("unroll")                                                     \
        for (int t = 0; t < 2; t++) {                                         \
            int id = tid + t * 256;                                           \
            int r = id >> 3, cc = (id & 7) * 8;                               \
            size_t rowb = (size_t)(b * LL + (kstart) + r) * 3072 + h * 192;   \
            uint32_t dst = (uint32_t)((r * 72 + cc) * 2);                     \
            cp16(sb + A_KH*2 + dst, qkvh + rowb + 64 + cc);                   \
            cp16(sb + A_KL*2 + dst, qkvl + rowb + 64 + cc);                   \
            cp16(sb + A_VH*2 + dst, qkvh + rowb + 128 + cc);                  \
            cp16(sb + A_VL*2 + dst, qkvl + rowb + 128 + cc);                  \
        }                                                                     \
    } while (0)

    const int ntiles = qtile * 2 + 2;
    KV_ISSUE(0, 0); CP_COMMIT();
    if (ntiles > 1) KV_ISSUE(64, 1);
    CP_COMMIT();

    CP_WAIT1();
    __syncthreads();

    uint32_t qh[4][4], ql[4][4];
    #pragma unroll
    for (int j = 0; j < 4; j++) {
        uint32_t off = (uint32_t)(((wrow + rA) * 72 + j * 16 + cA) * 2);
        ldsm4(qh[j], base + AQ_H*2 + off);
        ldsm4(ql[j], base + AQ_L*2 + off);
    }

    float o[8][4];
    #pragma unroll
    for (int i = 0; i < 8; i++)
        #pragma unroll
        for (int k = 0; k < 4; k++) o[i][k] = 0.f;
    float m0 = -1e30f, m1 = -1e30f, li0 = 0.f, li1 = 0.f;

    const int row0 = qbase + wrow + g;
    const int row1 = row0 + 8;

    for (int it = 0; it < ntiles; it++) {
        if (it > 0) { CP_WAIT1(); __syncthreads(); }
        const int s = it & 1;
        const int kstart = it * 64;
        const uint32_t uK_h = base + (AKV_BASE + s * AKV_STG + A_KH) * 2;
        const uint32_t uK_l = base + (AKV_BASE + s * AKV_STG + A_KL) * 2;
        const uint32_t uV_h = base + (AKV_BASE + s * AKV_STG + A_VH) * 2;
        const uint32_t uV_l = base + (AKV_BASE + s * AKV_STG + A_VL) * 2;

        float sc[8][4];
        #pragma unroll
        for (int i = 0; i < 8; i++)
            #pragma unroll
            for (int k = 0; k < 4; k++) sc[i][k] = 0.f;

        #pragma unroll
        for (int j = 0; j < 4; j++) {
            #pragma unroll
            for (int kb = 0; kb < 4; kb++) {
                uint32_t off = (uint32_t)(((kb * 16 + rA) * 72 + j * 16 + cA) * 2);
                uint32_t kh[4], kl[4];
                ldsm4(kh, uK_h + off);
                ldsm4(kl, uK_l + off);
                int n0 = kb * 2;
                mma16816(sc[n0],   qh[j], kh[0], kh[2]);
                mma16816(sc[n0],   ql[j], kh[0], kh[2]);
                mma16816(sc[n0],   qh[j], kl[0], kl[2]);
                mma16816(sc[n0+1], qh[j], kh[1], kh[3]);
                mma16816(sc[n0+1], ql[j], kh[1], kh[3]);
                mma16816(sc[n0+1], qh[j], kl[1], kl[3]);
            }
        }

        const bool need_mask = (kstart + 63) > (qbase + wrow);
        #pragma unroll
        for (int ni = 0; ni < 8; ni++) {
            int col = kstart + ni * 8 + tg * 2;
            if (need_mask) {
                sc[ni][0] = (col     > row0) ? -1e30f : sc[ni][0] * 0.125f;
                sc[ni][1] = (col + 1 > row0) ? -1e30f : sc[ni][1] * 0.125f;
                sc[ni][2] = (col     > row1) ? -1e30f : sc[ni][2] * 0.125f;
                sc[ni][3] = (col + 1 > row1) ? -1e30f : sc[ni][3] * 0.125f;
            } else {
                sc[ni][0] *= 0.125f; sc[ni][1] *= 0.125f;
                sc[ni][2] *= 0.125f; sc[ni][3] *= 0.125f;
            }
        }

        float mx0 = m0, mx1 = m1;
        #pragma unroll
        for (int ni = 0; ni < 8; ni++) {
            mx0 = fmaxf(mx0, fmaxf(sc[ni][0], sc[ni][1]));
            mx1 = fmaxf(mx1, fmaxf(sc[ni][2], sc[ni][3]));
        }
        mx0 = fmaxf(mx0, __shfl_xor_sync(0xffffffffu, mx0, 1));
        mx0 = fmaxf(mx0, __shfl_xor_sync(0xffffffffu, mx0, 2));
        mx1 = fmaxf(mx1, __shfl_xor_sync(0xffffffffu, mx1, 1));
        mx1 = fmaxf(mx1, __shfl_xor_sync(0xffffffffu, mx1, 2));
        float cs0 = __expf(m0 - mx0), cs1 = __expf(m1 - mx1);
        m0 = mx0; m1 = mx1;
        li0 *= cs0; li1 *= cs1;
        #pragma unroll
        for (int ni = 0; ni < 8; ni++) {
            o[ni][0] *= cs0; o[ni][1] *= cs0;
            o[ni][2] *= cs1; o[ni][3] *= cs1;
        }
        float ps0 = 0.f, ps1 = 0.f;
        #pragma unroll
        for (int ni = 0; ni < 8; ni++) {
            sc[ni][0] = __expf(sc[ni][0] - m0);
            sc[ni][1] = __expf(sc[ni][1] - m0);
            sc[ni][2] = __expf(sc[ni][2] - m1);
            sc[ni][3] = __expf(sc[ni][3] - m1);
            ps0 += sc[ni][0] + sc[ni][1];
            ps1 += sc[ni][2] + sc[ni][3];
        }
        ps0 += __shfl_xor_sync(0xffffffffu, ps0, 1);
        ps0 += __shfl_xor_sync(0xffffffffu, ps0, 2);
        ps1 += __shfl_xor_sync(0xffffffffu, ps1, 1);
        ps1 += __shfl_xor_sync(0xffffffffu, ps1, 2);
        li0 += ps0; li1 += ps1;

        #pragma unroll
        for (int j = 0; j < 4; j++) {
            uint32_t pah[4], pal[4];
            {
                bf h0,h1,l0,l1;
                split2(sc[2*j][0], h0, l0); split2(sc[2*j][1], h1, l1);
                pah[0] = pack_bf2(h0,h1); pal[0] = pack_bf2(l0,l1);
                split2(sc[2*j][2], h0, l0); split2(sc[2*j][3], h1, l1);
                pah[1] = pack_bf2(h0,h1); pal[1] = pack_bf2(l0,l1);
                split2(sc[2*j+1][0], h0, l0); split2(sc[2*j+1][1], h1, l1);
                pah[2] = pack_bf2(h0,h1); pal[2] = pack_bf2(l0,l1);
                split2(sc[2*j+1][2], h0, l0); split2(sc[2*j+1][3], h1, l1);
                pah[3] = pack_bf2(h0,h1); pal[3] = pack_bf2(l0,l1);
            }
            #pragma unroll
            for (int nb = 0; nb < 4; nb++) {
                uint32_t off = (uint32_t)(((j * 16 + rA) * 72 + nb * 16 + cA) * 2);
                uint32_t vh[4], vl[4];
                ldsm4t(vh, uV_h + off);
                ldsm4t(vl, uV_l + off);
                int n0 = nb * 2;
                mma16816(o[n0],   pah, vh[0], vh[1]);
                mma16816(o[n0],   pal, vh[0], vh[1]);
                mma16816(o[n0],   pah, vl[0], vl[1]);
                mma16816(o[n0+1], pah, vh[2], vh[3]);
                mma16816(o[n0+1], pal, vh[2], vh[3]);
                mma16816(o[n0+1], pah, vl[2], vl[3]);
            }
        }

        __syncthreads();
        if (it + 2 < ntiles) KV_ISSUE((it + 2) * 64, s);
        CP_COMMIT();
    }
#undef KV_ISSUE

    float inv0 = 1.f / li0, inv1 = 1.f / li1;
    size_t or0 = (size_t)(b * LL + row0) * EE + h * DHH;
    size_t or1 = (size_t)(b * LL + row1) * EE + h * DHH;
    #pragma unroll
    for (int ni = 0; ni < 8; ni++) {
        int cc = ni * 8 + tg * 2;
        bf h0,h1,l0,l1;
        split2(o[ni][0] * inv0, h0, l0); split2(o[ni][1] * inv0, h1, l1);
        *(uint32_t*)&outh[or0 + cc] = pack_bf2(h0,h1);
        *(uint32_t*)&outl[or0 + cc] = pack_bf2(l0,l1);
        split2(o[ni][2] * inv1, h0, l0); split2(o[ni][3] * inv1, h1, l1);
        *(uint32_t*)&outh[or1 + cc] = pack_bf2(h0,h1);
        *(uint32_t*)&outl[or1 + cc] = pack_bf2(l0,l1);
    }
}

// ---------------------------------------------------------------------------
// Launch
// ---------------------------------------------------------------------------
extern "C" void kernel_launch(void* const* d_in, const int* in_sizes, int n_in,
                              void* d_out, int out_size) {
    const float* x    = (const float*)d_in[0];
    const float* Wa   = (const float*)d_in[1];
    const float* Wout = (const float*)d_in[2];
    const float* bout = (const float*)d_in[3];
    const float* W1   = (const float*)d_in[4];
    const float* b1   = (const float*)d_in[5];
    const float* W2   = (const float*)d_in[6];
    const float* b2   = (const float*)d_in[7];
    const float* g1   = (const float*)d_in[8];
    const float* be1  = (const float*)d_in[9];
    const float* g2   = (const float*)d_in[10];
    const float* be2  = (const float*)d_in[11];
    float* out = (float*)d_out;

    unsigned char* arena;
    cudaGetSymbolAddress((void**)&arena, g_arena);

    bf* qkvh = (bf*)(arena + OFF_QKVH);
    bf* qkvl = (bf*)(arena + OFF_QKVL);
    float* res1 = (float*)(arena + OFF_RES1);
    bf* ath = (bf*)(arena + OFF_ATH);
    bf* atl = (bf*)(arena + OFF_ATL);
    bf* o1h = (bf*)(arena + OFF_O1H);
    bf* o1l = (bf*)(arena + OFF_O1L);
    bf* o2h = (bf*)(arena + OFF_O2H);
    bf* o2l = (bf*)(arena + OFF_O2L);
    bf* hh  = (bf*)(arena + OFF_HH);
    bf* hl  = (bf*)(arena + OFF_HL);
    bf* wah = (bf*)(arena + OFF_WAH);
    bf* wal = (bf*)(arena + OFF_WAL);
    bf* woh = (bf*)(arena + OFF_WOH);
    bf* wol = (bf*)(arena + OFF_WOL);
    bf* w1h = (bf*)(arena + OFF_W1H);
    bf* w1l = (bf*)(arena + OFF_W1L);
    bf* w2h = (bf*)(arena + OFF_W2H);
    bf* w2l = (bf*)(arena + OFF_W2L);

    static bool attr_done = false;
    if (!attr_done) {
        cudaFuncSetAttribute(gemm_bf3<false,false,true>,
            cudaFuncAttributeMaxDynamicSharedMemorySize, GEMM_SMEM);
        cudaFuncSetAttribute(gemm_bf3<true,true,false>,
            cudaFuncAttributeMaxDynamicSharedMemorySize, GEMM_SMEM);
        cudaFuncSetAttribute(gemm_bf3<true,false,true>,
            cudaFuncAttributeMaxDynamicSharedMemorySize, GEMM_SMEM);
        cudaFuncSetAttribute(attn_tc,
            cudaFuncAttributeMaxDynamicSharedMemorySize, ATTN_SMEM);
        attr_done = true;
    }

    // weight splits
    split_kernel<<<(EE*3072/4 + 255)/256, 256>>>(Wa,   wah, wal, EE*3072/4);
    split_kernel<<<(EE*EE/4   + 255)/256, 256>>>(Wout, woh, wol, EE*EE/4);
    split_kernel<<<(EE*HIDD/4 + 255)/256, 256>>>(W1,   w1h, w1l, EE*HIDD/4);
    split_kernel<<<(HIDD*EE/4 + 255)/256, 256>>>(W2,   w2h, w2l, HIDD*EE/4);

    // 1) o1 = LN(x)
    ln_split_kernel<<<MROWS, 256>>>(x, g1, be1, o1h, o1l);

    // 2) qkv = o1 @ Wa (split output)
    gemm_bf3<false,false,true><<<dim3(3072/128, MROWS/128), 256, GEMM_SMEM>>>(
        o1h, o1l, wah, wal, nullptr, nullptr, nullptr, qkvh, qkvl,
        MROWS, 3072, EE);

    // 3) attention
    attn_tc<<<dim3(LL/128, BB*NHH), 256, ATTN_SMEM>>>(qkvh, qkvl, ath, atl);

    // 4) res1 = attn @ Wout + bout + x
    gemm_bf3<true,true,false><<<dim3(EE/128, MROWS/128), 256, GEMM_SMEM>>>(
        ath, atl, woh, wol, bout, x, res1, nullptr, nullptr,
        MROWS, EE, EE);

    // 5) o2 = LN(res1)
    ln_split_kernel<<<MROWS, 256>>>(res1, g2, be2, o2h, o2l);

    // 6) h = o2 @ W1 + b1 (split output)
    gemm_bf3<true,false,true><<<dim3(HIDD/128, MROWS/128), 256, GEMM_SMEM>>>(
        o2h, o2l, w1h, w1l, b1, nullptr, nullptr, hh, hl,
        MROWS, HIDD, EE);

    // 7) out = h @ W2 + b2 + x
    gemm_bf3<true,true,false><<<dim3(EE/128, MROWS/128), 256, GEMM_SMEM>>>(
        hh, hl, w2h, w2l, b2, x, out, nullptr, nullptr,
        MROWS, EE, HIDD);
}

// round 6
// speedup vs baseline: 3.9696x; 1.3736x over previous
#include <cuda_runtime.h>
#include <cuda_fp16.h>
#include <cstdint>
#include <cstddef>

// Problem constants
#define BB   2
#define LL   2048
#define EE   1024
#define NHH  16
#define DHH  64
#define HIDD 4096
#define MROWS (BB*LL)          // 4096

typedef __half hf;

// ---------------------------------------------------------------------------
// Scratch arena
// ---------------------------------------------------------------------------
constexpr size_t SZ_QKV1 = (size_t)MROWS * 3072 * 2;   // fp16 plane
constexpr size_t SZ_RES1 = (size_t)MROWS * EE * 4;     // fp32
constexpr size_t SZ_ACT  = (size_t)MROWS * EE * 2;     // fp16 plane
constexpr size_t SZ_H    = (size_t)MROWS * HIDD * 2;   // fp16 plane
constexpr size_t SZ_WA   = (size_t)EE * 3072 * 2;
constexpr size_t SZ_WO   = (size_t)EE * EE * 2;
constexpr size_t SZ_W1   = (size_t)EE * HIDD * 2;
constexpr size_t SZ_W2   = (size_t)HIDD * EE * 2;

constexpr size_t OFF_QKVH = 0;
constexpr size_t OFF_QKVL = OFF_QKVH + SZ_QKV1;
constexpr size_t OFF_RES1 = OFF_QKVL + SZ_QKV1;
constexpr size_t OFF_ATH  = OFF_RES1 + SZ_RES1;
constexpr size_t OFF_ATL  = OFF_ATH  + SZ_ACT;
constexpr size_t OFF_O1H  = OFF_ATL  + SZ_ACT;
constexpr size_t OFF_O1L  = OFF_O1H  + SZ_ACT;
constexpr size_t OFF_O2H  = OFF_O1L  + SZ_ACT;
constexpr size_t OFF_O2L  = OFF_O2H  + SZ_ACT;
constexpr size_t OFF_HH   = OFF_O2L  + SZ_ACT;
constexpr size_t OFF_HL   = OFF_HH   + SZ_H;
constexpr size_t OFF_WAH  = OFF_HL   + SZ_H;    // weights: single fp16 plane
constexpr size_t OFF_WOH  = OFF_WAH  + SZ_WA;
constexpr size_t OFF_W1H  = OFF_WOH  + SZ_WO;
constexpr size_t OFF_W2H  = OFF_W1H  + SZ_W1;
constexpr size_t ARENA_SZ = OFF_W2H  + SZ_W2;

__device__ __align__(256) unsigned char g_arena[ARENA_SZ];

// ---------------------------------------------------------------------------
// Helpers
// ---------------------------------------------------------------------------
__device__ __forceinline__ void split2h(float v, hf& h, hf& l) {
    h = __float2half(v);
    l = __float2half(v - __half2float(h));
}
__device__ __forceinline__ uint32_t pack_hf2(hf a, hf b) {
    __half2 t; t.x = a; t.y = b;
    return *(uint32_t*)&t;
}
__device__ __forceinline__ void ldsm4(uint32_t* r, uint32_t a) {
    asm volatile("ldmatrix.sync.aligned.m8n8.x4.shared.b16 {%0,%1,%2,%3}, [%4];\n"
        : "=r"(r[0]), "=r"(r[1]), "=r"(r[2]), "=r"(r[3]) : "r"(a));
}
__device__ __forceinline__ void ldsm4t(uint32_t* r, uint32_t a) {
    asm volatile("ldmatrix.sync.aligned.m8n8.x4.trans.shared.b16 {%0,%1,%2,%3}, [%4];\n"
        : "=r"(r[0]), "=r"(r[1]), "=r"(r[2]), "=r"(r[3]) : "r"(a));
}
__device__ __forceinline__ void mma16816(float* c, const uint32_t* a, uint32_t b0, uint32_t b1) {
    asm volatile(
        "mma.sync.aligned.m16n8k16.row.col.f32.f16.f16.f32 "
        "{%0,%1,%2,%3}, {%4,%5,%6,%7}, {%8,%9}, {%0,%1,%2,%3};\n"
        : "+f"(c[0]), "+f"(c[1]), "+f"(c[2]), "+f"(c[3])
        : "r"(a[0]), "r"(a[1]), "r"(a[2]), "r"(a[3]), "r"(b0), "r"(b1));
}
__device__ __forceinline__ void cp16(uint32_t dst, const void* src) {
    asm volatile("cp.async.cg.shared.global [%0], [%1], 16;\n" :: "r"(dst), "l"(src));
}
#define CP_COMMIT() asm volatile("cp.async.commit_group;\n" ::: "memory")
#define CP_WAIT1()  asm volatile("cp.async.wait_group 1;\n" ::: "memory")

// ---------------------------------------------------------------------------
// fp32 -> fp16 converter (weights, hi only)
// ---------------------------------------------------------------------------
__global__ __launch_bounds__(256)
void cvt_kernel(const float* __restrict__ in, hf* __restrict__ oh, int n4) {
    int i = blockIdx.x * 256 + threadIdx.x;
    if (i >= n4) return;
    float4 v = ((const float4*)in)[i];
    uint2 p;
    p.x = pack_hf2(__float2half(v.x), __float2half(v.y));
    p.y = pack_hf2(__float2half(v.z), __float2half(v.w));
    *(uint2*)&oh[(size_t)i*4] = p;
}

// ---------------------------------------------------------------------------
// LayerNorm writing split fp16 output
// ---------------------------------------------------------------------------
__global__ __launch_bounds__(256)
void ln_split_kernel(const float* __restrict__ in, const float* __restrict__ g,
                     const float* __restrict__ be, hf* __restrict__ oh,
                     hf* __restrict__ ol) {
    int row = blockIdx.x;
    int tid = threadIdx.x;
    const float4* ip = (const float4*)(in + (size_t)row * EE);
    float4 v = ip[tid];
    float s  = v.x + v.y + v.z + v.w;
    float ss = v.x*v.x + v.y*v.y + v.z*v.z + v.w*v.w;
    #pragma unroll
    for (int o = 16; o; o >>= 1) {
        s  += __shfl_xor_sync(0xffffffffu, s,  o);
        ss += __shfl_xor_sync(0xffffffffu, ss, o);
    }
    __shared__ float sm[8], sm2[8];
    int w = tid >> 5;
    if ((tid & 31) == 0) { sm[w] = s; sm2[w] = ss; }
    __syncthreads();
    float ts = 0.f, tss = 0.f;
    #pragma unroll
    for (int i = 0; i < 8; i++) { ts += sm[i]; tss += sm2[i]; }
    float mu  = ts  * (1.f / EE);
    float var = tss * (1.f / EE) - mu * mu;
    float rs  = rsqrtf(var + 1e-5f);
    float4 gv = ((const float4*)g)[tid];
    float4 bv = ((const float4*)be)[tid];
    float4 o;
    o.x = (v.x - mu) * rs * gv.x + bv.x;
    o.y = (v.y - mu) * rs * gv.y + bv.y;
    o.z = (v.z - mu) * rs * gv.z + bv.z;
    o.w = (v.w - mu) * rs * gv.w + bv.w;
    hf h0,h1,h2,h3,l0,l1,l2,l3;
    split2h(o.x,h0,l0); split2h(o.y,h1,l1); split2h(o.z,h2,l2); split2h(o.w,h3,l3);
    size_t base = (size_t)row * EE + tid * 4;
    *(uint32_t*)&oh[base]     = pack_hf2(h0,h1);
    *(uint32_t*)&oh[base + 2] = pack_hf2(h2,h3);
    *(uint32_t*)&ol[base]     = pack_hf2(l0,l1);
    *(uint32_t*)&ol[base + 2] = pack_hf2(l2,l3);
}

// ---------------------------------------------------------------------------
// fp16x2 tensor-core GEMM: C = (Ah+Al) @ Bh   (B single fp16, error = B quant)
// Block 128x128, BK=32, 8 warps (2Mx4N), warp tile 64x32, mma.m16n8k16.
// 2-stage cp.async, 2 CTAs/SM.
// ---------------------------------------------------------------------------
#define SA 40
#define SB 136
#define G_AH 0
#define G_AL 5120
#define G_BH 10240
#define G_STG 14592
#define GEMM_SMEM (2 * G_STG * 2)  // 58368 bytes

template<bool BIAS, bool RES, bool SPLIT>
__global__ __launch_bounds__(256, 2)
void gemm_fp16(const hf* __restrict__ Ah, const hf* __restrict__ Al,
               const hf* __restrict__ Bh,
               const float* __restrict__ bias, const float* __restrict__ res,
               float* __restrict__ C, hf* __restrict__ Ch, hf* __restrict__ Cl,
               int M, int N, int K) {
    extern __shared__ __align__(16) hf smem[];
    const uint32_t base = (uint32_t)__cvta_generic_to_shared(smem);

    const int tid = threadIdx.x, lane = tid & 31, warp = tid >> 5;
    const int wm = (warp & 1) * 64, wn = (warp >> 1) * 32;
    const int rowBase = blockIdx.y * 128, colBase = blockIdx.x * 128;

    const int am = tid >> 2, ak = (tid & 3) * 8;
    const int bk = tid >> 4, bn = (tid & 15) * 8;

    const hf* gAh = Ah + (size_t)(rowBase + am) * K + ak;
    const hf* gAl = Al + (size_t)(rowBase + am) * K + ak;
    const hf* gBh = Bh + (size_t)bk * N + colBase + bn;
    const size_t aStep = 64 * (size_t)K;
    const size_t bStep = 16 * (size_t)N;

    const uint32_t sA0 = (uint32_t)((am * SA + ak) * 2);
    const uint32_t sA1 = (uint32_t)(((am + 64) * SA + ak) * 2);
    const uint32_t sB0 = (uint32_t)((bk * SB + bn) * 2);
    const uint32_t sB1 = (uint32_t)(((bk + 16) * SB + bn) * 2);

#define G_ISSUE(kt, s) do {                                                   \
        uint32_t sb = base + (uint32_t)(s) * (G_STG * 2);                     \
        cp16(sb + G_AH*2 + sA0, gAh + (kt));                                  \
        cp16(sb + G_AH*2 + sA1, gAh + aStep + (kt));                          \
        cp16(sb + G_AL*2 + sA0, gAl + (kt));                                  \
        cp16(sb + G_AL*2 + sA1, gAl + aStep + (kt));                          \
        cp16(sb + G_BH*2 + sB0, gBh + (size_t)(kt) * N);                      \
        cp16(sb + G_BH*2 + sB1, gBh + (size_t)(kt) * N + bStep);              \
    } while (0)

    const int rA = lane & 15, cA = (lane >> 4) * 8;
    const int rB = lane & 15, cB = (lane >> 4) * 8;

    float acc[4][4][4];
    #pragma unroll
    for (int i = 0; i < 4; i++)
        #pragma unroll
        for (int j = 0; j < 4; j++)
            #pragma unroll
            for (int k = 0; k < 4; k++) acc[i][j][k] = 0.f;

    G_ISSUE(0, 0); CP_COMMIT();
    G_ISSUE(32, 1); CP_COMMIT();

    const int nk = K >> 5;
    for (int i = 0; i < nk; i++) {
        CP_WAIT1();
        __syncthreads();
        const int s = i & 1;
        const uint32_t uAh = base + s * (G_STG*2) + G_AH*2;
        const uint32_t uAl = base + s * (G_STG*2) + G_AL*2;
        const uint32_t uBh = base + s * (G_STG*2) + G_BH*2;

        #pragma unroll
        for (int kk = 0; kk < 32; kk += 16) {
            uint32_t bhf[2][4];
            #pragma unroll
            for (int j = 0; j < 2; j++) {
                uint32_t offB = (uint32_t)(((kk + rB) * SB + wn + j * 16 + cB) * 2);
                ldsm4t(bhf[j], uBh + offB);
            }
            #pragma unroll
            for (int mi = 0; mi < 4; mi++) {
                uint32_t offA = (uint32_t)(((wm + mi * 16 + rA) * SA + kk + cA) * 2);
                uint32_t ahf[4], alf[4];
                ldsm4(ahf, uAh + offA);
                ldsm4(alf, uAl + offA);
                #pragma unroll
                for (int ni = 0; ni < 4; ni++) {
                    uint32_t b0 = bhf[ni >> 1][(ni & 1) * 2];
                    uint32_t b1 = bhf[ni >> 1][(ni & 1) * 2 + 1];
                    mma16816(acc[mi][ni], ahf, b0, b1);
                    mma16816(acc[mi][ni], alf, b0, b1);
                }
            }
        }
        __syncthreads();
        if (i + 2 < nk) G_ISSUE((i + 2) * 32, s);
        CP_COMMIT();
    }
#undef G_ISSUE

    // epilogue
    const int g = lane >> 2, tg = lane & 3;
    #pragma unroll
    for (int mi = 0; mi < 4; mi++) {
        #pragma unroll
        for (int ni = 0; ni < 4; ni++) {
            int r0 = rowBase + wm + mi * 16 + g;
            int c0 = colBase + wn + ni * 8 + tg * 2;
            float* a = acc[mi][ni];
            float2 v0 = make_float2(a[0], a[1]);
            float2 v1 = make_float2(a[2], a[3]);
            if (BIAS) {
                float bx = bias[c0], by = bias[c0 + 1];
                v0.x += bx; v0.y += by; v1.x += bx; v1.y += by;
            }
            if (RES) {
                float2 q0 = *(const float2*)&res[(size_t)r0 * N + c0];
                float2 q1 = *(const float2*)&res[(size_t)(r0 + 8) * N + c0];
                v0.x += q0.x; v0.y += q0.y; v1.x += q1.x; v1.y += q1.y;
            }
            if (SPLIT) {
                hf h0,h1,l0,l1;
                split2h(v0.x, h0, l0); split2h(v0.y, h1, l1);
                *(uint32_t*)&Ch[(size_t)r0 * N + c0] = pack_hf2(h0,h1);
                *(uint32_t*)&Cl[(size_t)r0 * N + c0] = pack_hf2(l0,l1);
                split2h(v1.x, h0, l0); split2h(v1.y, h1, l1);
                *(uint32_t*)&Ch[(size_t)(r0 + 8) * N + c0] = pack_hf2(h0,h1);
                *(uint32_t*)&Cl[(size_t)(r0 + 8) * N + c0] = pack_hf2(l0,l1);
            } else {
                *(float2*)&C[(size_t)r0 * N + c0] = v0;
                *(float2*)&C[(size_t)(r0 + 8) * N + c0] = v1;
            }
        }
    }
}

// ---------------------------------------------------------------------------
// Tensor-core causal flash attention, fp16. Q split (h+l); K, V single fp16
// (hi plane of qkv only). Layout per row: h*192 + {q:0,k:64,v:128} + d.
// Block: 128 q rows x (b,h), 256 threads, K/V tiles of 64 keys, 2-stage.
// Smem halves: Qh 0, Ql 9216; stage s at 18432 + s*9216: Kh +0, Vh +4608.
// ---------------------------------------------------------------------------
#define AQ_H 0
#define AQ_L 9216
#define AKV_BASE 18432
#define AKV_STG  9216
#define A_KH 0
#define A_VH 4608
#define ATTN_SMEM ((18432 + 2*9216) * 2)   // 73728 bytes

__global__ __launch_bounds__(256)
void attn_tc(const hf* __restrict__ qkvh, const hf* __restrict__ qkvl,
             hf* __restrict__ outh, hf* __restrict__ outl) {
    extern __shared__ __align__(16) hf smem[];
    const uint32_t base = (uint32_t)__cvta_generic_to_shared(smem);

    const int tid = threadIdx.x, lane = tid & 31, warp = tid >> 5;
    const int qtile = blockIdx.x, bh = blockIdx.y;
    const int b = bh >> 4, h = bh & 15;
    const int qbase = qtile * 128;
    const int wrow = warp * 16;
    const int g = lane >> 2, tg = lane & 3;
    const int rA = lane & 15, cA = (lane >> 4) * 8;

    {
        #pragma unroll
        for (int t = 0; t < 4; t++) {
            int id = tid + t * 256;
            int r = id >> 3, cc = (id & 7) * 8;
            size_t src = (size_t)(b * LL + qbase + r) * 3072 + h * 192 + cc;
            uint32_t dst = (uint32_t)((r * 72 + cc) * 2);
            cp16(base + AQ_H*2 + dst, qkvh + src);
            cp16(base + AQ_L*2 + dst, qkvl + src);
        }
    }
#define KV_ISSUE(kstart, s) do {                                              \
        uint32_t sb = base + (AKV_BASE + (s) * AKV_STG) * 2;                  \
        _Pragma("unroll")                                                     \
        for (int t = 0; t < 2; t++) {                                         \
            int id = tid + t * 256;                                           \
            int r = id >> 3, cc = (id & 7) * 8;                               \
            size_t rowb = (size_t)(b * LL + (kstart) + r) * 3072 + h * 192;   \
            uint32_t dst = (uint32_t)((r * 72 + cc) * 2);                     \
            cp16(sb + A_KH*2 + dst, qkvh + rowb + 64 + cc);                   \
            cp16(sb + A_VH*2 + dst, qkvh + rowb + 128 + cc);                  \
        }                                                                     \
    } while (0)

    const int ntiles = qtile * 2 + 2;
    KV_ISSUE(0, 0); CP_COMMIT();
    if (ntiles > 1) KV_ISSUE(64, 1);
    CP_COMMIT();

    CP_WAIT1();
    __syncthreads();

    uint32_t qh[4][4], ql[4][4];
    #pragma unroll
    for (int j = 0; j < 4; j++) {
        uint32_t off = (uint32_t)(((wrow + rA) * 72 + j * 16 + cA) * 2);
        ldsm4(qh[j], base + AQ_H*2 + off);
        ldsm4(ql[j], base + AQ_L*2 + off);
    }

    float o[8][4];
    #pragma unroll
    for (int i = 0; i < 8; i++)
        #pragma unroll
        for (int k = 0; k < 4; k++) o[i][k] = 0.f;
    float m0 = -1e30f, m1 = -1e30f, li0 = 0.f, li1 = 0.f;

    const int row0 = qbase + wrow + g;
    const int row1 = row0 + 8;

    for (int it = 0; it < ntiles; it++) {
        if (it > 0) { CP_WAIT1(); __syncthreads(); }
        const int s = it & 1;
        const int kstart = it * 64;
        const uint32_t uK_h = base + (AKV_BASE + s * AKV_STG + A_KH) * 2;
        const uint32_t uV_h = base + (AKV_BASE + s * AKV_STG + A_VH) * 2;

        float sc[8][4];
        #pragma unroll
        for (int i = 0; i < 8; i++)
            #pragma unroll
            for (int k = 0; k < 4; k++) sc[i][k] = 0.f;

        #pragma unroll
        for (int j = 0; j < 4; j++) {
            #pragma unroll
            for (int kb = 0; kb < 4; kb++) {
                uint32_t off = (uint32_t)(((kb * 16 + rA) * 72 + j * 16 + cA) * 2);
                uint32_t kh[4];
                ldsm4(kh, uK_h + off);
                int n0 = kb * 2;
                mma16816(sc[n0],   qh[j], kh[0], kh[2]);
                mma16816(sc[n0],   ql[j], kh[0], kh[2]);
                mma16816(sc[n0+1], qh[j], kh[1], kh[3]);
                mma16816(sc[n0+1], ql[j], kh[1], kh[3]);
            }
        }

        const bool need_mask = (kstart + 63) > (qbase + wrow);
        #pragma unroll
        for (int ni = 0; ni < 8; ni++) {
            int col = kstart + ni * 8 + tg * 2;
            if (need_mask) {
                sc[ni][0] = (col     > row0) ? -1e30f : sc[ni][0] * 0.125f;
                sc[ni][1] = (col + 1 > row0) ? -1e30f : sc[ni][1] * 0.125f;
                sc[ni][2] = (col     > row1) ? -1e30f : sc[ni][2] * 0.125f;
                sc[ni][3] = (col + 1 > row1) ? -1e30f : sc[ni][3] * 0.125f;
            } else {
                sc[ni][0] *= 0.125f; sc[ni][1] *= 0.125f;
                sc[ni][2] *= 0.125f; sc[ni][3] *= 0.125f;
            }
        }

        float mx0 = m0, mx1 = m1;
        #pragma unroll
        for (int ni = 0; ni < 8; ni++) {
            mx0 = fmaxf(mx0, fmaxf(sc[ni][0], sc[ni][1]));
            mx1 = fmaxf(mx1, fmaxf(sc[ni][2], sc[ni][3]));
        }
        mx0 = fmaxf(mx0, __shfl_xor_sync(0xffffffffu, mx0, 1));
        mx0 = fmaxf(mx0, __shfl_xor_sync(0xffffffffu, mx0, 2));
        mx1 = fmaxf(mx1, __shfl_xor_sync(0xffffffffu, mx1, 1));
        mx1 = fmaxf(mx1, __shfl_xor_sync(0xffffffffu, mx1, 2));
        float cs0 = __expf(m0 - mx0), cs1 = __expf(m1 - mx1);
        m0 = mx0; m1 = mx1;
        li0 *= cs0; li1 *= cs1;
        #pragma unroll
        for (int ni = 0; ni < 8; ni++) {
            o[ni][0] *= cs0; o[ni][1] *= cs0;
            o[ni][2] *= cs1; o[ni][3] *= cs1;
        }
        float ps0 = 0.f, ps1 = 0.f;
        #pragma unroll
        for (int ni = 0; ni < 8; ni++) {
            sc[ni][0] = __expf(sc[ni][0] - m0);
            sc[ni][1] = __expf(sc[ni][1] - m0);
            sc[ni][2] = __expf(sc[ni][2] - m1);
            sc[ni][3] = __expf(sc[ni][3] - m1);
            ps0 += sc[ni][0] + sc[ni][1];
            ps1 += sc[ni][2] + sc[ni][3];
        }
        ps0 += __shfl_xor_sync(0xffffffffu, ps0, 1);
        ps0 += __shfl_xor_sync(0xffffffffu, ps0, 2);
        ps1 += __shfl_xor_sync(0xffffffffu, ps1, 1);
        ps1 += __shfl_xor_sync(0xffffffffu, ps1, 2);
        li0 += ps0; li1 += ps1;

        #pragma unroll
        for (int j = 0; j < 4; j++) {
            uint32_t pah[4], pal[4];
            {
                hf h0,h1,l0,l1;
                split2h(sc[2*j][0], h0, l0); split2h(sc[2*j][1], h1, l1);
                pah[0] = pack_hf2(h0,h1); pal[0] = pack_hf2(l0,l1);
                split2h(sc[2*j][2], h0, l0); split2h(sc[2*j][3], h1, l1);
                pah[1] = pack_hf2(h0,h1); pal[1] = pack_hf2(l0,l1);
                split2h(sc[2*j+1][0], h0, l0); split2h(sc[2*j+1][1], h1, l1);
                pah[2] = pack_hf2(h0,h1); pal[2] = pack_hf2(l0,l1);
                split2h(sc[2*j+1][2], h0, l0); split2h(sc[2*j+1][3], h1, l1);
                pah[3] = pack_hf2(h0,h1); pal[3] = pack_hf2(l0,l1);
            }
            #pragma unroll
            for (int nb = 0; nb < 4; nb++) {
                uint32_t off = (uint32_t)(((j * 16 + rA) * 72 + nb * 16 + cA) * 2);
                uint32_t vh[4];
                ldsm4t(vh, uV_h + off);
                int n0 = nb * 2;
                mma16816(o[n0],   pah, vh[0], vh[1]);
                mma16816(o[n0],   pal, vh[0], vh[1]);
                mma16816(o[n0+1], pah, vh[2], vh[3]);
                mma16816(o[n0+1], pal, vh[2], vh[3]);
            }
        }

        __syncthreads();
        if (it + 2 < ntiles) KV_ISSUE((it + 2) * 64, s);
        CP_COMMIT();
    }
#undef KV_ISSUE

    float inv0 = 1.f / li0, inv1 = 1.f / li1;
    size_t or0 = (size_t)(b * LL + row0) * EE + h * DHH;
    size_t or1 = (size_t)(b * LL + row1) * EE + h * DHH;
    #pragma unroll
    for (int ni = 0; ni < 8; ni++) {
        int cc = ni * 8 + tg * 2;
        hf h0,h1,l0,l1;
        split2h(o[ni][0] * inv0, h0, l0); split2h(o[ni][1] * inv0, h1, l1);
        *(uint32_t*)&outh[or0 + cc] = pack_hf2(h0,h1);
        *(uint32_t*)&outl[or0 + cc] = pack_hf2(l0,l1);
        split2h(o[ni][2] * inv1, h0, l0); split2h(o[ni][3] * inv1, h1, l1);
        *(uint32_t*)&outh[or1 + cc] = pack_hf2(h0,h1);
        *(uint32_t*)&outl[or1 + cc] = pack_hf2(l0,l1);
    }
}

// ---------------------------------------------------------------------------
// Launch
// ---------------------------------------------------------------------------
extern "C" void kernel_launch(void* const* d_in, const int* in_sizes, int n_in,
                              void* d_out, int out_size) {
    const float* x    = (const float*)d_in[0];
    const float* Wa   = (const float*)d_in[1];
    const float* Wout = (const float*)d_in[2];
    const float* bout = (const float*)d_in[3];
    const float* W1   = (const float*)d_in[4];
    const float* b1   = (const float*)d_in[5];
    const float* W2   = (const float*)d_in[6];
    const float* b2   = (const float*)d_in[7];
    const float* g1   = (const float*)d_in[8];
    const float* be1  = (const float*)d_in[9];
    const float* g2   = (const float*)d_in[10];
    const float* be2  = (const float*)d_in[11];
    float* out = (float*)d_out;

    unsigned char* arena;
    cudaGetSymbolAddress((void**)&arena, g_arena);

    hf* qkvh = (hf*)(arena + OFF_QKVH);
    hf* qkvl = (hf*)(arena + OFF_QKVL);
    float* res1 = (float*)(arena + OFF_RES1);
    hf* ath = (hf*)(arena + OFF_ATH);
    hf* atl = (hf*)(arena + OFF_ATL);
    hf* o1h = (hf*)(arena + OFF_O1H);
    hf* o1l = (hf*)(arena + OFF_O1L);
    hf* o2h = (hf*)(arena + OFF_O2H);
    hf* o2l = (hf*)(arena + OFF_O2L);
    hf* hh  = (hf*)(arena + OFF_HH);
    hf* hl  = (hf*)(arena + OFF_HL);
    hf* wah = (hf*)(arena + OFF_WAH);
    hf* woh = (hf*)(arena + OFF_WOH);
    hf* w1h = (hf*)(arena + OFF_W1H);
    hf* w2h = (hf*)(arena + OFF_W2H);

    static bool attr_done = false;
    if (!attr_done) {
        cudaFuncSetAttribute(gemm_fp16<false,false,true>,
            cudaFuncAttributeMaxDynamicSharedMemorySize, GEMM_SMEM);
        cudaFuncSetAttribute(gemm_fp16<true,true,false>,
            cudaFuncAttributeMaxDynamicSharedMemorySize, GEMM_SMEM);
        cudaFuncSetAttribute(gemm_fp16<true,false,true>,
            cudaFuncAttributeMaxDynamicSharedMemorySize, GEMM_SMEM);
        cudaFuncSetAttribute(attn_tc,
            cudaFuncAttributeMaxDynamicSharedMemorySize, ATTN_SMEM);
        attr_done = true;
    }

    // weight conversions (hi only)
    cvt_kernel<<<(EE*3072/4 + 255)/256, 256>>>(Wa,   wah, EE*3072/4);
    cvt_kernel<<<(EE*EE/4   + 255)/256, 256>>>(Wout, woh, EE*EE/4);
    cvt_kernel<<<(EE*HIDD/4 + 255)/256, 256>>>(W1,   w1h, EE*HIDD/4);
    cvt_kernel<<<(HIDD*EE/4 + 255)/256, 256>>>(W2,   w2h, HIDD*EE/4);

    // 1) o1 = LN(x)
    ln_split_kernel<<<MROWS, 256>>>(x, g1, be1, o1h, o1l);

    // 2) qkv = o1 @ Wa (split output)
    gemm_fp16<false,false,true><<<dim3(3072/128, MROWS/128), 256, GEMM_SMEM>>>(
        o1h, o1l, wah, nullptr, nullptr, nullptr, qkvh, qkvl,
        MROWS, 3072, EE);

    // 3) attention
    attn_tc<<<dim3(LL/128, BB*NHH), 256, ATTN_SMEM>>>(qkvh, qkvl, ath, atl);

    // 4) res1 = attn @ Wout + bout + x
    gemm_fp16<true,true,false><<<dim3(EE/128, MROWS/128), 256, GEMM_SMEM>>>(
        ath, atl, woh, bout, x, res1, nullptr, nullptr,
        MROWS, EE, EE);

    // 5) o2 = LN(res1)
    ln_split_kernel<<<MROWS, 256>>>(res1, g2, be2, o2h, o2l);

    // 6) h = o2 @ W1 + b1 (split output)
    gemm_fp16<true,false,true><<<dim3(HIDD/128, MROWS/128), 256, GEMM_SMEM>>>(
        o2h, o2l, w1h, b1, nullptr, nullptr, hh, hl,
        MROWS, HIDD, EE);

    // 7) out = h @ W2 + b2 + x
    gemm_fp16<true,true,false><<<dim3(EE/128, MROWS/128), 256, GEMM_SMEM>>>(
        hh, hl, w2h, b2, x, out, nullptr, nullptr,
        MROWS, EE, HIDD);
}

// round 7
// speedup vs baseline: 6.3338x; 1.5956x over previous
#include <cuda_runtime.h>
#include <cuda_fp16.h>
#include <cstdint>
#include <cstddef>

// Problem constants
#define BB   2
#define LL   2048
#define EE   1024
#define NHH  16
#define DHH  64
#define HIDD 4096
#define MROWS (BB*LL)          // 4096

typedef __half hf;

// ---------------------------------------------------------------------------
// Scratch arena
// ---------------------------------------------------------------------------
constexpr size_t SZ_QKV1 = (size_t)MROWS * 3072 * 2;   // fp16 plane
constexpr size_t SZ_RES1 = (size_t)MROWS * EE * 4;     // fp32
constexpr size_t SZ_ACT  = (size_t)MROWS * EE * 2;     // fp16 plane
constexpr size_t SZ_H    = (size_t)MROWS * HIDD * 2;   // fp16 plane
constexpr size_t SZ_WA   = (size_t)EE * 3072 * 2;
constexpr size_t SZ_WO   = (size_t)EE * EE * 2;
constexpr size_t SZ_W1   = (size_t)EE * HIDD * 2;
constexpr size_t SZ_W2   = (size_t)HIDD * EE * 2;

constexpr size_t OFF_QKVH = 0;
constexpr size_t OFF_QKVL = OFF_QKVH + SZ_QKV1;   // lo plane (only Q cols used)
constexpr size_t OFF_RES1 = OFF_QKVL + SZ_QKV1;
constexpr size_t OFF_AT   = OFF_RES1 + SZ_RES1;
constexpr size_t OFF_O1   = OFF_AT   + SZ_ACT;
constexpr size_t OFF_O2   = OFF_O1   + SZ_ACT;
constexpr size_t OFF_H    = OFF_O2   + SZ_ACT;
constexpr size_t OFF_WAH  = OFF_H    + SZ_H;
constexpr size_t OFF_WOH  = OFF_WAH  + SZ_WA;
constexpr size_t OFF_W1H  = OFF_WOH  + SZ_WO;
constexpr size_t OFF_W2H  = OFF_W1H  + SZ_W1;
constexpr size_t ARENA_SZ = OFF_W2H  + SZ_W2;

__device__ __align__(256) unsigned char g_arena[ARENA_SZ];

// ---------------------------------------------------------------------------
// Helpers
// ---------------------------------------------------------------------------
__device__ __forceinline__ void split2h(float v, hf& h, hf& l) {
    h = __float2half(v);
    l = __float2half(v - __half2float(h));
}
__device__ __forceinline__ uint32_t pack_hf2(hf a, hf b) {
    __half2 t; t.x = a; t.y = b;
    return *(uint32_t*)&t;
}
__device__ __forceinline__ void ldsm4(uint32_t* r, uint32_t a) {
    asm volatile("ldmatrix.sync.aligned.m8n8.x4.shared.b16 {%0,%1,%2,%3}, [%4];\n"
        : "=r"(r[0]), "=r"(r[1]), "=r"(r[2]), "=r"(r[3]) : "r"(a));
}
__device__ __forceinline__ void ldsm4t(uint32_t* r, uint32_t a) {
    asm volatile("ldmatrix.sync.aligned.m8n8.x4.trans.shared.b16 {%0,%1,%2,%3}, [%4];\n"
        : "=r"(r[0]), "=r"(r[1]), "=r"(r[2]), "=r"(r[3]) : "r"(a));
}
__device__ __forceinline__ void mma16816(float* c, const uint32_t* a, uint32_t b0, uint32_t b1) {
    asm volatile(
        "mma.sync.aligned.m16n8k16.row.col.f32.f16.f16.f32 "
        "{%0,%1,%2,%3}, {%4,%5,%6,%7}, {%8,%9}, {%0,%1,%2,%3};\n"
        : "+f"(c[0]), "+f"(c[1]), "+f"(c[2]), "+f"(c[3])
        : "r"(a[0]), "r"(a[1]), "r"(a[2]), "r"(a[3]), "r"(b0), "r"(b1));
}
__device__ __forceinline__ void cp16(uint32_t dst, const void* src) {
    asm volatile("cp.async.cg.shared.global [%0], [%1], 16;\n" :: "r"(dst), "l"(src));
}
#define CP_COMMIT() asm volatile("cp.async.commit_group;\n" ::: "memory")
#define CP_WAIT1()  asm volatile("cp.async.wait_group 1;\n" ::: "memory")

// ---------------------------------------------------------------------------
// fp32 -> fp16 converter (weights)
// ---------------------------------------------------------------------------
__global__ __launch_bounds__(256)
void cvt_kernel(const float* __restrict__ in, hf* __restrict__ oh, int n4) {
    int i = blockIdx.x * 256 + threadIdx.x;
    if (i >= n4) return;
    float4 v = ((const float4*)in)[i];
    uint2 p;
    p.x = pack_hf2(__float2half(v.x), __float2half(v.y));
    p.y = pack_hf2(__float2half(v.z), __float2half(v.w));
    *(uint2*)&oh[(size_t)i*4] = p;
}

// ---------------------------------------------------------------------------
// LayerNorm writing single fp16 plane
// ---------------------------------------------------------------------------
__global__ __launch_bounds__(256)
void ln_kernel(const float* __restrict__ in, const float* __restrict__ g,
               const float* __restrict__ be, hf* __restrict__ oh) {
    int row = blockIdx.x;
    int tid = threadIdx.x;
    const float4* ip = (const float4*)(in + (size_t)row * EE);
    float4 v = ip[tid];
    float s  = v.x + v.y + v.z + v.w;
    float ss = v.x*v.x + v.y*v.y + v.z*v.z + v.w*v.w;
    #pragma unroll
    for (int o = 16; o; o >>= 1) {
        s  += __shfl_xor_sync(0xffffffffu, s,  o);
        ss += __shfl_xor_sync(0xffffffffu, ss, o);
    }
    __shared__ float sm[8], sm2[8];
    int w = tid >> 5;
    if ((tid & 31) == 0) { sm[w] = s; sm2[w] = ss; }
    __syncthreads();
    float ts = 0.f, tss = 0.f;
    #pragma unroll
    for (int i = 0; i < 8; i++) { ts += sm[i]; tss += sm2[i]; }
    float mu  = ts  * (1.f / EE);
    float var = tss * (1.f / EE) - mu * mu;
    float rs  = rsqrtf(var + 1e-5f);
    float4 gv = ((const float4*)g)[tid];
    float4 bv = ((const float4*)be)[tid];
    float4 o;
    o.x = (v.x - mu) * rs * gv.x + bv.x;
    o.y = (v.y - mu) * rs * gv.y + bv.y;
    o.z = (v.z - mu) * rs * gv.z + bv.z;
    o.w = (v.w - mu) * rs * gv.w + bv.w;
    size_t base = (size_t)row * EE + tid * 4;
    *(uint32_t*)&oh[base]     = pack_hf2(__float2half(o.x), __float2half(o.y));
    *(uint32_t*)&oh[base + 2] = pack_hf2(__float2half(o.z), __float2half(o.w));
}

// ---------------------------------------------------------------------------
// fp16 tensor-core GEMM: C = A @ B (both single fp16).
// Block 128x128, BK=32, 8 warps (2Mx4N), warp tile 64x32, mma.m16n8k16.
// 2-stage cp.async, 2 CTAs/SM.
// ---------------------------------------------------------------------------
#define SA 40
#define SB 136
#define G_AH 0
#define G_BH 5120
#define G_STG 9472
#define GEMM_SMEM (2 * G_STG * 2)  // 37888 bytes

template<bool BIAS, bool RES, bool SPLIT>
__global__ __launch_bounds__(256, 2)
void gemm_fp16(const hf* __restrict__ Ah, const hf* __restrict__ Bh,
               const float* __restrict__ bias, const float* __restrict__ res,
               float* __restrict__ C, hf* __restrict__ Ch, hf* __restrict__ Cl,
               int M, int N, int K) {
    extern __shared__ __align__(16) hf smem[];
    const uint32_t base = (uint32_t)__cvta_generic_to_shared(smem);

    const int tid = threadIdx.x, lane = tid & 31, warp = tid >> 5;
    const int wm = (warp & 1) * 64, wn = (warp >> 1) * 32;
    const int rowBase = blockIdx.y * 128, colBase = blockIdx.x * 128;

    const int am = tid >> 2, ak = (tid & 3) * 8;
    const int bk = tid >> 4, bn = (tid & 15) * 8;

    const hf* gAh = Ah + (size_t)(rowBase + am) * K + ak;
    const hf* gBh = Bh + (size_t)bk * N + colBase + bn;
    const size_t aStep = 64 * (size_t)K;
    const size_t bStep = 16 * (size_t)N;

    const uint32_t sA0 = (uint32_t)((am * SA + ak) * 2);
    const uint32_t sA1 = (uint32_t)(((am + 64) * SA + ak) * 2);
    const uint32_t sB0 = (uint32_t)((bk * SB + bn) * 2);
    const uint32_t sB1 = (uint32_t)(((bk + 16) * SB + bn) * 2);

#define G_ISSUE(kt, s) do {                                                   \
        uint32_t sb = base + (uint32_t)(s) * (G_STG * 2);                     \
        cp16(sb + G_AH*2 + sA0, gAh + (kt));                                  \
        cp16(sb + G_AH*2 + sA1, gAh + aStep + (kt));                          \
        cp16(sb + G_BH*2 + sB0, gBh + (size_t)(kt) * N);                      \
        cp16(sb + G_BH*2 + sB1, gBh + (size_t)(kt) * N + bStep);              \
    } while (0)

    const int rA = lane & 15, cA = (lane >> 4) * 8;
    const int rB = lane & 15, cB = (lane >> 4) * 8;

    float acc[4][4][4];
    #pragma unroll
    for (int i = 0; i < 4; i++)
        #pragma unroll
        for (int j = 0; j < 4; j++)
            #pragma unroll
            for (int k = 0; k < 4; k++) acc[i][j][k] = 0.f;

    G_ISSUE(0, 0); CP_COMMIT();
    G_ISSUE(32, 1); CP_COMMIT();

    const int nk = K >> 5;
    for (int i = 0; i < nk; i++) {
        CP_WAIT1();
        __syncthreads();
        const int s = i & 1;
        const uint32_t uAh = base + s * (G_STG*2) + G_AH*2;
        const uint32_t uBh = base + s * (G_STG*2) + G_BH*2;

        #pragma unroll
        for (int kk = 0; kk < 32; kk += 16) {
            uint32_t bhf[2][4];
            #pragma unroll
            for (int j = 0; j < 2; j++) {
                uint32_t offB = (uint32_t)(((kk + rB) * SB + wn + j * 16 + cB) * 2);
                ldsm4t(bhf[j], uBh + offB);
            }
            #pragma unroll
            for (int mi = 0; mi < 4; mi++) {
                uint32_t offA = (uint32_t)(((wm + mi * 16 + rA) * SA + kk + cA) * 2);
                uint32_t ahf[4];
                ldsm4(ahf, uAh + offA);
                #pragma unroll
                for (int ni = 0; ni < 4; ni++) {
                    uint32_t b0 = bhf[ni >> 1][(ni & 1) * 2];
                    uint32_t b1 = bhf[ni >> 1][(ni & 1) * 2 + 1];
                    mma16816(acc[mi][ni], ahf, b0, b1);
                }
            }
        }
        __syncthreads();
        if (i + 2 < nk) G_ISSUE((i + 2) * 32, s);
        CP_COMMIT();
    }
#undef G_ISSUE

    // epilogue
    const int g = lane >> 2, tg = lane & 3;
    #pragma unroll
    for (int mi = 0; mi < 4; mi++) {
        #pragma unroll
        for (int ni = 0; ni < 4; ni++) {
            int r0 = rowBase + wm + mi * 16 + g;
            int c0 = colBase + wn + ni * 8 + tg * 2;
            float* a = acc[mi][ni];
            float2 v0 = make_float2(a[0], a[1]);
            float2 v1 = make_float2(a[2], a[3]);
            if (BIAS) {
                float bx = bias[c0], by = bias[c0 + 1];
                v0.x += bx; v0.y += by; v1.x += bx; v1.y += by;
            }
            if (RES) {
                float2 q0 = *(const float2*)&res[(size_t)r0 * N + c0];
                float2 q1 = *(const float2*)&res[(size_t)(r0 + 8) * N + c0];
                v0.x += q0.x; v0.y += q0.y; v1.x += q1.x; v1.y += q1.y;
            }
            if (SPLIT) {
                hf h0,h1,l0,l1;
                split2h(v0.x, h0, l0); split2h(v0.y, h1, l1);
                *(uint32_t*)&Ch[(size_t)r0 * N + c0] = pack_hf2(h0,h1);
                *(uint32_t*)&Cl[(size_t)r0 * N + c0] = pack_hf2(l0,l1);
                split2h(v1.x, h0, l0); split2h(v1.y, h1, l1);
                *(uint32_t*)&Ch[(size_t)(r0 + 8) * N + c0] = pack_hf2(h0,h1);
                *(uint32_t*)&Cl[(size_t)(r0 + 8) * N + c0] = pack_hf2(l0,l1);
            } else if (Ch != nullptr) {
                // single fp16 plane output
                *(uint32_t*)&Ch[(size_t)r0 * N + c0] =
                    pack_hf2(__float2half(v0.x), __float2half(v0.y));
                *(uint32_t*)&Ch[(size_t)(r0 + 8) * N + c0] =
                    pack_hf2(__float2half(v1.x), __float2half(v1.y));
            } else {
                *(float2*)&C[(size_t)r0 * N + c0] = v0;
                *(float2*)&C[(size_t)(r0 + 8) * N + c0] = v1;
            }
        }
    }
}

// ---------------------------------------------------------------------------
// Tensor-core causal flash attention, fp16. Q split (h+l); K, V, P single.
// qkv layout per row: h*192 + {q:0,k:64,v:128} + d.
// Block: 128 q rows x (b,h), 256 threads, K/V tiles of 64 keys, 2-stage.
// Smem halves: Qh 0, Ql 9216; stage s at 18432 + s*9216: Kh +0, Vh +4608.
// ---------------------------------------------------------------------------
#define AQ_H 0
#define AQ_L 9216
#define AKV_BASE 18432
#define AKV_STG  9216
#define A_KH 0
#define A_VH 4608
#define ATTN_SMEM ((18432 + 2*9216) * 2)   // 73728 bytes

__global__ __launch_bounds__(256)
void attn_tc(const hf* __restrict__ qkvh, const hf* __restrict__ qkvl,
             hf* __restrict__ outh) {
    extern __shared__ __align__(16) hf smem[];
    const uint32_t base = (uint32_t)__cvta_generic_to_shared(smem);

    const int tid = threadIdx.x, lane = tid & 31, warp = tid >> 5;
    const int qtile = blockIdx.x, bh = blockIdx.y;
    const int b = bh >> 4, h = bh & 15;
    const int qbase = qtile * 128;
    const int wrow = warp * 16;
    const int g = lane >> 2, tg = lane & 3;
    const int rA = lane & 15, cA = (lane >> 4) * 8;

    {
        #pragma unroll
        for (int t = 0; t < 4; t++) {
            int id = tid + t * 256;
            int r = id >> 3, cc = (id & 7) * 8;
            size_t src = (size_t)(b * LL + qbase + r) * 3072 + h * 192 + cc;
            uint32_t dst = (uint32_t)((r * 72 + cc) * 2);
            cp16(base + AQ_H*2 + dst, qkvh + src);
            cp16(base + AQ_L*2 + dst, qkvl + src);
        }
    }
#define KV_ISSUE(kstart, s) do {                                              \
        uint32_t sb = base + (AKV_BASE + (s) * AKV_STG) * 2;                  \
        _Pragma("unroll")                                                     \
        for (int t = 0; t < 2; t++) {                                         \
            int id = tid + t * 256;                                           \
            int r = id >> 3, cc = (id & 7) * 8;                               \
            size_t rowb = (size_t)(b * LL + (kstart) + r) * 3072 + h * 192;   \
            uint32_t dst = (uint32_t)((r * 72 + cc) * 2);                     \
            cp16(sb + A_KH*2 + dst, qkvh + rowb + 64 + cc);                   \
            cp16(sb + A_VH*2 + dst, qkvh + rowb + 128 + cc);                  \
        }                                                                     \
    } while (0)

    const int ntiles = qtile * 2 + 2;
    KV_ISSUE(0, 0); CP_COMMIT();
    if (ntiles > 1) KV_ISSUE(64, 1);
    CP_COMMIT();

    CP_WAIT1();
    __syncthreads();

    uint32_t qh[4][4], ql[4][4];
    #pragma unroll
    for (int j = 0; j < 4; j++) {
        uint32_t off = (uint32_t)(((wrow + rA) * 72 + j * 16 + cA) * 2);
        ldsm4(qh[j], base + AQ_H*2 + off);
        ldsm4(ql[j], base + AQ_L*2 + off);
    }

    float o[8][4];
    #pragma unroll
    for (int i = 0; i < 8; i++)
        #pragma unroll
        for (int k = 0; k < 4; k++) o[i][k] = 0.f;
    float m0 = -1e30f, m1 = -1e30f, li0 = 0.f, li1 = 0.f;

    const int row0 = qbase + wrow + g;
    const int row1 = row0 + 8;

    for (int it = 0; it < ntiles; it++) {
        if (it > 0) { CP_WAIT1(); __syncthreads(); }
        const int s = it & 1;
        const int kstart = it * 64;
        const uint32_t uK_h = base + (AKV_BASE + s * AKV_STG + A_KH) * 2;
        const uint32_t uV_h = base + (AKV_BASE + s * AKV_STG + A_VH) * 2;

        float sc[8][4];
        #pragma unroll
        for (int i = 0; i < 8; i++)
            #pragma unroll
            for (int k = 0; k < 4; k++) sc[i][k] = 0.f;

        #pragma unroll
        for (int j = 0; j < 4; j++) {
            #pragma unroll
            for (int kb = 0; kb < 4; kb++) {
                uint32_t off = (uint32_t)(((kb * 16 + rA) * 72 + j * 16 + cA) * 2);
                uint32_t kh[4];
                ldsm4(kh, uK_h + off);
                int n0 = kb * 2;
                mma16816(sc[n0],   qh[j], kh[0], kh[2]);
                mma16816(sc[n0],   ql[j], kh[0], kh[2]);
                mma16816(sc[n0+1], qh[j], kh[1], kh[3]);
                mma16816(sc[n0+1], ql[j], kh[1], kh[3]);
            }
        }

        const bool need_mask = (kstart + 63) > (qbase + wrow);
        #pragma unroll
        for (int ni = 0; ni < 8; ni++) {
            int col = kstart + ni * 8 + tg * 2;
            if (need_mask) {
                sc[ni][0] = (col     > row0) ? -1e30f : sc[ni][0] * 0.125f;
                sc[ni][1] = (col + 1 > row0) ? -1e30f : sc[ni][1] * 0.125f;
                sc[ni][2] = (col     > row1) ? -1e30f : sc[ni][2] * 0.125f;
                sc[ni][3] = (col + 1 > row1) ? -1e30f : sc[ni][3] * 0.125f;
            } else {
                sc[ni][0] *= 0.125f; sc[ni][1] *= 0.125f;
                sc[ni][2] *= 0.125f; sc[ni][3] *= 0.125f;
            }
        }

        float mx0 = m0, mx1 = m1;
        #pragma unroll
        for (int ni = 0; ni < 8; ni++) {
            mx0 = fmaxf(mx0, fmaxf(sc[ni][0], sc[ni][1]));
            mx1 = fmaxf(mx1, fmaxf(sc[ni][2], sc[ni][3]));
        }
        mx0 = fmaxf(mx0, __shfl_xor_sync(0xffffffffu, mx0, 1));
        mx0 = fmaxf(mx0, __shfl_xor_sync(0xffffffffu, mx0, 2));
        mx1 = fmaxf(mx1, __shfl_xor_sync(0xffffffffu, mx1, 1));
        mx1 = fmaxf(mx1, __shfl_xor_sync(0xffffffffu, mx1, 2));
        float cs0 = __expf(m0 - mx0), cs1 = __expf(m1 - mx1);
        m0 = mx0; m1 = mx1;
        li0 *= cs0; li1 *= cs1;
        #pragma unroll
        for (int ni = 0; ni < 8; ni++) {
            o[ni][0] *= cs0; o[ni][1] *= cs0;
            o[ni][2] *= cs1; o[ni][3] *= cs1;
        }
        float ps0 = 0.f, ps1 = 0.f;
        #pragma unroll
        for (int ni = 0; ni < 8; ni++) {
            sc[ni][0] = __expf(sc[ni][0] - m0);
            sc[ni][1] = __expf(sc[ni][1] - m0);
            sc[ni][2] = __expf(sc[ni][2] - m1);
            sc[ni][3] = __expf(sc[ni][3] - m1);
            ps0 += sc[ni][0] + sc[ni][1];
            ps1 += sc[ni][2] + sc[ni][3];
        }
        ps0 += __shfl_xor_sync(0xffffffffu, ps0, 1);
        ps0 += __shfl_xor_sync(0xffffffffu, ps0, 2);
        ps1 += __shfl_xor_sync(0xffffffffu, ps1, 1);
        ps1 += __shfl_xor_sync(0xffffffffu, ps1, 2);
        li0 += ps0; li1 += ps1;

        #pragma unroll
        for (int j = 0; j < 4; j++) {
            uint32_t pah[4];
            pah[0] = pack_hf2(__float2half(sc[2*j][0]),   __float2half(sc[2*j][1]));
            pah[1] = pack_hf2(__float2half(sc[2*j][2]),   __float2half(sc[2*j][3]));
            pah[2] = pack_hf2(__float2half(sc[2*j+1][0]), __float2half(sc[2*j+1][1]));
            pah[3] = pack_hf2(__float2half(sc[2*j+1][2]), __float2half(sc[2*j+1][3]));
            #pragma unroll
            for (int nb = 0; nb < 4; nb++) {
                uint32_t off = (uint32_t)(((j * 16 + rA) * 72 + nb * 16 + cA) * 2);
                uint32_t vh[4];
                ldsm4t(vh, uV_h + off);
                int n0 = nb * 2;
                mma16816(o[n0],   pah, vh[0], vh[1]);
                mma16816(o[n0+1], pah, vh[2], vh[3]);
            }
        }

        __syncthreads();
        if (it + 2 < ntiles) KV_ISSUE((it + 2) * 64, s);
        CP_COMMIT();
    }
#undef KV_ISSUE

    float inv0 = 1.f / li0, inv1 = 1.f / li1;
    size_t or0 = (size_t)(b * LL + row0) * EE + h * DHH;
    size_t or1 = (size_t)(b * LL + row1) * EE + h * DHH;
    #pragma unroll
    for (int ni = 0; ni < 8; ni++) {
        int cc = ni * 8 + tg * 2;
        *(uint32_t*)&outh[or0 + cc] =
            pack_hf2(__float2half(o[ni][0] * inv0), __float2half(o[ni][1] * inv0));
        *(uint32_t*)&outh[or1 + cc] =
            pack_hf2(__float2half(o[ni][2] * inv1), __float2half(o[ni][3] * inv1));
    }
}

// ---------------------------------------------------------------------------
// Launch
// ---------------------------------------------------------------------------
extern "C" void kernel_launch(void* const* d_in, const int* in_sizes, int n_in,
                              void* d_out, int out_size) {
    const float* x    = (const float*)d_in[0];
    const float* Wa   = (const float*)d_in[1];
    const float* Wout = (const float*)d_in[2];
    const float* bout = (const float*)d_in[3];
    const float* W1   = (const float*)d_in[4];
    const float* b1   = (const float*)d_in[5];
    const float* W2   = (const float*)d_in[6];
    const float* b2   = (const float*)d_in[7];
    const float* g1   = (const float*)d_in[8];
    const float* be1  = (const float*)d_in[9];
    const float* g2   = (const float*)d_in[10];
    const float* be2  = (const float*)d_in[11];
    float* out = (float*)d_out;

    unsigned char* arena;
    cudaGetSymbolAddress((void**)&arena, g_arena);

    hf* qkvh = (hf*)(arena + OFF_QKVH);
    hf* qkvl = (hf*)(arena + OFF_QKVL);
    float* res1 = (float*)(arena + OFF_RES1);
    hf* at  = (hf*)(arena + OFF_AT);
    hf* o1  = (hf*)(arena + OFF_O1);
    hf* o2  = (hf*)(arena + OFF_O2);
    hf* hh  = (hf*)(arena + OFF_H);
    hf* wah = (hf*)(arena + OFF_WAH);
    hf* woh = (hf*)(arena + OFF_WOH);
    hf* w1h = (hf*)(arena + OFF_W1H);
    hf* w2h = (hf*)(arena + OFF_W2H);

    static bool attr_done = false;
    if (!attr_done) {
        cudaFuncSetAttribute(gemm_fp16<false,false,true>,
            cudaFuncAttributeMaxDynamicSharedMemorySize, GEMM_SMEM);
        cudaFuncSetAttribute(gemm_fp16<true,true,false>,
            cudaFuncAttributeMaxDynamicSharedMemorySize, GEMM_SMEM);
        cudaFuncSetAttribute(gemm_fp16<true,false,false>,
            cudaFuncAttributeMaxDynamicSharedMemorySize, GEMM_SMEM);
        cudaFuncSetAttribute(attn_tc,
            cudaFuncAttributeMaxDynamicSharedMemorySize, ATTN_SMEM);
        attr_done = true;
    }

    // weight conversions
    cvt_kernel<<<(EE*3072/4 + 255)/256, 256>>>(Wa,   wah, EE*3072/4);
    cvt_kernel<<<(EE*EE/4   + 255)/256, 256>>>(Wout, woh, EE*EE/4);
    cvt_kernel<<<(EE*HIDD/4 + 255)/256, 256>>>(W1,   w1h, EE*HIDD/4);
    cvt_kernel<<<(HIDD*EE/4 + 255)/256, 256>>>(W2,   w2h, HIDD*EE/4);

    // 1) o1 = LN(x)  (single fp16 plane)
    ln_kernel<<<MROWS, 256>>>(x, g1, be1, o1);

    // 2) qkv = o1 @ Wa (split hi/lo output; lo used for Q only)
    gemm_fp16<false,false,true><<<dim3(3072/128, MROWS/128), 256, GEMM_SMEM>>>(
        o1, wah, nullptr, nullptr, nullptr, qkvh, qkvl,
        MROWS, 3072, EE);

    // 3) attention (single-plane output)
    attn_tc<<<dim3(LL/128, BB*NHH), 256, ATTN_SMEM>>>(qkvh, qkvl, at);

    // 4) res1 = attn @ Wout + bout + x  (fp32 out)
    gemm_fp16<true,true,false><<<dim3(EE/128, MROWS/128), 256, GEMM_SMEM>>>(
        at, woh, bout, x, res1, nullptr, nullptr,
        MROWS, EE, EE);

    // 5) o2 = LN(res1) (single plane)
    ln_kernel<<<MROWS, 256>>>(res1, g2, be2, o2);

    // 6) h = o2 @ W1 + b1  (single fp16 plane output)
    gemm_fp16<true,false,false><<<dim3(HIDD/128, MROWS/128), 256, GEMM_SMEM>>>(
        o2, w1h, b1, nullptr, nullptr, hh, nullptr,
        MROWS, HIDD, EE);

    // 7) out = h @ W2 + b2 + x (fp32 out)
    gemm_fp16<true,true,false><<<dim3(EE/128, MROWS/128), 256, GEMM_SMEM>>>(
        hh, w2h, b2, x, out, nullptr, nullptr,
        MROWS, EE, HIDD);
}

// round 8
// speedup vs baseline: 6.3914x; 1.0091x over previous
#include <cuda_runtime.h>
#include <cuda_fp16.h>
#include <cstdint>
#include <cstddef>

// Problem constants
#define BB   2
#define LL   2048
#define EE   1024
#define NHH  16
#define DHH  64
#define HIDD 4096
#define MROWS (BB*LL)          // 4096

typedef __half hf;

// ---------------------------------------------------------------------------
// Scratch arena
// ---------------------------------------------------------------------------
constexpr size_t SZ_QKV1 = (size_t)MROWS * 3072 * 2;
constexpr size_t SZ_RES1 = (size_t)MROWS * EE * 4;
constexpr size_t SZ_ACT  = (size_t)MROWS * EE * 2;
constexpr size_t SZ_H    = (size_t)MROWS * HIDD * 2;
constexpr size_t SZ_WA   = (size_t)EE * 3072 * 2;
constexpr size_t SZ_WO   = (size_t)EE * EE * 2;
constexpr size_t SZ_W1   = (size_t)EE * HIDD * 2;
constexpr size_t SZ_W2   = (size_t)HIDD * EE * 2;

constexpr size_t OFF_QKVH = 0;
constexpr size_t OFF_QKVL = OFF_QKVH + SZ_QKV1;
constexpr size_t OFF_RES1 = OFF_QKVL + SZ_QKV1;
constexpr size_t OFF_AT   = OFF_RES1 + SZ_RES1;
constexpr size_t OFF_O1   = OFF_AT   + SZ_ACT;
constexpr size_t OFF_O2   = OFF_O1   + SZ_ACT;
constexpr size_t OFF_H    = OFF_O2   + SZ_ACT;
constexpr size_t OFF_WAH  = OFF_H    + SZ_H;
constexpr size_t OFF_WOH  = OFF_WAH  + SZ_WA;
constexpr size_t OFF_W1H  = OFF_WOH  + SZ_WO;
constexpr size_t OFF_W2H  = OFF_W1H  + SZ_W1;
constexpr size_t ARENA_SZ = OFF_W2H  + SZ_W2;

__device__ __align__(256) unsigned char g_arena[ARENA_SZ];

// ---------------------------------------------------------------------------
// Helpers
// ---------------------------------------------------------------------------
__device__ __forceinline__ void split2h(float v, hf& h, hf& l) {
    h = __float2half(v);
    l = __float2half(v - __half2float(h));
}
__device__ __forceinline__ uint32_t pack_hf2(hf a, hf b) {
    __half2 t; t.x = a; t.y = b;
    return *(uint32_t*)&t;
}
__device__ __forceinline__ void ldsm4(uint32_t* r, uint32_t a) {
    asm volatile("ldmatrix.sync.aligned.m8n8.x4.shared.b16 {%0,%1,%2,%3}, [%4];\n"
        : "=r"(r[0]), "=r"(r[1]), "=r"(r[2]), "=r"(r[3]) : "r"(a));
}
__device__ __forceinline__ void ldsm4t(uint32_t* r, uint32_t a) {
    asm volatile("ldmatrix.sync.aligned.m8n8.x4.trans.shared.b16 {%0,%1,%2,%3}, [%4];\n"
        : "=r"(r[0]), "=r"(r[1]), "=r"(r[2]), "=r"(r[3]) : "r"(a));
}
__device__ __forceinline__ void mma16816(float* c, const uint32_t* a, uint32_t b0, uint32_t b1) {
    asm volatile(
        "mma.sync.aligned.m16n8k16.row.col.f32.f16.f16.f32 "
        "{%0,%1,%2,%3}, {%4,%5,%6,%7}, {%8,%9}, {%0,%1,%2,%3};\n"
        : "+f"(c[0]), "+f"(c[1]), "+f"(c[2]), "+f"(c[3])
        : "r"(a[0]), "r"(a[1]), "r"(a[2]), "r"(a[3]), "r"(b0), "r"(b1));
}
__device__ __forceinline__ void cp16(uint32_t dst, const void* src) {
    asm volatile("cp.async.cg.shared.global [%0], [%1], 16;\n" :: "r"(dst), "l"(src));
}
#define CP_COMMIT() asm volatile("cp.async.commit_group;\n" ::: "memory")
#define CP_WAIT1()  asm volatile("cp.async.wait_group 1;\n" ::: "memory")

// ---------------------------------------------------------------------------
// fp32 -> fp16 converter (weights)
// ---------------------------------------------------------------------------
__global__ __launch_bounds__(256)
void cvt_kernel(const float* __restrict__ in, hf* __restrict__ oh, int n4) {
    int i = blockIdx.x * 256 + threadIdx.x;
    if (i >= n4) return;
    float4 v = ((const float4*)in)[i];
    uint2 p;
    p.x = pack_hf2(__float2half(v.x), __float2half(v.y));
    p.y = pack_hf2(__float2half(v.z), __float2half(v.w));
    *(uint2*)&oh[(size_t)i*4] = p;
}

// ---------------------------------------------------------------------------
// LayerNorm writing single fp16 plane
// ---------------------------------------------------------------------------
__global__ __launch_bounds__(256)
void ln_kernel(const float* __restrict__ in, const float* __restrict__ g,
               const float* __restrict__ be, hf* __restrict__ oh) {
    int row = blockIdx.x;
    int tid = threadIdx.x;
    const float4* ip = (const float4*)(in + (size_t)row * EE);
    float4 v = ip[tid];
    float s  = v.x + v.y + v.z + v.w;
    float ss = v.x*v.x + v.y*v.y + v.z*v.z + v.w*v.w;
    #pragma unroll
    for (int o = 16; o; o >>= 1) {
        s  += __shfl_xor_sync(0xffffffffu, s,  o);
        ss += __shfl_xor_sync(0xffffffffu, ss, o);
    }
    __shared__ float sm[8], sm2[8];
    int w = tid >> 5;
    if ((tid & 31) == 0) { sm[w] = s; sm2[w] = ss; }
    __syncthreads();
    float ts = 0.f, tss = 0.f;
    #pragma unroll
    for (int i = 0; i < 8; i++) { ts += sm[i]; tss += sm2[i]; }
    float mu  = ts  * (1.f / EE);
    float var = tss * (1.f / EE) - mu * mu;
    float rs  = rsqrtf(var + 1e-5f);
    float4 gv = ((const float4*)g)[tid];
    float4 bv = ((const float4*)be)[tid];
    float4 o;
    o.x = (v.x - mu) * rs * gv.x + bv.x;
    o.y = (v.y - mu) * rs * gv.y + bv.y;
    o.z = (v.z - mu) * rs * gv.z + bv.z;
    o.w = (v.w - mu) * rs * gv.w + bv.w;
    size_t base = (size_t)row * EE + tid * 4;
    *(uint32_t*)&oh[base]     = pack_hf2(__float2half(o.x), __float2half(o.y));
    *(uint32_t*)&oh[base + 2] = pack_hf2(__float2half(o.z), __float2half(o.w));
}

// ---------------------------------------------------------------------------
// fp16 tensor-core GEMM: C = A @ B (single fp16 operands).
// Block 128x128, BK=32, 8 warps (2Mx4N), warp tile 64x32, mma.m16n8k16.
// 3-stage cp.async ring, 2 groups in flight, ONE __syncthreads per iteration.
// ---------------------------------------------------------------------------
#define SA 40
#define SB 136
#define G_AH 0
#define G_BH 5120
#define G_STG 9472
#define GEMM_SMEM (3 * G_STG * 2)  // 56832 bytes

template<bool BIAS, bool RES, bool SPLIT>
__global__ __launch_bounds__(256, 2)
void gemm_fp16(const hf* __restrict__ Ah, const hf* __restrict__ Bh,
               const float* __restrict__ bias, const float* __restrict__ res,
               float* __restrict__ C, hf* __restrict__ Ch, hf* __restrict__ Cl,
               int M, int N, int K) {
    extern __shared__ __align__(16) hf smem[];
    const uint32_t base = (uint32_t)__cvta_generic_to_shared(smem);

    const int tid = threadIdx.x, lane = tid & 31, warp = tid >> 5;
    const int wm = (warp & 1) * 64, wn = (warp >> 1) * 32;
    const int rowBase = blockIdx.y * 128, colBase = blockIdx.x * 128;

    const int am = tid >> 2, ak = (tid & 3) * 8;
    const int bk = tid >> 4, bn = (tid & 15) * 8;

    const hf* gAh = Ah + (size_t)(rowBase + am) * K + ak;
    const hf* gBh = Bh + (size_t)bk * N + colBase + bn;
    const size_t aStep = 64 * (size_t)K;
    const size_t bStep = 16 * (size_t)N;

    const uint32_t sA0 = (uint32_t)((am * SA + ak) * 2);
    const uint32_t sA1 = (uint32_t)(((am + 64) * SA + ak) * 2);
    const uint32_t sB0 = (uint32_t)((bk * SB + bn) * 2);
    const uint32_t sB1 = (uint32_t)(((bk + 16) * SB + bn) * 2);

#define G_ISSUE(kt, s) do {                                                   \
        uint32_t sb = base + (uint32_t)(s) * (G_STG * 2);                     \
        cp16(sb + G_AH*2 + sA0, gAh + (kt));                                  \
        cp16(sb + G_AH*2 + sA1, gAh + aStep + (kt));                          \
        cp16(sb + G_BH*2 + sB0, gBh + (size_t)(kt) * N);                      \
        cp16(sb + G_BH*2 + sB1, gBh + (size_t)(kt) * N + bStep);              \
    } while (0)

    const int rA = lane & 15, cA = (lane >> 4) * 8;
    const int rB = lane & 15, cB = (lane >> 4) * 8;

    float acc[4][4][4];
    #pragma unroll
    for (int i = 0; i < 4; i++)
        #pragma unroll
        for (int j = 0; j < 4; j++)
            #pragma unroll
            for (int k = 0; k < 4; k++) acc[i][j][k] = 0.f;

    G_ISSUE(0, 0);  CP_COMMIT();
    G_ISSUE(32, 1); CP_COMMIT();     // K >= 64 for all our GEMMs

    const int nk = K >> 5;
    for (int i = 0; i < nk; i++) {
        CP_WAIT1();                  // stage i%3 ready; one group still in flight
        __syncthreads();             // also gates reuse of stage (i+2)%3 == (i-1)%3
        if (i + 2 < nk) G_ISSUE((i + 2) * 32, (i + 2) % 3);
        CP_COMMIT();

        const int s = i % 3;
        const uint32_t uAh = base + s * (G_STG*2) + G_AH*2;
        const uint32_t uBh = base + s * (G_STG*2) + G_BH*2;

        #pragma unroll
        for (int kk = 0; kk < 32; kk += 16) {
            uint32_t bhf[2][4];
            #pragma unroll
            for (int j = 0; j < 2; j++) {
                uint32_t offB = (uint32_t)(((kk + rB) * SB + wn + j * 16 + cB) * 2);
                ldsm4t(bhf[j], uBh + offB);
            }
            #pragma unroll
            for (int mi = 0; mi < 4; mi++) {
                uint32_t offA = (uint32_t)(((wm + mi * 16 + rA) * SA + kk + cA) * 2);
                uint32_t ahf[4];
                ldsm4(ahf, uAh + offA);
                #pragma unroll
                for (int ni = 0; ni < 4; ni++) {
                    uint32_t b0 = bhf[ni >> 1][(ni & 1) * 2];
                    uint32_t b1 = bhf[ni >> 1][(ni & 1) * 2 + 1];
                    mma16816(acc[mi][ni], ahf, b0, b1);
                }
            }
        }
    }
#undef G_ISSUE

    // epilogue
    const int g = lane >> 2, tg = lane & 3;
    #pragma unroll
    for (int mi = 0; mi < 4; mi++) {
        #pragma unroll
        for (int ni = 0; ni < 4; ni++) {
            int r0 = rowBase + wm + mi * 16 + g;
            int c0 = colBase + wn + ni * 8 + tg * 2;
            float* a = acc[mi][ni];
            float2 v0 = make_float2(a[0], a[1]);
            float2 v1 = make_float2(a[2], a[3]);
            if (BIAS) {
                float bx = bias[c0], by = bias[c0 + 1];
                v0.x += bx; v0.y += by; v1.x += bx; v1.y += by;
            }
            if (RES) {
                float2 q0 = *(const float2*)&res[(size_t)r0 * N + c0];
                float2 q1 = *(const float2*)&res[(size_t)(r0 + 8) * N + c0];
                v0.x += q0.x; v0.y += q0.y; v1.x += q1.x; v1.y += q1.y;
            }
            if (SPLIT) {
                hf h0,h1,l0,l1;
                split2h(v0.x, h0, l0); split2h(v0.y, h1, l1);
                *(uint32_t*)&Ch[(size_t)r0 * N + c0] = pack_hf2(h0,h1);
                *(uint32_t*)&Cl[(size_t)r0 * N + c0] = pack_hf2(l0,l1);
                split2h(v1.x, h0, l0); split2h(v1.y, h1, l1);
                *(uint32_t*)&Ch[(size_t)(r0 + 8) * N + c0] = pack_hf2(h0,h1);
                *(uint32_t*)&Cl[(size_t)(r0 + 8) * N + c0] = pack_hf2(l0,l1);
            } else if (Ch != nullptr) {
                *(uint32_t*)&Ch[(size_t)r0 * N + c0] =
                    pack_hf2(__float2half(v0.x), __float2half(v0.y));
                *(uint32_t*)&Ch[(size_t)(r0 + 8) * N + c0] =
                    pack_hf2(__float2half(v1.x), __float2half(v1.y));
            } else {
                *(float2*)&C[(size_t)r0 * N + c0] = v0;
                *(float2*)&C[(size_t)(r0 + 8) * N + c0] = v1;
            }
        }
    }
}

// ---------------------------------------------------------------------------
// Tensor-core causal flash attention, fp16. Q split (h+l); K, V, P single.
// qkv layout per row: h*192 + {q:0,k:64,v:128} + d.
// Block: 128 q rows x (b,h), 256 threads. K/V tiles of 64 keys, 3-stage ring,
// 2 groups in flight, ONE sync per tile. Q rides group 0.
// Smem halves: Qh 0, Ql 9216; stage s at 18432 + s*9216: Kh +0, Vh +4608.
// ---------------------------------------------------------------------------
#define AQ_H 0
#define AQ_L 9216
#define AKV_BASE 18432
#define AKV_STG  9216
#define A_KH 0
#define A_VH 4608
#define ATTN_SMEM ((18432 + 3*9216) * 2)   // 92160 bytes

__global__ __launch_bounds__(256)
void attn_tc(const hf* __restrict__ qkvh, const hf* __restrict__ qkvl,
             hf* __restrict__ outh) {
    extern __shared__ __align__(16) hf smem[];
    const uint32_t base = (uint32_t)__cvta_generic_to_shared(smem);

    const int tid = threadIdx.x, lane = tid & 31, warp = tid >> 5;
    const int qtile = blockIdx.x, bh = blockIdx.y;
    const int b = bh >> 4, h = bh & 15;
    const int qbase = qtile * 128;
    const int wrow = warp * 16;
    const int g = lane >> 2, tg = lane & 3;
    const int rA = lane & 15, cA = (lane >> 4) * 8;

#define KV_ISSUE(kstart, s) do {                                              \
        uint32_t sb = base + (AKV_BASE + (s) * AKV_STG) * 2;                  \
        _Pragma("unroll")                                                     \
        for (int t = 0; t < 2; t++) {                                         \
            int id = tid + t * 256;                                           \
            int r = id >> 3, cc = (id & 7) * 8;                               \
            size_t rowb = (size_t)(b * LL + (kstart) + r) * 3072 + h * 192;   \
            uint32_t dst = (uint32_t)((r * 72 + cc) * 2);                     \
            cp16(sb + A_KH*2 + dst, qkvh + rowb + 64 + cc);                   \
            cp16(sb + A_VH*2 + dst, qkvh + rowb + 128 + cc);                  \
        }                                                                     \
    } while (0)

    // group 0: Q (hi+lo) + KV tile 0
    {
        #pragma unroll
        for (int t = 0; t < 4; t++) {
            int id = tid + t * 256;
            int r = id >> 3, cc = (id & 7) * 8;
            size_t src = (size_t)(b * LL + qbase + r) * 3072 + h * 192 + cc;
            uint32_t dst = (uint32_t)((r * 72 + cc) * 2);
            cp16(base + AQ_H*2 + dst, qkvh + src);
            cp16(base + AQ_L*2 + dst, qkvl + src);
        }
    }
    KV_ISSUE(0, 0); CP_COMMIT();
    KV_ISSUE(64, 1); CP_COMMIT();   // ntiles >= 2 always

    const int ntiles = qtile * 2 + 2;

    uint32_t qh[4][4], ql[4][4];
    float o[8][4];
    #pragma unroll
    for (int i = 0; i < 8; i++)
        #pragma unroll
        for (int k = 0; k < 4; k++) o[i][k] = 0.f;
    float m0 = -1e30f, m1 = -1e30f, li0 = 0.f, li1 = 0.f;

    const int row0 = qbase + wrow + g;
    const int row1 = row0 + 8;

    for (int it = 0; it < ntiles; it++) {
        CP_WAIT1();
        __syncthreads();
        if (it + 2 < ntiles) KV_ISSUE((it + 2) * 64, (it + 2) % 3);
        CP_COMMIT();

        if (it == 0) {
            #pragma unroll
            for (int j = 0; j < 4; j++) {
                uint32_t off = (uint32_t)(((wrow + rA) * 72 + j * 16 + cA) * 2);
                ldsm4(qh[j], base + AQ_H*2 + off);
                ldsm4(ql[j], base + AQ_L*2 + off);
            }
        }

        const int s = it % 3;
        const int kstart = it * 64;
        const uint32_t uK_h = base + (AKV_BASE + s * AKV_STG + A_KH) * 2;
        const uint32_t uV_h = base + (AKV_BASE + s * AKV_STG + A_VH) * 2;

        float sc[8][4];
        #pragma unroll
        for (int i = 0; i < 8; i++)
            #pragma unroll
            for (int k = 0; k < 4; k++) sc[i][k] = 0.f;

        #pragma unroll
        for (int j = 0; j < 4; j++) {
            #pragma unroll
            for (int kb = 0; kb < 4; kb++) {
                uint32_t off = (uint32_t)(((kb * 16 + rA) * 72 + j * 16 + cA) * 2);
                uint32_t kh[4];
                ldsm4(kh, uK_h + off);
                int n0 = kb * 2;
                mma16816(sc[n0],   qh[j], kh[0], kh[2]);
                mma16816(sc[n0],   ql[j], kh[0], kh[2]);
                mma16816(sc[n0+1], qh[j], kh[1], kh[3]);
                mma16816(sc[n0+1], ql[j], kh[1], kh[3]);
            }
        }

        const bool need_mask = (kstart + 63) > (qbase + wrow);
        #pragma unroll
        for (int ni = 0; ni < 8; ni++) {
            int col = kstart + ni * 8 + tg * 2;
            if (need_mask) {
                sc[ni][0] = (col     > row0) ? -1e30f : sc[ni][0] * 0.125f;
                sc[ni][1] = (col + 1 > row0) ? -1e30f : sc[ni][1] * 0.125f;
                sc[ni][2] = (col     > row1) ? -1e30f : sc[ni][2] * 0.125f;
                sc[ni][3] = (col + 1 > row1) ? -1e30f : sc[ni][3] * 0.125f;
            } else {
                sc[ni][0] *= 0.125f; sc[ni][1] *= 0.125f;
                sc[ni][2] *= 0.125f; sc[ni][3] *= 0.125f;
            }
        }

        float mx0 = m0, mx1 = m1;
        #pragma unroll
        for (int ni = 0; ni < 8; ni++) {
            mx0 = fmaxf(mx0, fmaxf(sc[ni][0], sc[ni][1]));
            mx1 = fmaxf(mx1, fmaxf(sc[ni][2], sc[ni][3]));
        }
        mx0 = fmaxf(mx0, __shfl_xor_sync(0xffffffffu, mx0, 1));
        mx0 = fmaxf(mx0, __shfl_xor_sync(0xffffffffu, mx0, 2));
        mx1 = fmaxf(mx1, __shfl_xor_sync(0xffffffffu, mx1, 1));
        mx1 = fmaxf(mx1, __shfl_xor_sync(0xffffffffu, mx1, 2));
        float cs0 = __expf(m0 - mx0), cs1 = __expf(m1 - mx1);
        m0 = mx0; m1 = mx1;
        li0 *= cs0; li1 *= cs1;
        #pragma unroll
        for (int ni = 0; ni < 8; ni++) {
            o[ni][0] *= cs0; o[ni][1] *= cs0;
            o[ni][2] *= cs1; o[ni][3] *= cs1;
        }
        float ps0 = 0.f, ps1 = 0.f;
        #pragma unroll
        for (int ni = 0; ni < 8; ni++) {
            sc[ni][0] = __expf(sc[ni][0] - m0);
            sc[ni][1] = __expf(sc[ni][1] - m0);
            sc[ni][2] = __expf(sc[ni][2] - m1);
            sc[ni][3] = __expf(sc[ni][3] - m1);
            ps0 += sc[ni][0] + sc[ni][1];
            ps1 += sc[ni][2] + sc[ni][3];
        }
        ps0 += __shfl_xor_sync(0xffffffffu, ps0, 1);
        ps0 += __shfl_xor_sync(0xffffffffu, ps0, 2);
        ps1 += __shfl_xor_sync(0xffffffffu, ps1, 1);
        ps1 += __shfl_xor_sync(0xffffffffu, ps1, 2);
        li0 += ps0; li1 += ps1;

        #pragma unroll
        for (int j = 0; j < 4; j++) {
            uint32_t pah[4];
            pah[0] = pack_hf2(__float2half(sc[2*j][0]),   __float2half(sc[2*j][1]));
            pah[1] = pack_hf2(__float2half(sc[2*j][2]),   __float2half(sc[2*j][3]));
            pah[2] = pack_hf2(__float2half(sc[2*j+1][0]), __float2half(sc[2*j+1][1]));
            pah[3] = pack_hf2(__float2half(sc[2*j+1][2]), __float2half(sc[2*j+1][3]));
            #pragma unroll
            for (int nb = 0; nb < 4; nb++) {
                uint32_t off = (uint32_t)(((j * 16 + rA) * 72 + nb * 16 + cA) * 2);
                uint32_t vh[4];
                ldsm4t(vh, uV_h + off);
                int n0 = nb * 2;
                mma16816(o[n0],   pah, vh[0], vh[1]);
                mma16816(o[n0+1], pah, vh[2], vh[3]);
            }
        }
    }
#undef KV_ISSUE

    float inv0 = 1.f / li0, inv1 = 1.f / li1;
    size_t or0 = (size_t)(b * LL + row0) * EE + h * DHH;
    size_t or1 = (size_t)(b * LL + row1) * EE + h * DHH;
    #pragma unroll
    for (int ni = 0; ni < 8; ni++) {
        int cc = ni * 8 + tg * 2;
        *(uint32_t*)&outh[or0 + cc] =
            pack_hf2(__float2half(o[ni][0] * inv0), __float2half(o[ni][1] * inv0));
        *(uint32_t*)&outh[or1 + cc] =
            pack_hf2(__float2half(o[ni][2] * inv1), __float2half(o[ni][3] * inv1));
    }
}

// ---------------------------------------------------------------------------
// Launch
// ---------------------------------------------------------------------------
extern "C" void kernel_launch(void* const* d_in, const int* in_sizes, int n_in,
                              void* d_out, int out_size) {
    const float* x    = (const float*)d_in[0];
    const float* Wa   = (const float*)d_in[1];
    const float* Wout = (const float*)d_in[2];
    const float* bout = (const float*)d_in[3];
    const float* W1   = (const float*)d_in[4];
    const float* b1   = (const float*)d_in[5];
    const float* W2   = (const float*)d_in[6];
    const float* b2   = (const float*)d_in[7];
    const float* g1   = (const float*)d_in[8];
    const float* be1  = (const float*)d_in[9];
    const float* g2   = (const float*)d_in[10];
    const float* be2  = (const float*)d_in[11];
    float* out = (float*)d_out;

    unsigned char* arena;
    cudaGetSymbolAddress((void**)&arena, g_arena);

    hf* qkvh = (hf*)(arena + OFF_QKVH);
    hf* qkvl = (hf*)(arena + OFF_QKVL);
    float* res1 = (float*)(arena + OFF_RES1);
    hf* at  = (hf*)(arena + OFF_AT);
    hf* o1  = (hf*)(arena + OFF_O1);
    hf* o2  = (hf*)(arena + OFF_O2);
    hf* hh  = (hf*)(arena + OFF_H);
    hf* wah = (hf*)(arena + OFF_WAH);
    hf* woh = (hf*)(arena + OFF_WOH);
    hf* w1h = (hf*)(arena + OFF_W1H);
    hf* w2h = (hf*)(arena + OFF_W2H);

    static bool attr_done = false;
    if (!attr_done) {
        cudaFuncSetAttribute(gemm_fp16<false,false,true>,
            cudaFuncAttributeMaxDynamicSharedMemorySize, GEMM_SMEM);
        cudaFuncSetAttribute(gemm_fp16<true,true,false>,
            cudaFuncAttributeMaxDynamicSharedMemorySize, GEMM_SMEM);
        cudaFuncSetAttribute(gemm_fp16<true,false,false>,
            cudaFuncAttributeMaxDynamicSharedMemorySize, GEMM_SMEM);
        cudaFuncSetAttribute(attn_tc,
            cudaFuncAttributeMaxDynamicSharedMemorySize, ATTN_SMEM);
        attr_done = true;
    }

    // weight conversions
    cvt_kernel<<<(EE*3072/4 + 255)/256, 256>>>(Wa,   wah, EE*3072/4);
    cvt_kernel<<<(EE*EE/4   + 255)/256, 256>>>(Wout, woh, EE*EE/4);
    cvt_kernel<<<(EE*HIDD/4 + 255)/256, 256>>>(W1,   w1h, EE*HIDD/4);
    cvt_kernel<<<(HIDD*EE/4 + 255)/256, 256>>>(W2,   w2h, HIDD*EE/4);

    // 1) o1 = LN(x)
    ln_kernel<<<MROWS, 256>>>(x, g1, be1, o1);

    // 2) qkv = o1 @ Wa (split hi/lo output; lo used for Q only)
    gemm_fp16<false,false,true><<<dim3(3072/128, MROWS/128), 256, GEMM_SMEM>>>(
        o1, wah, nullptr, nullptr, nullptr, qkvh, qkvl,
        MROWS, 3072, EE);

    // 3) attention
    attn_tc<<<dim3(LL/128, BB*NHH), 256, ATTN_SMEM>>>(qkvh, qkvl, at);

    // 4) res1 = attn @ Wout + bout + x
    gemm_fp16<true,true,false><<<dim3(EE/128, MROWS/128), 256, GEMM_SMEM>>>(
        at, woh, bout, x, res1, nullptr, nullptr,
        MROWS, EE, EE);

    // 5) o2 = LN(res1)
    ln_kernel<<<MROWS, 256>>>(res1, g2, be2, o2);

    // 6) h = o2 @ W1 + b1  (single fp16 plane output)
    gemm_fp16<true,false,false><<<dim3(HIDD/128, MROWS/128), 256, GEMM_SMEM>>>(
        o2, w1h, b1, nullptr, nullptr, hh, nullptr,
        MROWS, HIDD, EE);

    // 7) out = h @ W2 + b2 + x (fp32 out)
    gemm_fp16<true,true,false><<<dim3(EE/128, MROWS/128), 256, GEMM_SMEM>>>(
        hh, w2h, b2, x, out, nullptr, nullptr,
        MROWS, EE, HIDD);
}

// round 9
// speedup vs baseline: 7.0763x; 1.1072x over previous
#include <cuda_runtime.h>
#include <cuda_fp16.h>
#include <cstdint>
#include <cstddef>

// Problem constants
#define BB   2
#define LL   2048
#define EE   1024
#define NHH  16
#define DHH  64
#define HIDD 4096
#define MROWS (BB*LL)          // 4096

typedef __half hf;

// ---------------------------------------------------------------------------
// Scratch arena
// ---------------------------------------------------------------------------
constexpr size_t SZ_QKV1 = (size_t)MROWS * 3072 * 2;
constexpr size_t SZ_RES1 = (size_t)MROWS * EE * 4;
constexpr size_t SZ_ACT  = (size_t)MROWS * EE * 2;
constexpr size_t SZ_H    = (size_t)MROWS * HIDD * 2;
constexpr size_t SZ_WA   = (size_t)EE * 3072 * 2;
constexpr size_t SZ_WO   = (size_t)EE * EE * 2;
constexpr size_t SZ_W1   = (size_t)EE * HIDD * 2;
constexpr size_t SZ_W2   = (size_t)HIDD * EE * 2;

constexpr size_t OFF_QKVH = 0;
constexpr size_t OFF_QKVL = OFF_QKVH + SZ_QKV1;
constexpr size_t OFF_RES1 = OFF_QKVL + SZ_QKV1;
constexpr size_t OFF_AT   = OFF_RES1 + SZ_RES1;
constexpr size_t OFF_O1   = OFF_AT   + SZ_ACT;
constexpr size_t OFF_O2   = OFF_O1   + SZ_ACT;
constexpr size_t OFF_H    = OFF_O2   + SZ_ACT;
constexpr size_t OFF_WAH  = OFF_H    + SZ_H;
constexpr size_t OFF_WOH  = OFF_WAH  + SZ_WA;
constexpr size_t OFF_W1H  = OFF_WOH  + SZ_WO;
constexpr size_t OFF_W2H  = OFF_W1H  + SZ_W1;
constexpr size_t ARENA_SZ = OFF_W2H  + SZ_W2;

__device__ __align__(256) unsigned char g_arena[ARENA_SZ];

// ---------------------------------------------------------------------------
// Helpers
// ---------------------------------------------------------------------------
__device__ __forceinline__ void split2h(float v, hf& h, hf& l) {
    h = __float2half(v);
    l = __float2half(v - __half2float(h));
}
__device__ __forceinline__ uint32_t pack_hf2(hf a, hf b) {
    __half2 t; t.x = a; t.y = b;
    return *(uint32_t*)&t;
}
__device__ __forceinline__ void ldsm4(uint32_t* r, uint32_t a) {
    asm volatile("ldmatrix.sync.aligned.m8n8.x4.shared.b16 {%0,%1,%2,%3}, [%4];\n"
        : "=r"(r[0]), "=r"(r[1]), "=r"(r[2]), "=r"(r[3]) : "r"(a));
}
__device__ __forceinline__ void ldsm4t(uint32_t* r, uint32_t a) {
    asm volatile("ldmatrix.sync.aligned.m8n8.x4.trans.shared.b16 {%0,%1,%2,%3}, [%4];\n"
        : "=r"(r[0]), "=r"(r[1]), "=r"(r[2]), "=r"(r[3]) : "r"(a));
}
__device__ __forceinline__ void mma16816(float* c, const uint32_t* a, uint32_t b0, uint32_t b1) {
    asm volatile(
        "mma.sync.aligned.m16n8k16.row.col.f32.f16.f16.f32 "
        "{%0,%1,%2,%3}, {%4,%5,%6,%7}, {%8,%9}, {%0,%1,%2,%3};\n"
        : "+f"(c[0]), "+f"(c[1]), "+f"(c[2]), "+f"(c[3])
        : "r"(a[0]), "r"(a[1]), "r"(a[2]), "r"(a[3]), "r"(b0), "r"(b1));
}
__device__ __forceinline__ void cp16(uint32_t dst, const void* src) {
    asm volatile("cp.async.cg.shared.global [%0], [%1], 16;\n" :: "r"(dst), "l"(src));
}
#define CP_COMMIT() asm volatile("cp.async.commit_group;\n" ::: "memory")
#define CP_WAIT1()  asm volatile("cp.async.wait_group 1;\n" ::: "memory")

// ---------------------------------------------------------------------------
// fp32 -> fp16 converter (weights)
// ---------------------------------------------------------------------------
__global__ __launch_bounds__(256)
void cvt_kernel(const float* __restrict__ in, hf* __restrict__ oh, int n4) {
    int i = blockIdx.x * 256 + threadIdx.x;
    if (i >= n4) return;
    float4 v = ((const float4*)in)[i];
    uint2 p;
    p.x = pack_hf2(__float2half(v.x), __float2half(v.y));
    p.y = pack_hf2(__float2half(v.z), __float2half(v.w));
    *(uint2*)&oh[(size_t)i*4] = p;
}

// ---------------------------------------------------------------------------
// LayerNorm writing single fp16 plane
// ---------------------------------------------------------------------------
__global__ __launch_bounds__(256)
void ln_kernel(const float* __restrict__ in, const float* __restrict__ g,
               const float* __restrict__ be, hf* __restrict__ oh) {
    int row = blockIdx.x;
    int tid = threadIdx.x;
    const float4* ip = (const float4*)(in + (size_t)row * EE);
    float4 v = ip[tid];
    float s  = v.x + v.y + v.z + v.w;
    float ss = v.x*v.x + v.y*v.y + v.z*v.z + v.w*v.w;
    #pragma unroll
    for (int o = 16; o; o >>= 1) {
        s  += __shfl_xor_sync(0xffffffffu, s,  o);
        ss += __shfl_xor_sync(0xffffffffu, ss, o);
    }
    __shared__ float sm[8], sm2[8];
    int w = tid >> 5;
    if ((tid & 31) == 0) { sm[w] = s; sm2[w] = ss; }
    __syncthreads();
    float ts = 0.f, tss = 0.f;
    #pragma unroll
    for (int i = 0; i < 8; i++) { ts += sm[i]; tss += sm2[i]; }
    float mu  = ts  * (1.f / EE);
    float var = tss * (1.f / EE) - mu * mu;
    float rs  = rsqrtf(var + 1e-5f);
    float4 gv = ((const float4*)g)[tid];
    float4 bv = ((const float4*)be)[tid];
    float4 o;
    o.x = (v.x - mu) * rs * gv.x + bv.x;
    o.y = (v.y - mu) * rs * gv.y + bv.y;
    o.z = (v.z - mu) * rs * gv.z + bv.z;
    o.w = (v.w - mu) * rs * gv.w + bv.w;
    size_t base = (size_t)row * EE + tid * 4;
    *(uint32_t*)&oh[base]     = pack_hf2(__float2half(o.x), __float2half(o.y));
    *(uint32_t*)&oh[base + 2] = pack_hf2(__float2half(o.z), __float2half(o.w));
}

// ---------------------------------------------------------------------------
// fp16 tensor-core GEMM: C = A @ B (single fp16 operands).
// Block 128x128, BK=32, 4 warps (2Mx2N), warp tile 64x64, mma.m16n8k16.
// 3-stage cp.async ring, 2 groups in flight, one sync per iteration, 2 CTAs/SM.
// ---------------------------------------------------------------------------
#define SA 40
#define SB 136
#define G_AH 0
#define G_BH 5120
#define G_STG 9472
#define GEMM_SMEM (3 * G_STG * 2)  // 56832 bytes

template<bool BIAS, bool RES, bool SPLIT>
__global__ __launch_bounds__(128, 2)
void gemm_fp16(const hf* __restrict__ Ah, const hf* __restrict__ Bh,
               const float* __restrict__ bias, const float* __restrict__ res,
               float* __restrict__ C, hf* __restrict__ Ch, hf* __restrict__ Cl,
               int M, int N, int K) {
    extern __shared__ __align__(16) hf smem[];
    const uint32_t base = (uint32_t)__cvta_generic_to_shared(smem);

    const int tid = threadIdx.x, lane = tid & 31, warp = tid >> 5;
    const int wm = (warp & 1) * 64, wn = (warp >> 1) * 64;
    const int rowBase = blockIdx.y * 128, colBase = blockIdx.x * 128;

    // global->smem mapping (128 threads, 8 cp16 each per stage)
    const int am = tid >> 2, ak = (tid & 3) * 8;    // A rows am+32j
    const int bk = tid >> 4, bn = (tid & 15) * 8;   // B rows bk+8j

    const hf* gAh = Ah + (size_t)(rowBase + am) * K + ak;
    const hf* gBh = Bh + (size_t)bk * N + colBase + bn;

    uint32_t sAoff[4], sBoff[4];
    #pragma unroll
    for (int j = 0; j < 4; j++) {
        sAoff[j] = (uint32_t)(((am + 32 * j) * SA + ak) * 2);
        sBoff[j] = (uint32_t)(((bk + 8 * j) * SB + bn) * 2);
    }

#define G_ISSUE(kt, s) do {                                                   \
        uint32_t sb = base + (uint32_t)(s) * (G_STG * 2);                     \
        _Pragma("unroll")                                                     \
        for (int j = 0; j < 4; j++)                                           \
            cp16(sb + G_AH*2 + sAoff[j], gAh + (size_t)(32 * j) * K + (kt));  \
        _Pragma("unroll")                                                     \
        for (int j = 0; j < 4; j++)                                           \
            cp16(sb + G_BH*2 + sBoff[j], gBh + (size_t)((kt) + 8 * j) * N);   \
    } while (0)

    const int rA = lane & 15, cA = (lane >> 4) * 8;
    const int rB = lane & 15, cB = (lane >> 4) * 8;

    float acc[4][8][4];
    #pragma unroll
    for (int i = 0; i < 4; i++)
        #pragma unroll
        for (int j = 0; j < 8; j++)
            #pragma unroll
            for (int k = 0; k < 4; k++) acc[i][j][k] = 0.f;

    G_ISSUE(0, 0);  CP_COMMIT();
    G_ISSUE(32, 1); CP_COMMIT();     // K >= 64 always

    const int nk = K >> 5;
    for (int i = 0; i < nk; i++) {
        CP_WAIT1();
        __syncthreads();
        if (i + 2 < nk) G_ISSUE((i + 2) * 32, (i + 2) % 3);
        CP_COMMIT();

        const int s = i % 3;
        const uint32_t uAh = base + s * (G_STG*2) + G_AH*2;
        const uint32_t uBh = base + s * (G_STG*2) + G_BH*2;

        #pragma unroll
        for (int kk = 0; kk < 32; kk += 16) {
            uint32_t bhf[4][4];
            #pragma unroll
            for (int j = 0; j < 4; j++) {
                uint32_t offB = (uint32_t)(((kk + rB) * SB + wn + j * 16 + cB) * 2);
                ldsm4t(bhf[j], uBh + offB);
            }
            #pragma unroll
            for (int mi = 0; mi < 4; mi++) {
                uint32_t offA = (uint32_t)(((wm + mi * 16 + rA) * SA + kk + cA) * 2);
                uint32_t ahf[4];
                ldsm4(ahf, uAh + offA);
                #pragma unroll
                for (int ni = 0; ni < 8; ni++) {
                    uint32_t b0 = bhf[ni >> 1][(ni & 1) * 2];
                    uint32_t b1 = bhf[ni >> 1][(ni & 1) * 2 + 1];
                    mma16816(acc[mi][ni], ahf, b0, b1);
                }
            }
        }
    }
#undef G_ISSUE

    // epilogue
    const int g = lane >> 2, tg = lane & 3;
    #pragma unroll
    for (int mi = 0; mi < 4; mi++) {
        #pragma unroll
        for (int ni = 0; ni < 8; ni++) {
            int r0 = rowBase + wm + mi * 16 + g;
            int c0 = colBase + wn + ni * 8 + tg * 2;
            float* a = acc[mi][ni];
            float2 v0 = make_float2(a[0], a[1]);
            float2 v1 = make_float2(a[2], a[3]);
            if (BIAS) {
                float bx = bias[c0], by = bias[c0 + 1];
                v0.x += bx; v0.y += by; v1.x += bx; v1.y += by;
            }
            if (RES) {
                float2 q0 = *(const float2*)&res[(size_t)r0 * N + c0];
                float2 q1 = *(const float2*)&res[(size_t)(r0 + 8) * N + c0];
                v0.x += q0.x; v0.y += q0.y; v1.x += q1.x; v1.y += q1.y;
            }
            if (SPLIT) {
                hf h0,h1,l0,l1;
                split2h(v0.x, h0, l0); split2h(v0.y, h1, l1);
                *(uint32_t*)&Ch[(size_t)r0 * N + c0] = pack_hf2(h0,h1);
                *(uint32_t*)&Cl[(size_t)r0 * N + c0] = pack_hf2(l0,l1);
                split2h(v1.x, h0, l0); split2h(v1.y, h1, l1);
                *(uint32_t*)&Ch[(size_t)(r0 + 8) * N + c0] = pack_hf2(h0,h1);
                *(uint32_t*)&Cl[(size_t)(r0 + 8) * N + c0] = pack_hf2(l0,l1);
            } else if (Ch != nullptr) {
                *(uint32_t*)&Ch[(size_t)r0 * N + c0] =
                    pack_hf2(__float2half(v0.x), __float2half(v0.y));
                *(uint32_t*)&Ch[(size_t)(r0 + 8) * N + c0] =
                    pack_hf2(__float2half(v1.x), __float2half(v1.y));
            } else {
                *(float2*)&C[(size_t)r0 * N + c0] = v0;
                *(float2*)&C[(size_t)(r0 + 8) * N + c0] = v1;
            }
        }
    }
}

// ---------------------------------------------------------------------------
// Tensor-core causal flash attention, fp16. Q split (h+l); K, V, P single.
// qkv layout per row: h*192 + {q:0,k:64,v:128} + d.
// Block: 128 q rows x (b,h), 256 threads. K/V tiles of 64 keys, 3-stage ring,
// 2 groups in flight, one sync per tile. Q rides group 0.
// ---------------------------------------------------------------------------
#define AQ_H 0
#define AQ_L 9216
#define AKV_BASE 18432
#define AKV_STG  9216
#define A_KH 0
#define A_VH 4608
#define ATTN_SMEM ((18432 + 3*9216) * 2)   // 92160 bytes

__global__ __launch_bounds__(256)
void attn_tc(const hf* __restrict__ qkvh, const hf* __restrict__ qkvl,
             hf* __restrict__ outh) {
    extern __shared__ __align__(16) hf smem[];
    const uint32_t base = (uint32_t)__cvta_generic_to_shared(smem);

    const int tid = threadIdx.x, lane = tid & 31, warp = tid >> 5;
    const int qtile = blockIdx.x, bh = blockIdx.y;
    const int b = bh >> 4, h = bh & 15;
    const int qbase = qtile * 128;
    const int wrow = warp * 16;
    const int g = lane >> 2, tg = lane & 3;
    const int rA = lane & 15, cA = (lane >> 4) * 8;

#define KV_ISSUE(kstart, s) do {                                              \
        uint32_t sb = base + (AKV_BASE + (s) * AKV_STG) * 2;                  \
        _Pragma("unroll")                                                     \
        for (int t = 0; t < 2; t++) {                                         \
            int id = tid + t * 256;                                           \
            int r = id >> 3, cc = (id & 7) * 8;                               \
            size_t rowb = (size_t)(b * LL + (kstart) + r) * 3072 + h * 192;   \
            uint32_t dst = (uint32_t)((r * 72 + cc) * 2);                     \
            cp16(sb + A_KH*2 + dst, qkvh + rowb + 64 + cc);                   \
            cp16(sb + A_VH*2 + dst, qkvh + rowb + 128 + cc);                  \
        }                                                                     \
    } while (0)

    {
        #pragma unroll
        for (int t = 0; t < 4; t++) {
            int id = tid + t * 256;
            int r = id >> 3, cc = (id & 7) * 8;
            size_t src = (size_t)(b * LL + qbase + r) * 3072 + h * 192 + cc;
            uint32_t dst = (uint32_t)((r * 72 + cc) * 2);
            cp16(base + AQ_H*2 + dst, qkvh + src);
            cp16(base + AQ_L*2 + dst, qkvl + src);
        }
    }
    KV_ISSUE(0, 0); CP_COMMIT();
    KV_ISSUE(64, 1); CP_COMMIT();

    const int ntiles = qtile * 2 + 2;

    uint32_t qh[4][4], ql[4][4];
    float o[8][4];
    #pragma unroll
    for (int i = 0; i < 8; i++)
        #pragma unroll
        for (int k = 0; k < 4; k++) o[i][k] = 0.f;
    float m0 = -1e30f, m1 = -1e30f, li0 = 0.f, li1 = 0.f;

    const int row0 = qbase + wrow + g;
    const int row1 = row0 + 8;

    for (int it = 0; it < ntiles; it++) {
        CP_WAIT1();
        __syncthreads();
        if (it + 2 < ntiles) KV_ISSUE((it + 2) * 64, (it + 2) % 3);
        CP_COMMIT();

        if (it == 0) {
            #pragma unroll
            for (int j = 0; j < 4; j++) {
                uint32_t off = (uint32_t)(((wrow + rA) * 72 + j * 16 + cA) * 2);
                ldsm4(qh[j], base + AQ_H*2 + off);
                ldsm4(ql[j], base + AQ_L*2 + off);
            }
        }

        const int s = it % 3;
        const int kstart = it * 64;
        const uint32_t uK_h = base + (AKV_BASE + s * AKV_STG + A_KH) * 2;
        const uint32_t uV_h = base + (AKV_BASE + s * AKV_STG + A_VH) * 2;

        float sc[8][4];
        #pragma unroll
        for (int i = 0; i < 8; i++)
            #pragma unroll
            for (int k = 0; k < 4; k++) sc[i][k] = 0.f;

        #pragma unroll
        for (int j = 0; j < 4; j++) {
            #pragma unroll
            for (int kb = 0; kb < 4; kb++) {
                uint32_t off = (uint32_t)(((kb * 16 + rA) * 72 + j * 16 + cA) * 2);
                uint32_t kh[4];
                ldsm4(kh, uK_h + off);
                int n0 = kb * 2;
                mma16816(sc[n0],   qh[j], kh[0], kh[2]);
                mma16816(sc[n0],   ql[j], kh[0], kh[2]);
                mma16816(sc[n0+1], qh[j], kh[1], kh[3]);
                mma16816(sc[n0+1], ql[j], kh[1], kh[3]);
            }
        }

        const bool need_mask = (kstart + 63) > (qbase + wrow);
        #pragma unroll
        for (int ni = 0; ni < 8; ni++) {
            int col = kstart + ni * 8 + tg * 2;
            if (need_mask) {
                sc[ni][0] = (col     > row0) ? -1e30f : sc[ni][0] * 0.125f;
                sc[ni][1] = (col + 1 > row0) ? -1e30f : sc[ni][1] * 0.125f;
                sc[ni][2] = (col     > row1) ? -1e30f : sc[ni][2] * 0.125f;
                sc[ni][3] = (col + 1 > row1) ? -1e30f : sc[ni][3] * 0.125f;
            } else {
                sc[ni][0] *= 0.125f; sc[ni][1] *= 0.125f;
                sc[ni][2] *= 0.125f; sc[ni][3] *= 0.125f;
            }
        }

        float mx0 = m0, mx1 = m1;
        #pragma unroll
        for (int ni = 0; ni < 8; ni++) {
            mx0 = fmaxf(mx0, fmaxf(sc[ni][0], sc[ni][1]));
            mx1 = fmaxf(mx1, fmaxf(sc[ni][2], sc[ni][3]));
        }
        mx0 = fmaxf(mx0, __shfl_xor_sync(0xffffffffu, mx0, 1));
        mx0 = fmaxf(mx0, __shfl_xor_sync(0xffffffffu, mx0, 2));
        mx1 = fmaxf(mx1, __shfl_xor_sync(0xffffffffu, mx1, 1));
        mx1 = fmaxf(mx1, __shfl_xor_sync(0xffffffffu, mx1, 2));
        float cs0 = __expf(m0 - mx0), cs1 = __expf(m1 - mx1);
        m0 = mx0; m1 = mx1;
        li0 *= cs0; li1 *= cs1;
        #pragma unroll
        for (int ni = 0; ni < 8; ni++) {
            o[ni][0] *= cs0; o[ni][1] *= cs0;
            o[ni][2] *= cs1; o[ni][3] *= cs1;
        }
        float ps0 = 0.f, ps1 = 0.f;
        #pragma unroll
        for (int ni = 0; ni < 8; ni++) {
            sc[ni][0] = __expf(sc[ni][0] - m0);
            sc[ni][1] = __expf(sc[ni][1] - m0);
            sc[ni][2] = __expf(sc[ni][2] - m1);
            sc[ni][3] = __expf(sc[ni][3] - m1);
            ps0 += sc[ni][0] + sc[ni][1];
            ps1 += sc[ni][2] + sc[ni][3];
        }
        ps0 += __shfl_xor_sync(0xffffffffu, ps0, 1);
        ps0 += __shfl_xor_sync(0xffffffffu, ps0, 2);
        ps1 += __shfl_xor_sync(0xffffffffu, ps1, 1);
        ps1 += __shfl_xor_sync(0xffffffffu, ps1, 2);
        li0 += ps0; li1 += ps1;

        #pragma unroll
        for (int j = 0; j < 4; j++) {
            uint32_t pah[4];
            pah[0] = pack_hf2(__float2half(sc[2*j][0]),   __float2half(sc[2*j][1]));
            pah[1] = pack_hf2(__float2half(sc[2*j][2]),   __float2half(sc[2*j][3]));
            pah[2] = pack_hf2(__float2half(sc[2*j+1][0]), __float2half(sc[2*j+1][1]));
            pah[3] = pack_hf2(__float2half(sc[2*j+1][2]), __float2half(sc[2*j+1][3]));
            #pragma unroll
            for (int nb = 0; nb < 4; nb++) {
                uint32_t off = (uint32_t)(((j * 16 + rA) * 72 + nb * 16 + cA) * 2);
                uint32_t vh[4];
                ldsm4t(vh, uV_h + off);
                int n0 = nb * 2;
                mma16816(o[n0],   pah, vh[0], vh[1]);
                mma16816(o[n0+1], pah, vh[2], vh[3]);
            }
        }
    }
#undef KV_ISSUE

    float inv0 = 1.f / li0, inv1 = 1.f / li1;
    size_t or0 = (size_t)(b * LL + row0) * EE + h * DHH;
    size_t or1 = (size_t)(b * LL + row1) * EE + h * DHH;
    #pragma unroll
    for (int ni = 0; ni < 8; ni++) {
        int cc = ni * 8 + tg * 2;
        *(uint32_t*)&outh[or0 + cc] =
            pack_hf2(__float2half(o[ni][0] * inv0), __float2half(o[ni][1] * inv0));
        *(uint32_t*)&outh[or1 + cc] =
            pack_hf2(__float2half(o[ni][2] * inv1), __float2half(o[ni][3] * inv1));
    }
}

// ---------------------------------------------------------------------------
// Launch
// ---------------------------------------------------------------------------
extern "C" void kernel_launch(void* const* d_in, const int* in_sizes, int n_in,
                              void* d_out, int out_size) {
    const float* x    = (const float*)d_in[0];
    const float* Wa   = (const float*)d_in[1];
    const float* Wout = (const float*)d_in[2];
    const float* bout = (const float*)d_in[3];
    const float* W1   = (const float*)d_in[4];
    const float* b1   = (const float*)d_in[5];
    const float* W2   = (const float*)d_in[6];
    const float* b2   = (const float*)d_in[7];
    const float* g1   = (const float*)d_in[8];
    const float* be1  = (const float*)d_in[9];
    const float* g2   = (const float*)d_in[10];
    const float* be2  = (const float*)d_in[11];
    float* out = (float*)d_out;

    unsigned char* arena;
    cudaGetSymbolAddress((void**)&arena, g_arena);

    hf* qkvh = (hf*)(arena + OFF_QKVH);
    hf* qkvl = (hf*)(arena + OFF_QKVL);
    float* res1 = (float*)(arena + OFF_RES1);
    hf* at  = (hf*)(arena + OFF_AT);
    hf* o1  = (hf*)(arena + OFF_O1);
    hf* o2  = (hf*)(arena + OFF_O2);
    hf* hh  = (hf*)(arena + OFF_H);
    hf* wah = (hf*)(arena + OFF_WAH);
    hf* woh = (hf*)(arena + OFF_WOH);
    hf* w1h = (hf*)(arena + OFF_W1H);
    hf* w2h = (hf*)(arena + OFF_W2H);

    static bool attr_done = false;
    if (!attr_done) {
        cudaFuncSetAttribute(gemm_fp16<false,false,true>,
            cudaFuncAttributeMaxDynamicSharedMemorySize, GEMM_SMEM);
        cudaFuncSetAttribute(gemm_fp16<true,true,false>,
            cudaFuncAttributeMaxDynamicSharedMemorySize, GEMM_SMEM);
        cudaFuncSetAttribute(gemm_fp16<true,false,false>,
            cudaFuncAttributeMaxDynamicSharedMemorySize, GEMM_SMEM);
        cudaFuncSetAttribute(attn_tc,
            cudaFuncAttributeMaxDynamicSharedMemorySize, ATTN_SMEM);
        attr_done = true;
    }

    // weight conversions
    cvt_kernel<<<(EE*3072/4 + 255)/256, 256>>>(Wa,   wah, EE*3072/4);
    cvt_kernel<<<(EE*EE/4   + 255)/256, 256>>>(Wout, woh, EE*EE/4);
    cvt_kernel<<<(EE*HIDD/4 + 255)/256, 256>>>(W1,   w1h, EE*HIDD/4);
    cvt_kernel<<<(HIDD*EE/4 + 255)/256, 256>>>(W2,   w2h, HIDD*EE/4);

    // 1) o1 = LN(x)
    ln_kernel<<<MROWS, 256>>>(x, g1, be1, o1);

    // 2) qkv = o1 @ Wa (split hi/lo output; lo used for Q only)
    gemm_fp16<false,false,true><<<dim3(3072/128, MROWS/128), 128, GEMM_SMEM>>>(
        o1, wah, nullptr, nullptr, nullptr, qkvh, qkvl,
        MROWS, 3072, EE);

    // 3) attention
    attn_tc<<<dim3(LL/128, BB*NHH), 256, ATTN_SMEM>>>(qkvh, qkvl, at);

    // 4) res1 = attn @ Wout + bout + x
    gemm_fp16<true,true,false><<<dim3(EE/128, MROWS/128), 128, GEMM_SMEM>>>(
        at, woh, bout, x, res1, nullptr, nullptr,
        MROWS, EE, EE);

    // 5) o2 = LN(res1)
    ln_kernel<<<MROWS, 256>>>(res1, g2, be2, o2);

    // 6) h = o2 @ W1 + b1  (single fp16 plane output)
    gemm_fp16<true,false,false><<<dim3(HIDD/128, MROWS/128), 128, GEMM_SMEM>>>(
        o2, w1h, b1, nullptr, nullptr, hh, nullptr,
        MROWS, HIDD, EE);

    // 7) out = h @ W2 + b2 + x (fp32 out)
    gemm_fp16<true,true,false><<<dim3(EE/128, MROWS/128), 128, GEMM_SMEM>>>(
        hh, w2h, b2, x, out, nullptr, nullptr,
        MROWS, EE, HIDD);
}